// round 11
// baseline (speedup 1.0000x reference)
#include <cuda_runtime.h>
#include <cuda_bf16.h>
#include <math.h>
#include <stdint.h>

#define BB   16
#define CC   64
#define NP   128
#define DD   128
#define HT   4
#define DH   32
#define HS   4
#define FF   128
#define DK   64
#define NTOK (BB*CC*NP)      // 131072
#define NSEQ (BB*CC)         // 1024
#define GAT_NEG -1e30f

// ---------------- scratch ----------------------------------------------------
__device__ float g_h[NTOK*DD];
__device__ float g_qkv[(size_t)NTOK*3*DD];
__device__ float g_o[NTOK*DD];
__device__ float g_x[NTOK*DD];
__device__ float g_ff[(size_t)NTOK*4*DD];
__device__ float g_Htemp[NTOK*DD];
__device__ float g_xh[(size_t)NTOK*HS*FF];
__device__ float g_Hs[NSEQ*DD];
__device__ float g_q2[NSEQ*DK];
__device__ float g_k2[NSEQ*DK];
__device__ float g_mask[BB*CC*CC];
__device__ float g_watt[8*DD];             // rows 0-3: w_src[h], 4-7: w_dst[h]
__device__ float g_asrc[BB*HS*NP*CC];      // [b][h][p][s]
__device__ float g_adst[BB*HS*NP*CC];

// ---------------- helpers ----------------------------------------------------
__device__ __forceinline__ void mma8(float c[4], const uint32_t a[4],
                                     uint32_t b0, uint32_t b1) {
    asm volatile(
        "mma.sync.aligned.m16n8k8.row.col.f32.tf32.tf32.f32 "
        "{%0,%1,%2,%3}, {%4,%5,%6,%7}, {%8,%9}, {%0,%1,%2,%3};"
        : "+f"(c[0]), "+f"(c[1]), "+f"(c[2]), "+f"(c[3])
        : "r"(a[0]), "r"(a[1]), "r"(a[2]), "r"(a[3]), "r"(b0), "r"(b1));
}
__device__ __forceinline__ void cp_async16(float* smem, const float* gmem) {
    uint32_t s = (uint32_t)__cvta_generic_to_shared(smem);
    asm volatile("cp.async.cg.shared.global [%0], [%1], 16;" :: "r"(s), "l"(gmem));
}
#define FU(x) __float_as_uint(x)

// ---------------- LayerNorm: warp per row (ln1 only now) ---------------------
__global__ void k_ln(const float* __restrict__ x, const float* __restrict__ add,
                     const float* __restrict__ gw, const float* __restrict__ bw,
                     float* __restrict__ out)
{
    int row  = blockIdx.x * 8 + (threadIdx.x >> 5);
    int lane = threadIdx.x & 31;
    const float4* xp = (const float4*)(x + (size_t)row * DD);
    float4 v = xp[lane];
    if (add) {
        float4 a = ((const float4*)(add + (size_t)row * DD))[lane];
        v.x += a.x; v.y += a.y; v.z += a.z; v.w += a.w;
    }
    float s = v.x + v.y + v.z + v.w;
    #pragma unroll
    for (int o = 16; o; o >>= 1) s += __shfl_xor_sync(0xffffffffu, s, o);
    float mean = s * (1.f/128.f);
    float dx = v.x-mean, dy = v.y-mean, dz = v.z-mean, dw = v.w-mean;
    float q = dx*dx + dy*dy + dz*dz + dw*dw;
    #pragma unroll
    for (int o = 16; o; o >>= 1) q += __shfl_xor_sync(0xffffffffu, q, o);
    float inv = rsqrtf(q * (1.f/128.f) + 1e-5f);
    float4 g4 = ((const float4*)gw)[lane];
    float4 b4 = ((const float4*)bw)[lane];
    float4 o4;
    o4.x = dx*inv*g4.x + b4.x;  o4.y = dy*inv*g4.y + b4.y;
    o4.z = dz*inv*g4.z + b4.z;  o4.w = dw*inv*g4.w + b4.w;
    ((float4*)(out + (size_t)row * DD))[lane] = o4;
}

// ---------------- tf32 GEMM, cp.async 2-stage pipeline (R7-proven) -----------
#define TBM 128
#define TBN 128
#define TILE (128*36)
__global__ void __launch_bounds__(256)
k_mma(const float* __restrict__ A, const float* __restrict__ W,
      const float* __restrict__ bias, const float* __restrict__ res,
      float* __restrict__ out, int M, int N, int K, int relu)
{
    extern __shared__ float smbuf[];
    float* As = smbuf;             // [2][128][36]
    float* Bs = smbuf + 2*TILE;    // [2][128][36]
    int tid  = threadIdx.x;
    int warp = tid >> 5, lane = tid & 31;
    int wm = warp >> 1, wn = warp & 1;
    int g = lane >> 2, t = lane & 3;
    int m0 = blockIdx.y * TBM;
    int n0 = blockIdx.x * TBN;
    int lr = tid >> 3, lc = (tid & 7) << 2;

    float acc[2][8][4] = {};
    const int nk = K >> 5;

    #pragma unroll
    for (int i = 0; i < 4; i++) {
        int r = lr + i * 32;
        cp_async16(&As[r*36 + lc], A + (size_t)(m0 + r) * K + lc);
        cp_async16(&Bs[r*36 + lc], W + (size_t)(n0 + r) * K + lc);
    }
    asm volatile("cp.async.commit_group;");

    for (int kt = 0; kt < nk; kt++) {
        int buf = (kt & 1) * TILE;
        if (kt + 1 < nk) {
            int nb = ((kt + 1) & 1) * TILE;
            int ko = (kt + 1) << 5;
            #pragma unroll
            for (int i = 0; i < 4; i++) {
                int r = lr + i * 32;
                cp_async16(&As[nb + r*36 + lc], A + (size_t)(m0 + r) * K + ko + lc);
                cp_async16(&Bs[nb + r*36 + lc], W + (size_t)(n0 + r) * K + ko + lc);
            }
            asm volatile("cp.async.commit_group;");
            asm volatile("cp.async.wait_group 1;");
        } else {
            asm volatile("cp.async.wait_group 0;");
        }
        __syncthreads();
        #pragma unroll
        for (int kk = 0; kk < 32; kk += 8) {
            uint32_t afrag[2][4];
            #pragma unroll
            for (int mi = 0; mi < 2; mi++) {
                int r = wm * 32 + mi * 16;
                afrag[mi][0] = FU(As[buf + (r + g    )*36 + kk + t    ]);
                afrag[mi][1] = FU(As[buf + (r + g + 8)*36 + kk + t    ]);
                afrag[mi][2] = FU(As[buf + (r + g    )*36 + kk + t + 4]);
                afrag[mi][3] = FU(As[buf + (r + g + 8)*36 + kk + t + 4]);
            }
            #pragma unroll
            for (int ni = 0; ni < 8; ni++) {
                int c = wn * 64 + ni * 8;
                uint32_t b0 = FU(Bs[buf + (c + g)*36 + kk + t    ]);
                uint32_t b1 = FU(Bs[buf + (c + g)*36 + kk + t + 4]);
                mma8(acc[0][ni], afrag[0], b0, b1);
                mma8(acc[1][ni], afrag[1], b0, b1);
            }
        }
        __syncthreads();
    }

    #pragma unroll
    for (int mi = 0; mi < 2; mi++) {
        #pragma unroll
        for (int ni = 0; ni < 8; ni++) {
            int r = m0 + wm * 32 + mi * 16 + g;
            int c = n0 + wn * 64 + ni * 8 + 2 * t;
            float bv0 = bias ? bias[c]     : 0.f;
            float bv1 = bias ? bias[c + 1] : 0.f;
            #pragma unroll
            for (int half = 0; half < 2; half++) {
                int row = r + half * 8;
                float v0 = acc[mi][ni][half*2 + 0] + bv0;
                float v1 = acc[mi][ni][half*2 + 1] + bv1;
                if (relu) { v0 = fmaxf(v0, 0.f); v1 = fmaxf(v1, 0.f); }
                if (res) {
                    const float2 rr = *(const float2*)(res + (size_t)row * N + c);
                    v0 += rr.x; v1 += rr.y;
                }
                *(float2*)(out + (size_t)row * N + c) = make_float2(v0, v1);
            }
        }
    }
}

// ========== tf32 GEMM (N=128) + smem-staged row-LN epilogue ==================
// v = acc + bias (+res) (+x0);  if out: write v;  out2 = rowLN(v)*lng + lnb.
// gridDim.x == 1 required (full rows per CTA). smem reuse: Vs[128][132].
#define VST 132
__global__ void __launch_bounds__(256)
k_mma_ln(const float* __restrict__ A, const float* __restrict__ W,
         const float* __restrict__ bias, const float* __restrict__ res,
         const float* __restrict__ x0, float* __restrict__ out,
         float* __restrict__ out2,
         const float* __restrict__ lng, const float* __restrict__ lnb, int K)
{
    extern __shared__ float smbuf[];
    float* As = smbuf;
    float* Bs = smbuf + 2*TILE;
    float* Vs = smbuf;             // epilogue union [128][132]
    int tid  = threadIdx.x;
    int warp = tid >> 5, lane = tid & 31;
    int wm = warp >> 1, wn = warp & 1;
    int g = lane >> 2, t = lane & 3;
    int m0 = blockIdx.y * TBM;
    int lr = tid >> 3, lc = (tid & 7) << 2;

    float acc[2][8][4] = {};
    const int nk = K >> 5;

    #pragma unroll
    for (int i = 0; i < 4; i++) {
        int r = lr + i * 32;
        cp_async16(&As[r*36 + lc], A + (size_t)(m0 + r) * K + lc);
        cp_async16(&Bs[r*36 + lc], W + (size_t)r * K + lc);
    }
    asm volatile("cp.async.commit_group;");

    for (int kt = 0; kt < nk; kt++) {
        int buf = (kt & 1) * TILE;
        if (kt + 1 < nk) {
            int nb = ((kt + 1) & 1) * TILE;
            int ko = (kt + 1) << 5;
            #pragma unroll
            for (int i = 0; i < 4; i++) {
                int r = lr + i * 32;
                cp_async16(&As[nb + r*36 + lc], A + (size_t)(m0 + r) * K + ko + lc);
                cp_async16(&Bs[nb + r*36 + lc], W + (size_t)r * K + ko + lc);
            }
            asm volatile("cp.async.commit_group;");
            asm volatile("cp.async.wait_group 1;");
        } else {
            asm volatile("cp.async.wait_group 0;");
        }
        __syncthreads();
        #pragma unroll
        for (int kk = 0; kk < 32; kk += 8) {
            uint32_t afrag[2][4];
            #pragma unroll
            for (int mi = 0; mi < 2; mi++) {
                int r = wm * 32 + mi * 16;
                afrag[mi][0] = FU(As[buf + (r + g    )*36 + kk + t    ]);
                afrag[mi][1] = FU(As[buf + (r + g + 8)*36 + kk + t    ]);
                afrag[mi][2] = FU(As[buf + (r + g    )*36 + kk + t + 4]);
                afrag[mi][3] = FU(As[buf + (r + g + 8)*36 + kk + t + 4]);
            }
            #pragma unroll
            for (int ni = 0; ni < 8; ni++) {
                int c = wn * 64 + ni * 8;
                uint32_t b0 = FU(Bs[buf + (c + g)*36 + kk + t    ]);
                uint32_t b1 = FU(Bs[buf + (c + g)*36 + kk + t + 4]);
                mma8(acc[0][ni], afrag[0], b0, b1);
                mma8(acc[1][ni], afrag[1], b0, b1);
            }
        }
        __syncthreads();
    }

    // ---- epilogue: v -> (out), Vs ----
    #pragma unroll
    for (int mi = 0; mi < 2; mi++) {
        #pragma unroll
        for (int ni = 0; ni < 8; ni++) {
            int r = wm * 32 + mi * 16 + g;
            int c = wn * 64 + ni * 8 + 2 * t;
            float bv0 = bias[c], bv1 = bias[c + 1];
            #pragma unroll
            for (int half = 0; half < 2; half++) {
                int row = r + half * 8;
                float v0 = acc[mi][ni][half*2 + 0] + bv0;
                float v1 = acc[mi][ni][half*2 + 1] + bv1;
                if (res) {
                    const float2 rr = *(const float2*)(res + (size_t)(m0 + row) * 128 + c);
                    v0 += rr.x; v1 += rr.y;
                }
                if (x0) {
                    const float2 rr = *(const float2*)(x0 + (size_t)(m0 + row) * 128 + c);
                    v0 += rr.x; v1 += rr.y;
                }
                if (out)
                    *(float2*)(out + (size_t)(m0 + row) * 128 + c) = make_float2(v0, v1);
                Vs[row*VST + c    ] = v0;
                Vs[row*VST + c + 1] = v1;
            }
        }
    }
    __syncthreads();

    // ---- row-LN from smem: warp per row ----
    {
        float4 g4 = ((const float4*)lng)[lane];
        float4 b4 = ((const float4*)lnb)[lane];
        for (int r = warp; r < 128; r += 8) {
            float4 v = *(float4*)&Vs[r*VST + lane*4];
            float s = v.x + v.y + v.z + v.w;
            #pragma unroll
            for (int o = 16; o; o >>= 1) s += __shfl_xor_sync(0xffffffffu, s, o);
            float mean = s * (1.f/128.f);
            float dx=v.x-mean, dy=v.y-mean, dz=v.z-mean, dw=v.w-mean;
            float q = dx*dx+dy*dy+dz*dz+dw*dw;
            #pragma unroll
            for (int o = 16; o; o >>= 1) q += __shfl_xor_sync(0xffffffffu, q, o);
            float inv = rsqrtf(q * (1.f/128.f) + 1e-5f);
            float4 ov;
            ov.x = dx*inv*g4.x + b4.x; ov.y = dy*inv*g4.y + b4.y;
            ov.z = dz*inv*g4.z + b4.z; ov.w = dw*inv*g4.w + b4.w;
            ((float4*)(out2 + (size_t)(m0 + r) * 128))[lane] = ov;
        }
    }
}

// ---------------- small SIMT GEMM (q2/k2) ------------------------------------
#define BM 64
#define BN 64
#define BK 16
__global__ void k_gemm(const float* __restrict__ A, const float* __restrict__ W,
                       const float* __restrict__ bias, float* __restrict__ out,
                       int M, int N, int K)
{
    __shared__ float As[BK][BM];
    __shared__ float Bs[BK][BN];
    int tid = threadIdx.x;
    int tx = tid & 15, ty = tid >> 4;
    int m0 = blockIdx.y * BM, n0 = blockIdx.x * BN;
    int lr = tid >> 2;
    int lk = (tid & 3) * 4;
    float acc[4][4] = {};
    for (int k0 = 0; k0 < K; k0 += BK) {
        float4 a4 = *(const float4*)(A + (size_t)(m0 + lr) * K + k0 + lk);
        float4 b4 = *(const float4*)(W + (size_t)(n0 + lr) * K + k0 + lk);
        As[lk+0][lr] = a4.x; As[lk+1][lr] = a4.y; As[lk+2][lr] = a4.z; As[lk+3][lr] = a4.w;
        Bs[lk+0][lr] = b4.x; Bs[lk+1][lr] = b4.y; Bs[lk+2][lr] = b4.z; Bs[lk+3][lr] = b4.w;
        __syncthreads();
        #pragma unroll
        for (int k = 0; k < BK; k++) {
            float4 ra = *(const float4*)&As[k][ty*4];
            float4 rb = *(const float4*)&Bs[k][tx*4];
            float av[4] = {ra.x, ra.y, ra.z, ra.w};
            float bv[4] = {rb.x, rb.y, rb.z, rb.w};
            #pragma unroll
            for (int i = 0; i < 4; i++)
                #pragma unroll
                for (int j = 0; j < 4; j++)
                    acc[i][j] += av[i] * bv[j];
        }
        __syncthreads();
    }
    #pragma unroll
    for (int i = 0; i < 4; i++) {
        int m = m0 + ty*4 + i;
        #pragma unroll
        for (int j = 0; j < 4; j++) {
            int n = n0 + tx*4 + j;
            out[(size_t)m * N + n] = acc[i][j] + bias[n];
        }
    }
}

// ============== attention v4 (R10-proven) ====================================
#define AQS 36
#define AVS 132
#define APW 68
__global__ void __launch_bounds__(128, 3)
k_attn_mma()
{
    extern __shared__ float sm[];
    float* Qs = sm;                  // [128][36]
    float* Ks = sm + 4608;           // [128][36]
    float* VT = sm + 9216;           // [32][132]
    float* Pb = sm;                  // union: per-warp [32][68]

    int n = blockIdx.x >> 2, h = blockIdx.x & 3;
    int tid = threadIdx.x;
    int warp = tid >> 5, lane = tid & 31;
    int g = lane >> 2, t = lane & 3;
    int m0 = warp * 32;
    const float* base = g_qkv + (size_t)n * NP * 3 * DD;

    for (int idx = tid; idx < NP*DH; idx += 128) {
        int j = idx >> 5, d = idx & 31;
        Qs[j*AQS + d] = base[j*384 +       h*32 + d];
        Ks[j*AQS + d] = base[j*384 + 128 + h*32 + d];
        VT[d*AVS + j] = base[j*384 + 256 + h*32 + d];
    }
    __syncthreads();

    float s[2][16][4] = {};
    #pragma unroll
    for (int kk = 0; kk < 32; kk += 8) {
        uint32_t afrag[2][4];
        #pragma unroll
        for (int mi = 0; mi < 2; mi++) {
            int r = m0 + mi * 16;
            afrag[mi][0] = FU(Qs[(r + g    )*AQS + kk + t    ]);
            afrag[mi][1] = FU(Qs[(r + g + 8)*AQS + kk + t    ]);
            afrag[mi][2] = FU(Qs[(r + g    )*AQS + kk + t + 4]);
            afrag[mi][3] = FU(Qs[(r + g + 8)*AQS + kk + t + 4]);
        }
        #pragma unroll
        for (int ni = 0; ni < 16; ni++) {
            int c = ni * 8;
            uint32_t b0 = FU(Ks[(c + g)*AQS + kk + t    ]);
            uint32_t b1 = FU(Ks[(c + g)*AQS + kk + t + 4]);
            mma8(s[0][ni], afrag[0], b0, b1);
            mma8(s[1][ni], afrag[1], b0, b1);
        }
    }
    __syncthreads();

    const float scale = 0.17677669529663687f;
    float mx[2][2] = {{-INFINITY,-INFINITY},{-INFINITY,-INFINITY}};
    #pragma unroll
    for (int mi = 0; mi < 2; mi++)
        #pragma unroll
        for (int ni = 0; ni < 16; ni++) {
            #pragma unroll
            for (int q = 0; q < 4; q++) s[mi][ni][q] *= scale;
            mx[mi][0] = fmaxf(mx[mi][0], fmaxf(s[mi][ni][0], s[mi][ni][1]));
            mx[mi][1] = fmaxf(mx[mi][1], fmaxf(s[mi][ni][2], s[mi][ni][3]));
        }
    #pragma unroll
    for (int mi = 0; mi < 2; mi++)
        #pragma unroll
        for (int hf = 0; hf < 2; hf++) {
            mx[mi][hf] = fmaxf(mx[mi][hf], __shfl_xor_sync(0xffffffffu, mx[mi][hf], 1));
            mx[mi][hf] = fmaxf(mx[mi][hf], __shfl_xor_sync(0xffffffffu, mx[mi][hf], 2));
        }
    float sum[2][2] = {};
    #pragma unroll
    for (int mi = 0; mi < 2; mi++)
        #pragma unroll
        for (int ni = 0; ni < 16; ni++) {
            s[mi][ni][0] = __expf(s[mi][ni][0] - mx[mi][0]);
            s[mi][ni][1] = __expf(s[mi][ni][1] - mx[mi][0]);
            s[mi][ni][2] = __expf(s[mi][ni][2] - mx[mi][1]);
            s[mi][ni][3] = __expf(s[mi][ni][3] - mx[mi][1]);
            sum[mi][0] += s[mi][ni][0] + s[mi][ni][1];
            sum[mi][1] += s[mi][ni][2] + s[mi][ni][3];
        }
    float inv[2][2];
    #pragma unroll
    for (int mi = 0; mi < 2; mi++)
        #pragma unroll
        for (int hf = 0; hf < 2; hf++) {
            float ss = sum[mi][hf];
            ss += __shfl_xor_sync(0xffffffffu, ss, 1);
            ss += __shfl_xor_sync(0xffffffffu, ss, 2);
            inv[mi][hf] = 1.f / ss;
        }

    float* Pw = Pb + warp * (32 * APW);
    float o[2][4][4] = {};
    #pragma unroll
    for (int hf = 0; hf < 2; hf++) {
        #pragma unroll
        for (int mi = 0; mi < 2; mi++) {
            int lr = mi * 16 + g;
            #pragma unroll
            for (int ni = 0; ni < 8; ni++) {
                int c = ni * 8 + 2 * t;
                Pw[ lr      *APW + c    ] = s[mi][hf*8 + ni][0];
                Pw[ lr      *APW + c + 1] = s[mi][hf*8 + ni][1];
                Pw[(lr + 8) *APW + c    ] = s[mi][hf*8 + ni][2];
                Pw[(lr + 8) *APW + c + 1] = s[mi][hf*8 + ni][3];
            }
        }
        __syncwarp();
        #pragma unroll
        for (int kk = 0; kk < 64; kk += 8) {
            uint32_t afrag[2][4];
            #pragma unroll
            for (int mi = 0; mi < 2; mi++) {
                int lr = mi * 16;
                afrag[mi][0] = FU(Pw[(lr + g    )*APW + kk + t    ]);
                afrag[mi][1] = FU(Pw[(lr + g + 8)*APW + kk + t    ]);
                afrag[mi][2] = FU(Pw[(lr + g    )*APW + kk + t + 4]);
                afrag[mi][3] = FU(Pw[(lr + g + 8)*APW + kk + t + 4]);
            }
            int j0 = hf*64 + kk + t, j1 = hf*64 + kk + t + 4;
            #pragma unroll
            for (int ni = 0; ni < 4; ni++) {
                int c = ni * 8;
                uint32_t b0 = FU(VT[(c + g)*AVS + j0]);
                uint32_t b1 = FU(VT[(c + g)*AVS + j1]);
                mma8(o[0][ni], afrag[0], b0, b1);
                mma8(o[1][ni], afrag[1], b0, b1);
            }
        }
        __syncwarp();
    }

    #pragma unroll
    for (int mi = 0; mi < 2; mi++) {
        int r0 = n*NP + m0 + mi * 16 + g;
        #pragma unroll
        for (int ni = 0; ni < 4; ni++) {
            int d = ni * 8 + 2 * t;
            *(float2*)(g_o + (size_t) r0      *DD + h*32 + d) =
                make_float2(o[mi][ni][0]*inv[mi][0], o[mi][ni][1]*inv[mi][0]);
            *(float2*)(g_o + (size_t)(r0 + 8) *DD + h*32 + d) =
                make_float2(o[mi][ni][2]*inv[mi][1], o[mi][ni][3]*inv[mi][1]);
        }
    }
}

// ---------------- mean over Np -----------------------------------------------
__global__ void k_mean()
{
    int n = blockIdx.x, d = threadIdx.x;
    float s = 0.f;
    for (int p = 0; p < NP; p++) s += g_Htemp[((size_t)n*NP + p)*DD + d];
    g_Hs[n*DD + d] = s * (1.f/128.f);
}

// ---------------- W_att = gat_w[h]^T @ att{src,dst}[h] -----------------------
__global__ void k_watt(const float* __restrict__ gw, const float* __restrict__ asv,
                       const float* __restrict__ adv)
{
    int idx = blockIdx.x * 256 + threadIdx.x;   // 1024 total
    int r = idx >> 7, d = idx & 127;
    int h = r & 3;
    const float* att = (r < 4) ? asv : adv;
    float s = 0.f;
    for (int f = 0; f < 128; f++)
        s += att[h*FF + f] * gw[h*FF*DD + f*DD + d];
    g_watt[r*DD + d] = s;
}

// ---------------- asrc/adst = H_temp @ W_att^T, scattered layout -------------
__global__ void k_asd()
{
    __shared__ float4 W4[8][32];
    int tid = threadIdx.x, warp = tid >> 5, lane = tid & 31;
    for (int i = tid; i < 256; i += 256)
        ((float4*)W4)[i] = ((const float4*)g_watt)[i];
    __syncthreads();
    int tok = blockIdx.x * 8 + warp;
    float4 v = ((const float4*)(g_Htemp + (size_t)tok * DD))[lane];
    int p = tok & 127, bs = tok >> 7;
    int s = bs & 63, b = bs >> 6;
    #pragma unroll
    for (int r = 0; r < 8; r++) {
        float4 w = W4[r][lane];
        float a = v.x*w.x + v.y*w.y + v.z*w.z + v.w*w.w;
        #pragma unroll
        for (int o = 16; o; o >>= 1) a += __shfl_xor_sync(0xffffffffu, a, o);
        if (lane == 0) {
            int h = r & 3;
            float* dst = (r < 4) ? g_asrc : g_adst;
            dst[(((b*4 + h)*128 + p)*64) + s] = a;
        }
    }
}

// ---------------- graph adjacency --------------------------------------------
__global__ void k_graph(const float* __restrict__ adj)
{
    __shared__ float k2s[CC*DK];
    __shared__ float Amat[CC*65];
    int b = blockIdx.x, c = threadIdx.x;
    for (int idx = c; idx < CC*DK; idx += 64) k2s[idx] = g_k2[(size_t)b*CC*DK + idx];
    __syncthreads();
    float qreg[DK];
    #pragma unroll
    for (int d = 0; d < DK; d++) qreg[d] = g_q2[(size_t)b*CC*DK + c*DK + d];
    for (int e = 0; e < CC; e++) {
        float a = 0.f;
        #pragma unroll
        for (int d = 0; d < DK; d++) a += qreg[d] * k2s[e*DK + d];
        Amat[c*65 + e] = tanhf(a * 0.125f) + adj[c*CC + e];
    }
    for (int e = 0; e < CC; e++) g_mask[(size_t)b*CC*CC + c*CC + e] = 0.f;
    for (int kk = 0; kk < 8; kk++) {
        float best = -INFINITY; int bi = 0;
        for (int e = 0; e < CC; e++) {
            float v = Amat[c*65 + e];
            if (v > best) { best = v; bi = e; }
        }
        if (bi != c && best != 0.f) g_mask[(size_t)b*CC*CC + c*CC + bi] = 1.f;
        Amat[c*65 + bi] = -INFINITY;
    }
}

// ============== GAT v2 (R7-proven) + __expf ==================================
#define XST 68
#define AST 68
#define OST 132
#define GU  8704          // 128*68
__global__ void __launch_bounds__(256)
k_gat(const float* __restrict__ gbias, const float* __restrict__ sg,
      const float* __restrict__ sb, float* __restrict__ out)
{
    extern __shared__ float sm[];
    float* U   = sm;
    float* Awt = sm + GU;
    float* Asv = sm + GU + 4352;
    float* Adv = sm + GU + 4416;
    float* XhT = U;
    float* Os  = U;

    int b = blockIdx.x >> 7, p = blockIdx.x & 127;
    int tid = threadIdx.x, w = tid >> 5, lane = tid & 31;
    int wm = w >> 2, wn = w & 3;
    int g = lane >> 2, t4 = lane & 3;

    float mr0[8], mr1[8];
    #pragma unroll
    for (int i = 0; i < 8; i++) {
        int t = w*8 + i;
        mr0[i] = g_mask[(size_t)b*CC*CC + lane*CC + t];
        mr1[i] = g_mask[(size_t)b*CC*CC + (lane+32)*CC + t];
    }

    float acc[2][4][4] = {};
    for (int h = 0; h < HS; h++) {
        __syncthreads();
        for (int idx = tid; idx < CC*FF; idx += 256) {
            int s = idx >> 7, f = idx & 127;
            XhT[f*XST + s] = g_xh[(size_t)(((b*CC + s)*NP + p))*(HS*FF) + h*FF + f];
        }
        if (tid < 64)            Asv[tid]      = g_asrc[(((b*4 + h)*128 + p)*64) + tid];
        else if (tid < 128)      Adv[tid - 64] = g_adst[(((b*4 + h)*128 + p)*64) + tid - 64];
        __syncthreads();

        #pragma unroll
        for (int i = 0; i < 8; i++) {
            int t = w*8 + i;
            float adt = Adv[t];
            float e0 = Asv[lane]      + adt; e0 = e0 > 0.f ? e0 : 0.2f*e0;
            float e1 = Asv[lane + 32] + adt; e1 = e1 > 0.f ? e1 : 0.2f*e1;
            float me = fmaxf(mr0[i] > 0.5f ? e0 : GAT_NEG, mr1[i] > 0.5f ? e1 : GAT_NEG);
            #pragma unroll
            for (int o = 16; o; o >>= 1) me = fmaxf(me, __shfl_xor_sync(0xffffffffu, me, o));
            float w0 = (mr0[i] > 0.5f) ? __expf(e0 - me) : 0.f;
            float w1 = (mr1[i] > 0.5f) ? __expf(e1 - me) : 0.f;
            float ws = w0 + w1;
            #pragma unroll
            for (int o = 16; o; o >>= 1) ws += __shfl_xor_sync(0xffffffffu, ws, o);
            float inv = ws > 0.f ? 1.f / ws : 0.f;
            Awt[t*AST + lane]      = w0 * inv;
            Awt[t*AST + lane + 32] = w1 * inv;
        }
        __syncthreads();

        #pragma unroll
        for (int kk = 0; kk < CC; kk += 8) {
            uint32_t afrag[2][4];
            #pragma unroll
            for (int mi = 0; mi < 2; mi++) {
                int r = wm * 32 + mi * 16;
                afrag[mi][0] = FU(Awt[(r + g    )*AST + kk + t4    ]);
                afrag[mi][1] = FU(Awt[(r + g + 8)*AST + kk + t4    ]);
                afrag[mi][2] = FU(Awt[(r + g    )*AST + kk + t4 + 4]);
                afrag[mi][3] = FU(Awt[(r + g + 8)*AST + kk + t4 + 4]);
            }
            #pragma unroll
            for (int ni = 0; ni < 4; ni++) {
                int c = wn * 32 + ni * 8;
                uint32_t b0 = FU(XhT[(c + g)*XST + kk + t4    ]);
                uint32_t b1 = FU(XhT[(c + g)*XST + kk + t4 + 4]);
                mma8(acc[0][ni], afrag[0], b0, b1);
                mma8(acc[1][ni], afrag[1], b0, b1);
            }
        }
    }

    __syncthreads();
    for (int idx = tid; idx < CC*DD; idx += 256) {
        int r = idx >> 7, f = idx & 127;
        Os[r*OST + f] = g_Htemp[(((size_t)(b*CC + r))*NP + p)*DD + f] + gbias[f];
    }
    __syncthreads();
    #pragma unroll
    for (int mi = 0; mi < 2; mi++)
        #pragma unroll
        for (int ni = 0; ni < 4; ni++) {
            int r = wm*32 + mi*16 + g;
            int c = wn*32 + ni*8 + 2*t4;
            #pragma unroll
            for (int half = 0; half < 2; half++) {
                int row = r + half*8;
                Os[row*OST + c    ] += acc[mi][ni][half*2 + 0] * 0.25f;
                Os[row*OST + c + 1] += acc[mi][ni][half*2 + 1] * 0.25f;
            }
        }
    __syncthreads();
    {
        float4 g4 = ((const float4*)sg)[lane];
        float4 b4 = ((const float4*)sb)[lane];
        for (int r = w; r < CC; r += 8) {
            float4 v = *(float4*)&Os[r*OST + lane*4];
            float s1 = v.x + v.y + v.z + v.w;
            #pragma unroll
            for (int o = 16; o; o >>= 1) s1 += __shfl_xor_sync(0xffffffffu, s1, o);
            float mean = s1 * (1.f/128.f);
            float dx=v.x-mean, dy=v.y-mean, dz=v.z-mean, dw=v.w-mean;
            float q = dx*dx+dy*dy+dz*dz+dw*dw;
            #pragma unroll
            for (int o = 16; o; o >>= 1) q += __shfl_xor_sync(0xffffffffu, q, o);
            float inv = rsqrtf(q * (1.f/128.f) + 1e-5f);
            float4 ov;
            ov.x = dx*inv*g4.x + b4.x; ov.y = dy*inv*g4.y + b4.y;
            ov.z = dz*inv*g4.z + b4.z; ov.w = dw*inv*g4.w + b4.w;
            ((float4*)(out + (((size_t)(b*CC + r))*NP + p)*DD))[lane] = ov;
        }
    }
}

// ---------------- host launch -------------------------------------------------
extern "C" void kernel_launch(void* const* d_in, const int* in_sizes, int n_in,
                              void* d_out, int out_size)
{
    const float* H_in      = (const float*)d_in[0];
    const float* static_adj= (const float*)d_in[1];
    const float* attn_in_w = (const float*)d_in[2];
    const float* attn_in_b = (const float*)d_in[3];
    const float* attn_out_w= (const float*)d_in[4];
    const float* attn_out_b= (const float*)d_in[5];
    const float* ln1_g     = (const float*)d_in[6];
    const float* ln1_b     = (const float*)d_in[7];
    const float* ln2_g     = (const float*)d_in[8];
    const float* ln2_b     = (const float*)d_in[9];
    const float* ff1_w     = (const float*)d_in[10];
    const float* ff1_b     = (const float*)d_in[11];
    const float* ff2_w     = (const float*)d_in[12];
    const float* ff2_b     = (const float*)d_in[13];
    const float* tnorm_g   = (const float*)d_in[14];
    const float* tnorm_b   = (const float*)d_in[15];
    const float* q_w       = (const float*)d_in[16];
    const float* q_b       = (const float*)d_in[17];
    const float* k_w       = (const float*)d_in[18];
    const float* k_b       = (const float*)d_in[19];
    const float* gat_w     = (const float*)d_in[20];
    const float* gat_att_src = (const float*)d_in[21];
    const float* gat_att_dst = (const float*)d_in[22];
    const float* gat_bias  = (const float*)d_in[23];
    const float* snorm_g   = (const float*)d_in[24];
    const float* snorm_b   = (const float*)d_in[25];

    float *h_, *qkv_, *o_, *x_, *ff_, *Htemp_, *xh_, *Hs_, *q2_, *k2_;
    cudaGetSymbolAddress((void**)&h_,     g_h);
    cudaGetSymbolAddress((void**)&qkv_,   g_qkv);
    cudaGetSymbolAddress((void**)&o_,     g_o);
    cudaGetSymbolAddress((void**)&x_,     g_x);
    cudaGetSymbolAddress((void**)&ff_,    g_ff);
    cudaGetSymbolAddress((void**)&Htemp_, g_Htemp);
    cudaGetSymbolAddress((void**)&xh_,    g_xh);
    cudaGetSymbolAddress((void**)&Hs_,    g_Hs);
    cudaGetSymbolAddress((void**)&q2_,    g_q2);
    cudaGetSymbolAddress((void**)&k2_,    g_k2);

    const int mma_smem  = 4 * TILE * 4;                // 73728
    const int attn_smem = 13440 * 4;                   // 53760
    const int gat_smem  = (GU + 4352 + 128) * 4;       // 52736
    cudaFuncSetAttribute(k_mma, cudaFuncAttributeMaxDynamicSharedMemorySize, mma_smem);
    cudaFuncSetAttribute(k_mma_ln, cudaFuncAttributeMaxDynamicSharedMemorySize, mma_smem);
    cudaFuncSetAttribute(k_attn_mma, cudaFuncAttributeMaxDynamicSharedMemorySize, attn_smem);
    cudaFuncSetAttribute(k_gat,  cudaFuncAttributeMaxDynamicSharedMemorySize, gat_smem);

    // 0) W_att vectors
    k_watt<<<4, 256>>>(gat_w, gat_att_src, gat_att_dst);
    // 1) h = ln1(x0)
    k_ln<<<NTOK/8, 256>>>(H_in, nullptr, ln1_g, ln1_b, h_);
    // 2) qkv = h @ Wqkv^T + b
    k_mma<<<dim3(3, NTOK/TBM), 256, mma_smem>>>(h_, attn_in_w, attn_in_b, nullptr, qkv_,
                                                NTOK, 384, 128, 0);
    // 3) temporal attention v4
    k_attn_mma<<<NSEQ*HT, 128, attn_smem>>>();
    // 4+5) x1 = x0 + o@Wout^T + b ; h = ln2(x1)    (fused, smem-staged LN)
    k_mma_ln<<<dim3(1, NTOK/TBM), 256, mma_smem>>>(o_, attn_out_w, attn_out_b, H_in,
                                                   nullptr, x_, h_, ln2_g, ln2_b, 128);
    // 6) ff = relu(h @ W1^T + b1)
    k_mma<<<dim3(4, NTOK/TBM), 256, mma_smem>>>(h_, ff1_w, ff1_b, nullptr, ff_,
                                                NTOK, 512, 128, 1);
    // 7+8) Htemp = tnorm(x0 + x1 + ff@W2^T + b2)   (fused; x2 never written)
    k_mma_ln<<<dim3(1, NTOK/TBM), 256, mma_smem>>>(ff_, ff2_w, ff2_b, x_,
                                                   H_in, nullptr, Htemp_, tnorm_g, tnorm_b, 512);
    // 9) xh = H_temp @ gat_w^T
    k_mma<<<dim3(4, NTOK/TBM), 256, mma_smem>>>(Htemp_, gat_w, nullptr, nullptr, xh_,
                                                NTOK, 512, 128, 0);
    // 10) asrc/adst
    k_asd<<<NTOK/8, 256>>>();
    // 11) Hs = mean_p(H_temp)
    k_mean<<<NSEQ, 128>>>();
    // 12) q2, k2
    k_gemm<<<dim3(1, NSEQ/BM), 256>>>(Hs_, q_w, q_b, q2_, NSEQ, 64, 128);
    k_gemm<<<dim3(1, NSEQ/BM), 256>>>(Hs_, k_w, k_b, k2_, NSEQ, 64, 128);
    // 13) adjacency / top-k / mask
    k_graph<<<BB, 64>>>(static_adj);
    // 14) GAT v2 + snorm LN -> output
    k_gat<<<BB*NP, 256, gat_smem>>>(gat_bias, snorm_g, snorm_b, (float*)d_out);
}

// round 12
// speedup vs baseline: 1.1166x; 1.1166x over previous
#include <cuda_runtime.h>
#include <cuda_bf16.h>
#include <math.h>
#include <stdint.h>

#define BB   16
#define CC   64
#define NP   128
#define DD   128
#define HT   4
#define DH   32
#define HS   4
#define FF   128
#define DK   64
#define NTOK (BB*CC*NP)      // 131072
#define NSEQ (BB*CC)         // 1024
#define GAT_NEG -1e30f

// ---------------- scratch ----------------------------------------------------
__device__ float g_h[NTOK*DD];
__device__ float g_qkv[(size_t)NTOK*3*DD];
__device__ float g_o[NTOK*DD];
__device__ float g_x[NTOK*DD];
__device__ float g_ff[(size_t)NTOK*4*DD];
__device__ float g_Htemp[NTOK*DD];
__device__ __nv_bfloat16 g_xhb[(size_t)NTOK*HS*FF];   // bf16 xh
__device__ float g_Hs[NSEQ*DD];
__device__ float g_q2[NSEQ*DK];
__device__ float g_k2[NSEQ*DK];
__device__ float g_mask[BB*CC*CC];
__device__ float g_watt[8*DD];             // rows 0-3: w_src[h], 4-7: w_dst[h]
__device__ float g_asrc[BB*HS*NP*CC];      // [b][h][p][s]
__device__ float g_adst[BB*HS*NP*CC];

// ---------------- helpers ----------------------------------------------------
__device__ __forceinline__ void mma8(float c[4], const uint32_t a[4],
                                     uint32_t b0, uint32_t b1) {
    asm volatile(
        "mma.sync.aligned.m16n8k8.row.col.f32.tf32.tf32.f32 "
        "{%0,%1,%2,%3}, {%4,%5,%6,%7}, {%8,%9}, {%0,%1,%2,%3};"
        : "+f"(c[0]), "+f"(c[1]), "+f"(c[2]), "+f"(c[3])
        : "r"(a[0]), "r"(a[1]), "r"(a[2]), "r"(a[3]), "r"(b0), "r"(b1));
}
__device__ __forceinline__ void cp_async16(float* smem, const float* gmem) {
    uint32_t s = (uint32_t)__cvta_generic_to_shared(smem);
    asm volatile("cp.async.cg.shared.global [%0], [%1], 16;" :: "r"(s), "l"(gmem));
}
#define FU(x) __float_as_uint(x)

// ---------------- LayerNorm: warp per row, optional fused add ----------------
__global__ void k_ln(const float* __restrict__ x, const float* __restrict__ add,
                     const float* __restrict__ gw, const float* __restrict__ bw,
                     float* __restrict__ out)
{
    int row  = blockIdx.x * 8 + (threadIdx.x >> 5);
    int lane = threadIdx.x & 31;
    const float4* xp = (const float4*)(x + (size_t)row * DD);
    float4 v = xp[lane];
    if (add) {
        float4 a = ((const float4*)(add + (size_t)row * DD))[lane];
        v.x += a.x; v.y += a.y; v.z += a.z; v.w += a.w;
    }
    float s = v.x + v.y + v.z + v.w;
    #pragma unroll
    for (int o = 16; o; o >>= 1) s += __shfl_xor_sync(0xffffffffu, s, o);
    float mean = s * (1.f/128.f);
    float dx = v.x-mean, dy = v.y-mean, dz = v.z-mean, dw = v.w-mean;
    float q = dx*dx + dy*dy + dz*dz + dw*dw;
    #pragma unroll
    for (int o = 16; o; o >>= 1) q += __shfl_xor_sync(0xffffffffu, q, o);
    float inv = rsqrtf(q * (1.f/128.f) + 1e-5f);
    float4 g4 = ((const float4*)gw)[lane];
    float4 b4 = ((const float4*)bw)[lane];
    float4 o4;
    o4.x = dx*inv*g4.x + b4.x;  o4.y = dy*inv*g4.y + b4.y;
    o4.z = dz*inv*g4.z + b4.z;  o4.w = dw*inv*g4.w + b4.w;
    ((float4*)(out + (size_t)row * DD))[lane] = o4;
}

// ---------------- tf32 GEMM, cp.async 2-stage pipeline (R7-proven) -----------
#define TBM 128
#define TBN 128
#define TILE (128*36)
__global__ void __launch_bounds__(256)
k_mma(const float* __restrict__ A, const float* __restrict__ W,
      const float* __restrict__ bias, const float* __restrict__ res,
      float* __restrict__ out, int M, int N, int K, int relu)
{
    extern __shared__ float smbuf[];
    float* As = smbuf;             // [2][128][36]
    float* Bs = smbuf + 2*TILE;    // [2][128][36]
    int tid  = threadIdx.x;
    int warp = tid >> 5, lane = tid & 31;
    int wm = warp >> 1, wn = warp & 1;
    int g = lane >> 2, t = lane & 3;
    int m0 = blockIdx.y * TBM;
    int n0 = blockIdx.x * TBN;
    int lr = tid >> 3, lc = (tid & 7) << 2;

    float acc[2][8][4] = {};
    const int nk = K >> 5;

    #pragma unroll
    for (int i = 0; i < 4; i++) {
        int r = lr + i * 32;
        cp_async16(&As[r*36 + lc], A + (size_t)(m0 + r) * K + lc);
        cp_async16(&Bs[r*36 + lc], W + (size_t)(n0 + r) * K + lc);
    }
    asm volatile("cp.async.commit_group;");

    for (int kt = 0; kt < nk; kt++) {
        int buf = (kt & 1) * TILE;
        if (kt + 1 < nk) {
            int nb = ((kt + 1) & 1) * TILE;
            int ko = (kt + 1) << 5;
            #pragma unroll
            for (int i = 0; i < 4; i++) {
                int r = lr + i * 32;
                cp_async16(&As[nb + r*36 + lc], A + (size_t)(m0 + r) * K + ko + lc);
                cp_async16(&Bs[nb + r*36 + lc], W + (size_t)(n0 + r) * K + ko + lc);
            }
            asm volatile("cp.async.commit_group;");
            asm volatile("cp.async.wait_group 1;");
        } else {
            asm volatile("cp.async.wait_group 0;");
        }
        __syncthreads();
        #pragma unroll
        for (int kk = 0; kk < 32; kk += 8) {
            uint32_t afrag[2][4];
            #pragma unroll
            for (int mi = 0; mi < 2; mi++) {
                int r = wm * 32 + mi * 16;
                afrag[mi][0] = FU(As[buf + (r + g    )*36 + kk + t    ]);
                afrag[mi][1] = FU(As[buf + (r + g + 8)*36 + kk + t    ]);
                afrag[mi][2] = FU(As[buf + (r + g    )*36 + kk + t + 4]);
                afrag[mi][3] = FU(As[buf + (r + g + 8)*36 + kk + t + 4]);
            }
            #pragma unroll
            for (int ni = 0; ni < 8; ni++) {
                int c = wn * 64 + ni * 8;
                uint32_t b0 = FU(Bs[buf + (c + g)*36 + kk + t    ]);
                uint32_t b1 = FU(Bs[buf + (c + g)*36 + kk + t + 4]);
                mma8(acc[0][ni], afrag[0], b0, b1);
                mma8(acc[1][ni], afrag[1], b0, b1);
            }
        }
        __syncthreads();
    }

    #pragma unroll
    for (int mi = 0; mi < 2; mi++) {
        #pragma unroll
        for (int ni = 0; ni < 8; ni++) {
            int r = m0 + wm * 32 + mi * 16 + g;
            int c = n0 + wn * 64 + ni * 8 + 2 * t;
            float bv0 = bias ? bias[c]     : 0.f;
            float bv1 = bias ? bias[c + 1] : 0.f;
            #pragma unroll
            for (int half = 0; half < 2; half++) {
                int row = r + half * 8;
                float v0 = acc[mi][ni][half*2 + 0] + bv0;
                float v1 = acc[mi][ni][half*2 + 1] + bv1;
                if (relu) { v0 = fmaxf(v0, 0.f); v1 = fmaxf(v1, 0.f); }
                if (res) {
                    const float2 rr = *(const float2*)(res + (size_t)row * N + c);
                    v0 += rr.x; v1 += rr.y;
                }
                *(float2*)(out + (size_t)row * N + c) = make_float2(v0, v1);
            }
        }
    }
}

// ---------------- tf32 GEMM -> bf16 output (xh only; no bias/res/relu) -------
__global__ void __launch_bounds__(256)
k_mma_bf(const float* __restrict__ A, const float* __restrict__ W,
         __nv_bfloat16* __restrict__ out, int N, int K)
{
    extern __shared__ float smbuf[];
    float* As = smbuf;
    float* Bs = smbuf + 2*TILE;
    int tid  = threadIdx.x;
    int warp = tid >> 5, lane = tid & 31;
    int wm = warp >> 1, wn = warp & 1;
    int g = lane >> 2, t = lane & 3;
    int m0 = blockIdx.y * TBM;
    int n0 = blockIdx.x * TBN;
    int lr = tid >> 3, lc = (tid & 7) << 2;

    float acc[2][8][4] = {};
    const int nk = K >> 5;

    #pragma unroll
    for (int i = 0; i < 4; i++) {
        int r = lr + i * 32;
        cp_async16(&As[r*36 + lc], A + (size_t)(m0 + r) * K + lc);
        cp_async16(&Bs[r*36 + lc], W + (size_t)(n0 + r) * K + lc);
    }
    asm volatile("cp.async.commit_group;");

    for (int kt = 0; kt < nk; kt++) {
        int buf = (kt & 1) * TILE;
        if (kt + 1 < nk) {
            int nb = ((kt + 1) & 1) * TILE;
            int ko = (kt + 1) << 5;
            #pragma unroll
            for (int i = 0; i < 4; i++) {
                int r = lr + i * 32;
                cp_async16(&As[nb + r*36 + lc], A + (size_t)(m0 + r) * K + ko + lc);
                cp_async16(&Bs[nb + r*36 + lc], W + (size_t)(n0 + r) * K + ko + lc);
            }
            asm volatile("cp.async.commit_group;");
            asm volatile("cp.async.wait_group 1;");
        } else {
            asm volatile("cp.async.wait_group 0;");
        }
        __syncthreads();
        #pragma unroll
        for (int kk = 0; kk < 32; kk += 8) {
            uint32_t afrag[2][4];
            #pragma unroll
            for (int mi = 0; mi < 2; mi++) {
                int r = wm * 32 + mi * 16;
                afrag[mi][0] = FU(As[buf + (r + g    )*36 + kk + t    ]);
                afrag[mi][1] = FU(As[buf + (r + g + 8)*36 + kk + t    ]);
                afrag[mi][2] = FU(As[buf + (r + g    )*36 + kk + t + 4]);
                afrag[mi][3] = FU(As[buf + (r + g + 8)*36 + kk + t + 4]);
            }
            #pragma unroll
            for (int ni = 0; ni < 8; ni++) {
                int c = wn * 64 + ni * 8;
                uint32_t b0 = FU(Bs[buf + (c + g)*36 + kk + t    ]);
                uint32_t b1 = FU(Bs[buf + (c + g)*36 + kk + t + 4]);
                mma8(acc[0][ni], afrag[0], b0, b1);
                mma8(acc[1][ni], afrag[1], b0, b1);
            }
        }
        __syncthreads();
    }

    #pragma unroll
    for (int mi = 0; mi < 2; mi++) {
        #pragma unroll
        for (int ni = 0; ni < 8; ni++) {
            int r = m0 + wm * 32 + mi * 16 + g;
            int c = n0 + wn * 64 + ni * 8 + 2 * t;
            #pragma unroll
            for (int half = 0; half < 2; half++) {
                int row = r + half * 8;
                __nv_bfloat162 bv = __floats2bfloat162_rn(acc[mi][ni][half*2 + 0],
                                                          acc[mi][ni][half*2 + 1]);
                *(__nv_bfloat162*)(out + (size_t)row * N + c) = bv;
            }
        }
    }
}

// ---------------- small SIMT GEMM (q2/k2) ------------------------------------
#define BM 64
#define BN 64
#define BK 16
__global__ void k_gemm(const float* __restrict__ A, const float* __restrict__ W,
                       const float* __restrict__ bias, float* __restrict__ out,
                       int M, int N, int K)
{
    __shared__ float As[BK][BM];
    __shared__ float Bs[BK][BN];
    int tid = threadIdx.x;
    int tx = tid & 15, ty = tid >> 4;
    int m0 = blockIdx.y * BM, n0 = blockIdx.x * BN;
    int lr = tid >> 2;
    int lk = (tid & 3) * 4;
    float acc[4][4] = {};
    for (int k0 = 0; k0 < K; k0 += BK) {
        float4 a4 = *(const float4*)(A + (size_t)(m0 + lr) * K + k0 + lk);
        float4 b4 = *(const float4*)(W + (size_t)(n0 + lr) * K + k0 + lk);
        As[lk+0][lr] = a4.x; As[lk+1][lr] = a4.y; As[lk+2][lr] = a4.z; As[lk+3][lr] = a4.w;
        Bs[lk+0][lr] = b4.x; Bs[lk+1][lr] = b4.y; Bs[lk+2][lr] = b4.z; Bs[lk+3][lr] = b4.w;
        __syncthreads();
        #pragma unroll
        for (int k = 0; k < BK; k++) {
            float4 ra = *(const float4*)&As[k][ty*4];
            float4 rb = *(const float4*)&Bs[k][tx*4];
            float av[4] = {ra.x, ra.y, ra.z, ra.w};
            float bv[4] = {rb.x, rb.y, rb.z, rb.w};
            #pragma unroll
            for (int i = 0; i < 4; i++)
                #pragma unroll
                for (int j = 0; j < 4; j++)
                    acc[i][j] += av[i] * bv[j];
        }
        __syncthreads();
    }
    #pragma unroll
    for (int i = 0; i < 4; i++) {
        int m = m0 + ty*4 + i;
        #pragma unroll
        for (int j = 0; j < 4; j++) {
            int n = n0 + tx*4 + j;
            out[(size_t)m * N + n] = acc[i][j] + bias[n];
        }
    }
}

// ============== attention v4 (R10-proven) ====================================
#define AQS 36
#define AVS 132
#define APW 68
__global__ void __launch_bounds__(128, 3)
k_attn_mma()
{
    extern __shared__ float sm[];
    float* Qs = sm;                  // [128][36]
    float* Ks = sm + 4608;           // [128][36]
    float* VT = sm + 9216;           // [32][132]
    float* Pb = sm;                  // union: per-warp [32][68]

    int n = blockIdx.x >> 2, h = blockIdx.x & 3;
    int tid = threadIdx.x;
    int warp = tid >> 5, lane = tid & 31;
    int g = lane >> 2, t = lane & 3;
    int m0 = warp * 32;
    const float* base = g_qkv + (size_t)n * NP * 3 * DD;

    for (int idx = tid; idx < NP*DH; idx += 128) {
        int j = idx >> 5, d = idx & 31;
        Qs[j*AQS + d] = base[j*384 +       h*32 + d];
        Ks[j*AQS + d] = base[j*384 + 128 + h*32 + d];
        VT[d*AVS + j] = base[j*384 + 256 + h*32 + d];
    }
    __syncthreads();

    float s[2][16][4] = {};
    #pragma unroll
    for (int kk = 0; kk < 32; kk += 8) {
        uint32_t afrag[2][4];
        #pragma unroll
        for (int mi = 0; mi < 2; mi++) {
            int r = m0 + mi * 16;
            afrag[mi][0] = FU(Qs[(r + g    )*AQS + kk + t    ]);
            afrag[mi][1] = FU(Qs[(r + g + 8)*AQS + kk + t    ]);
            afrag[mi][2] = FU(Qs[(r + g    )*AQS + kk + t + 4]);
            afrag[mi][3] = FU(Qs[(r + g + 8)*AQS + kk + t + 4]);
        }
        #pragma unroll
        for (int ni = 0; ni < 16; ni++) {
            int c = ni * 8;
            uint32_t b0 = FU(Ks[(c + g)*AQS + kk + t    ]);
            uint32_t b1 = FU(Ks[(c + g)*AQS + kk + t + 4]);
            mma8(s[0][ni], afrag[0], b0, b1);
            mma8(s[1][ni], afrag[1], b0, b1);
        }
    }
    __syncthreads();

    const float scale = 0.17677669529663687f;
    float mx[2][2] = {{-INFINITY,-INFINITY},{-INFINITY,-INFINITY}};
    #pragma unroll
    for (int mi = 0; mi < 2; mi++)
        #pragma unroll
        for (int ni = 0; ni < 16; ni++) {
            #pragma unroll
            for (int q = 0; q < 4; q++) s[mi][ni][q] *= scale;
            mx[mi][0] = fmaxf(mx[mi][0], fmaxf(s[mi][ni][0], s[mi][ni][1]));
            mx[mi][1] = fmaxf(mx[mi][1], fmaxf(s[mi][ni][2], s[mi][ni][3]));
        }
    #pragma unroll
    for (int mi = 0; mi < 2; mi++)
        #pragma unroll
        for (int hf = 0; hf < 2; hf++) {
            mx[mi][hf] = fmaxf(mx[mi][hf], __shfl_xor_sync(0xffffffffu, mx[mi][hf], 1));
            mx[mi][hf] = fmaxf(mx[mi][hf], __shfl_xor_sync(0xffffffffu, mx[mi][hf], 2));
        }
    float sum[2][2] = {};
    #pragma unroll
    for (int mi = 0; mi < 2; mi++)
        #pragma unroll
        for (int ni = 0; ni < 16; ni++) {
            s[mi][ni][0] = __expf(s[mi][ni][0] - mx[mi][0]);
            s[mi][ni][1] = __expf(s[mi][ni][1] - mx[mi][0]);
            s[mi][ni][2] = __expf(s[mi][ni][2] - mx[mi][1]);
            s[mi][ni][3] = __expf(s[mi][ni][3] - mx[mi][1]);
            sum[mi][0] += s[mi][ni][0] + s[mi][ni][1];
            sum[mi][1] += s[mi][ni][2] + s[mi][ni][3];
        }
    float inv[2][2];
    #pragma unroll
    for (int mi = 0; mi < 2; mi++)
        #pragma unroll
        for (int hf = 0; hf < 2; hf++) {
            float ss = sum[mi][hf];
            ss += __shfl_xor_sync(0xffffffffu, ss, 1);
            ss += __shfl_xor_sync(0xffffffffu, ss, 2);
            inv[mi][hf] = 1.f / ss;
        }

    float* Pw = Pb + warp * (32 * APW);
    float o[2][4][4] = {};
    #pragma unroll
    for (int hf = 0; hf < 2; hf++) {
        #pragma unroll
        for (int mi = 0; mi < 2; mi++) {
            int lr = mi * 16 + g;
            #pragma unroll
            for (int ni = 0; ni < 8; ni++) {
                int c = ni * 8 + 2 * t;
                Pw[ lr      *APW + c    ] = s[mi][hf*8 + ni][0];
                Pw[ lr      *APW + c + 1] = s[mi][hf*8 + ni][1];
                Pw[(lr + 8) *APW + c    ] = s[mi][hf*8 + ni][2];
                Pw[(lr + 8) *APW + c + 1] = s[mi][hf*8 + ni][3];
            }
        }
        __syncwarp();
        #pragma unroll
        for (int kk = 0; kk < 64; kk += 8) {
            uint32_t afrag[2][4];
            #pragma unroll
            for (int mi = 0; mi < 2; mi++) {
                int lr = mi * 16;
                afrag[mi][0] = FU(Pw[(lr + g    )*APW + kk + t    ]);
                afrag[mi][1] = FU(Pw[(lr + g + 8)*APW + kk + t    ]);
                afrag[mi][2] = FU(Pw[(lr + g    )*APW + kk + t + 4]);
                afrag[mi][3] = FU(Pw[(lr + g + 8)*APW + kk + t + 4]);
            }
            int j0 = hf*64 + kk + t, j1 = hf*64 + kk + t + 4;
            #pragma unroll
            for (int ni = 0; ni < 4; ni++) {
                int c = ni * 8;
                uint32_t b0 = FU(VT[(c + g)*AVS + j0]);
                uint32_t b1 = FU(VT[(c + g)*AVS + j1]);
                mma8(o[0][ni], afrag[0], b0, b1);
                mma8(o[1][ni], afrag[1], b0, b1);
            }
        }
        __syncwarp();
    }

    #pragma unroll
    for (int mi = 0; mi < 2; mi++) {
        int r0 = n*NP + m0 + mi * 16 + g;
        #pragma unroll
        for (int ni = 0; ni < 4; ni++) {
            int d = ni * 8 + 2 * t;
            *(float2*)(g_o + (size_t) r0      *DD + h*32 + d) =
                make_float2(o[mi][ni][0]*inv[mi][0], o[mi][ni][1]*inv[mi][0]);
            *(float2*)(g_o + (size_t)(r0 + 8) *DD + h*32 + d) =
                make_float2(o[mi][ni][2]*inv[mi][1], o[mi][ni][3]*inv[mi][1]);
        }
    }
}

// ---------------- mean over Np -----------------------------------------------
__global__ void k_mean()
{
    int n = blockIdx.x, d = threadIdx.x;
    float s = 0.f;
    for (int p = 0; p < NP; p++) s += g_Htemp[((size_t)n*NP + p)*DD + d];
    g_Hs[n*DD + d] = s * (1.f/128.f);
}

// ---------------- W_att = gat_w[h]^T @ att{src,dst}[h] -----------------------
__global__ void k_watt(const float* __restrict__ gw, const float* __restrict__ asv,
                       const float* __restrict__ adv)
{
    int idx = blockIdx.x * 256 + threadIdx.x;   // 1024 total
    int r = idx >> 7, d = idx & 127;
    int h = r & 3;
    const float* att = (r < 4) ? asv : adv;
    float s = 0.f;
    for (int f = 0; f < 128; f++)
        s += att[h*FF + f] * gw[h*FF*DD + f*DD + d];
    g_watt[r*DD + d] = s;
}

// ---------------- asrc/adst = H_temp @ W_att^T, scattered layout -------------
__global__ void k_asd()
{
    __shared__ float4 W4[8][32];
    int tid = threadIdx.x, warp = tid >> 5, lane = tid & 31;
    for (int i = tid; i < 256; i += 256)
        ((float4*)W4)[i] = ((const float4*)g_watt)[i];
    __syncthreads();
    int tok = blockIdx.x * 8 + warp;
    float4 v = ((const float4*)(g_Htemp + (size_t)tok * DD))[lane];
    int p = tok & 127, bs = tok >> 7;
    int s = bs & 63, b = bs >> 6;
    #pragma unroll
    for (int r = 0; r < 8; r++) {
        float4 w = W4[r][lane];
        float a = v.x*w.x + v.y*w.y + v.z*w.z + v.w*w.w;
        #pragma unroll
        for (int o = 16; o; o >>= 1) a += __shfl_xor_sync(0xffffffffu, a, o);
        if (lane == 0) {
            int h = r & 3;
            float* dst = (r < 4) ? g_asrc : g_adst;
            dst[(((b*4 + h)*128 + p)*64) + s] = a;
        }
    }
}

// ---------------- graph adjacency --------------------------------------------
__global__ void k_graph(const float* __restrict__ adj)
{
    __shared__ float k2s[CC*DK];
    __shared__ float Amat[CC*65];
    int b = blockIdx.x, c = threadIdx.x;
    for (int idx = c; idx < CC*DK; idx += 64) k2s[idx] = g_k2[(size_t)b*CC*DK + idx];
    __syncthreads();
    float qreg[DK];
    #pragma unroll
    for (int d = 0; d < DK; d++) qreg[d] = g_q2[(size_t)b*CC*DK + c*DK + d];
    for (int e = 0; e < CC; e++) {
        float a = 0.f;
        #pragma unroll
        for (int d = 0; d < DK; d++) a += qreg[d] * k2s[e*DK + d];
        Amat[c*65 + e] = tanhf(a * 0.125f) + adj[c*CC + e];
    }
    for (int e = 0; e < CC; e++) g_mask[(size_t)b*CC*CC + c*CC + e] = 0.f;
    for (int kk = 0; kk < 8; kk++) {
        float best = -INFINITY; int bi = 0;
        for (int e = 0; e < CC; e++) {
            float v = Amat[c*65 + e];
            if (v > best) { best = v; bi = e; }
        }
        if (bi != c && best != 0.f) g_mask[(size_t)b*CC*CC + c*CC + bi] = 1.f;
        Amat[c*65 + bi] = -INFINITY;
    }
}

// ============== GAT v2 (R10-proven) + bf16 xh loads ==========================
#define XST 68
#define AST 68
#define OST 132
#define GU  8704          // 128*68
__global__ void __launch_bounds__(256)
k_gat(const float* __restrict__ gbias, const float* __restrict__ sg,
      const float* __restrict__ sb, float* __restrict__ out)
{
    extern __shared__ float sm[];
    float* U   = sm;
    float* Awt = sm + GU;
    float* Asv = sm + GU + 4352;
    float* Adv = sm + GU + 4416;
    float* XhT = U;
    float* Os  = U;

    int b = blockIdx.x >> 7, p = blockIdx.x & 127;
    int tid = threadIdx.x, w = tid >> 5, lane = tid & 31;
    int wm = w >> 2, wn = w & 3;
    int g = lane >> 2, t4 = lane & 3;

    float mr0[8], mr1[8];
    #pragma unroll
    for (int i = 0; i < 8; i++) {
        int t = w*8 + i;
        mr0[i] = g_mask[(size_t)b*CC*CC + lane*CC + t];
        mr1[i] = g_mask[(size_t)b*CC*CC + (lane+32)*CC + t];
    }

    float acc[2][4][4] = {};
    for (int h = 0; h < HS; h++) {
        __syncthreads();
        // bf16 loads: 2 elems per access, convert to fp32 into transposed smem
        for (int idx = tid; idx < CC*FF/2; idx += 256) {
            int s = idx >> 6, fp = idx & 63;
            const __nv_bfloat162 v2 = *(const __nv_bfloat162*)
                (g_xhb + (size_t)(((b*CC + s)*NP + p))*(HS*FF) + h*FF + 2*fp);
            float2 vf = __bfloat1622float2(v2);
            XhT[(2*fp    )*XST + s] = vf.x;
            XhT[(2*fp + 1)*XST + s] = vf.y;
        }
        if (tid < 64)            Asv[tid]      = g_asrc[(((b*4 + h)*128 + p)*64) + tid];
        else if (tid < 128)      Adv[tid - 64] = g_adst[(((b*4 + h)*128 + p)*64) + tid - 64];
        __syncthreads();

        #pragma unroll
        for (int i = 0; i < 8; i++) {
            int t = w*8 + i;
            float adt = Adv[t];
            float e0 = Asv[lane]      + adt; e0 = e0 > 0.f ? e0 : 0.2f*e0;
            float e1 = Asv[lane + 32] + adt; e1 = e1 > 0.f ? e1 : 0.2f*e1;
            float me = fmaxf(mr0[i] > 0.5f ? e0 : GAT_NEG, mr1[i] > 0.5f ? e1 : GAT_NEG);
            #pragma unroll
            for (int o = 16; o; o >>= 1) me = fmaxf(me, __shfl_xor_sync(0xffffffffu, me, o));
            float w0 = (mr0[i] > 0.5f) ? __expf(e0 - me) : 0.f;
            float w1 = (mr1[i] > 0.5f) ? __expf(e1 - me) : 0.f;
            float ws = w0 + w1;
            #pragma unroll
            for (int o = 16; o; o >>= 1) ws += __shfl_xor_sync(0xffffffffu, ws, o);
            float inv = ws > 0.f ? 1.f / ws : 0.f;
            Awt[t*AST + lane]      = w0 * inv;
            Awt[t*AST + lane + 32] = w1 * inv;
        }
        __syncthreads();

        #pragma unroll
        for (int kk = 0; kk < CC; kk += 8) {
            uint32_t afrag[2][4];
            #pragma unroll
            for (int mi = 0; mi < 2; mi++) {
                int r = wm * 32 + mi * 16;
                afrag[mi][0] = FU(Awt[(r + g    )*AST + kk + t4    ]);
                afrag[mi][1] = FU(Awt[(r + g + 8)*AST + kk + t4    ]);
                afrag[mi][2] = FU(Awt[(r + g    )*AST + kk + t4 + 4]);
                afrag[mi][3] = FU(Awt[(r + g + 8)*AST + kk + t4 + 4]);
            }
            #pragma unroll
            for (int ni = 0; ni < 4; ni++) {
                int c = wn * 32 + ni * 8;
                uint32_t b0 = FU(XhT[(c + g)*XST + kk + t4    ]);
                uint32_t b1 = FU(XhT[(c + g)*XST + kk + t4 + 4]);
                mma8(acc[0][ni], afrag[0], b0, b1);
                mma8(acc[1][ni], afrag[1], b0, b1);
            }
        }
    }

    __syncthreads();
    for (int idx = tid; idx < CC*DD; idx += 256) {
        int r = idx >> 7, f = idx & 127;
        Os[r*OST + f] = g_Htemp[(((size_t)(b*CC + r))*NP + p)*DD + f] + gbias[f];
    }
    __syncthreads();
    #pragma unroll
    for (int mi = 0; mi < 2; mi++)
        #pragma unroll
        for (int ni = 0; ni < 4; ni++) {
            int r = wm*32 + mi*16 + g;
            int c = wn*32 + ni*8 + 2*t4;
            #pragma unroll
            for (int half = 0; half < 2; half++) {
                int row = r + half*8;
                Os[row*OST + c    ] += acc[mi][ni][half*2 + 0] * 0.25f;
                Os[row*OST + c + 1] += acc[mi][ni][half*2 + 1] * 0.25f;
            }
        }
    __syncthreads();
    {
        float4 g4 = ((const float4*)sg)[lane];
        float4 b4 = ((const float4*)sb)[lane];
        for (int r = w; r < CC; r += 8) {
            float4 v = *(float4*)&Os[r*OST + lane*4];
            float s1 = v.x + v.y + v.z + v.w;
            #pragma unroll
            for (int o = 16; o; o >>= 1) s1 += __shfl_xor_sync(0xffffffffu, s1, o);
            float mean = s1 * (1.f/128.f);
            float dx=v.x-mean, dy=v.y-mean, dz=v.z-mean, dw=v.w-mean;
            float q = dx*dx+dy*dy+dz*dz+dw*dw;
            #pragma unroll
            for (int o = 16; o; o >>= 1) q += __shfl_xor_sync(0xffffffffu, q, o);
            float inv = rsqrtf(q * (1.f/128.f) + 1e-5f);
            float4 ov;
            ov.x = dx*inv*g4.x + b4.x; ov.y = dy*inv*g4.y + b4.y;
            ov.z = dz*inv*g4.z + b4.z; ov.w = dw*inv*g4.w + b4.w;
            ((float4*)(out + (((size_t)(b*CC + r))*NP + p)*DD))[lane] = ov;
        }
    }
}

// ---------------- host launch -------------------------------------------------
extern "C" void kernel_launch(void* const* d_in, const int* in_sizes, int n_in,
                              void* d_out, int out_size)
{
    const float* H_in      = (const float*)d_in[0];
    const float* static_adj= (const float*)d_in[1];
    const float* attn_in_w = (const float*)d_in[2];
    const float* attn_in_b = (const float*)d_in[3];
    const float* attn_out_w= (const float*)d_in[4];
    const float* attn_out_b= (const float*)d_in[5];
    const float* ln1_g     = (const float*)d_in[6];
    const float* ln1_b     = (const float*)d_in[7];
    const float* ln2_g     = (const float*)d_in[8];
    const float* ln2_b     = (const float*)d_in[9];
    const float* ff1_w     = (const float*)d_in[10];
    const float* ff1_b     = (const float*)d_in[11];
    const float* ff2_w     = (const float*)d_in[12];
    const float* ff2_b     = (const float*)d_in[13];
    const float* tnorm_g   = (const float*)d_in[14];
    const float* tnorm_b   = (const float*)d_in[15];
    const float* q_w       = (const float*)d_in[16];
    const float* q_b       = (const float*)d_in[17];
    const float* k_w       = (const float*)d_in[18];
    const float* k_b       = (const float*)d_in[19];
    const float* gat_w     = (const float*)d_in[20];
    const float* gat_att_src = (const float*)d_in[21];
    const float* gat_att_dst = (const float*)d_in[22];
    const float* gat_bias  = (const float*)d_in[23];
    const float* snorm_g   = (const float*)d_in[24];
    const float* snorm_b   = (const float*)d_in[25];

    float *h_, *qkv_, *o_, *x_, *ff_, *Htemp_, *Hs_, *q2_, *k2_;
    __nv_bfloat16* xhb_;
    cudaGetSymbolAddress((void**)&h_,     g_h);
    cudaGetSymbolAddress((void**)&qkv_,   g_qkv);
    cudaGetSymbolAddress((void**)&o_,     g_o);
    cudaGetSymbolAddress((void**)&x_,     g_x);
    cudaGetSymbolAddress((void**)&ff_,    g_ff);
    cudaGetSymbolAddress((void**)&Htemp_, g_Htemp);
    cudaGetSymbolAddress((void**)&xhb_,   g_xhb);
    cudaGetSymbolAddress((void**)&Hs_,    g_Hs);
    cudaGetSymbolAddress((void**)&q2_,    g_q2);
    cudaGetSymbolAddress((void**)&k2_,    g_k2);

    const int mma_smem  = 4 * TILE * 4;                // 73728
    const int attn_smem = 13440 * 4;                   // 53760
    const int gat_smem  = (GU + 4352 + 128) * 4;       // 52736
    cudaFuncSetAttribute(k_mma, cudaFuncAttributeMaxDynamicSharedMemorySize, mma_smem);
    cudaFuncSetAttribute(k_mma_bf, cudaFuncAttributeMaxDynamicSharedMemorySize, mma_smem);
    cudaFuncSetAttribute(k_attn_mma, cudaFuncAttributeMaxDynamicSharedMemorySize, attn_smem);
    cudaFuncSetAttribute(k_gat,  cudaFuncAttributeMaxDynamicSharedMemorySize, gat_smem);

    // 0) W_att vectors
    k_watt<<<4, 256>>>(gat_w, gat_att_src, gat_att_dst);
    // 1) h = ln1(x0)
    k_ln<<<NTOK/8, 256>>>(H_in, nullptr, ln1_g, ln1_b, h_);
    // 2) qkv = h @ Wqkv^T + b
    k_mma<<<dim3(3, NTOK/TBM), 256, mma_smem>>>(h_, attn_in_w, attn_in_b, nullptr, qkv_,
                                                NTOK, 384, 128, 0);
    // 3) temporal attention v4
    k_attn_mma<<<NSEQ*HT, 128, attn_smem>>>();
    // 4) x1 = x0 + o @ Wout^T + b
    k_mma<<<dim3(1, NTOK/TBM), 256, mma_smem>>>(o_, attn_out_w, attn_out_b, H_in, x_,
                                                NTOK, 128, 128, 0);
    // 5) h = ln2(x1)
    k_ln<<<NTOK/8, 256>>>(x_, nullptr, ln2_g, ln2_b, h_);
    // 6) ff = relu(h @ W1^T + b1)
    k_mma<<<dim3(4, NTOK/TBM), 256, mma_smem>>>(h_, ff1_w, ff1_b, nullptr, ff_,
                                                NTOK, 512, 128, 1);
    // 7) x2 = x1 + ff @ W2^T + b2
    k_mma<<<dim3(1, NTOK/TBM), 256, mma_smem>>>(ff_, ff2_w, ff2_b, x_, x_,
                                                NTOK, 128, 512, 0);
    // 8) H_temp = ln(x0 + x2, tnorm)
    k_ln<<<NTOK/8, 256>>>(x_, H_in, tnorm_g, tnorm_b, Htemp_);
    // 9) xh = H_temp @ gat_w^T  (bf16 output)
    k_mma_bf<<<dim3(4, NTOK/TBM), 256, mma_smem>>>(Htemp_, gat_w, xhb_, 512, 128);
    // 10) asrc/adst (fp32 path, from H_temp)
    k_asd<<<NTOK/8, 256>>>();
    // 11) Hs = mean_p(H_temp)
    k_mean<<<NSEQ, 128>>>();
    // 12) q2, k2
    k_gemm<<<dim3(1, NSEQ/BM), 256>>>(Hs_, q_w, q_b, q2_, NSEQ, 64, 128);
    k_gemm<<<dim3(1, NSEQ/BM), 256>>>(Hs_, k_w, k_b, k2_, NSEQ, 64, 128);
    // 13) adjacency / top-k / mask
    k_graph<<<BB, 64>>>(static_adj);
    // 14) GAT v2 + snorm LN -> output
    k_gat<<<BB*NP, 256, gat_smem>>>(gat_bias, snorm_g, snorm_b, (float*)d_out);
}

// round 13
// speedup vs baseline: 1.1223x; 1.0051x over previous
#include <cuda_runtime.h>
#include <cuda_bf16.h>
#include <math.h>
#include <stdint.h>

#define BB   16
#define CC   64
#define NP   128
#define DD   128
#define HT   4
#define DH   32
#define HS   4
#define FF   128
#define DK   64
#define NTOK (BB*CC*NP)      // 131072
#define NSEQ (BB*CC)         // 1024
#define GAT_NEG -1e30f

// ---------------- scratch ----------------------------------------------------
__device__ float g_h[NTOK*DD];
__device__ __nv_bfloat16 g_qkvb[(size_t)NTOK*3*DD];   // bf16 qkv
__device__ float g_o[NTOK*DD];
__device__ float g_x[NTOK*DD];
__device__ float g_ff[(size_t)NTOK*4*DD];
__device__ float g_Htemp[NTOK*DD];
__device__ __nv_bfloat16 g_xhb[(size_t)NTOK*HS*FF];   // bf16 xh
__device__ float g_Hs[NSEQ*DD];
__device__ float g_q2[NSEQ*DK];
__device__ float g_k2[NSEQ*DK];
__device__ float g_mask[BB*CC*CC];
__device__ float g_watt[8*DD];
__device__ float g_asrc[BB*HS*NP*CC];
__device__ float g_adst[BB*HS*NP*CC];

// ---------------- helpers ----------------------------------------------------
__device__ __forceinline__ void mma8(float c[4], const uint32_t a[4],
                                     uint32_t b0, uint32_t b1) {
    asm volatile(
        "mma.sync.aligned.m16n8k8.row.col.f32.tf32.tf32.f32 "
        "{%0,%1,%2,%3}, {%4,%5,%6,%7}, {%8,%9}, {%0,%1,%2,%3};"
        : "+f"(c[0]), "+f"(c[1]), "+f"(c[2]), "+f"(c[3])
        : "r"(a[0]), "r"(a[1]), "r"(a[2]), "r"(a[3]), "r"(b0), "r"(b1));
}
__device__ __forceinline__ void cp_async16(float* smem, const float* gmem) {
    uint32_t s = (uint32_t)__cvta_generic_to_shared(smem);
    asm volatile("cp.async.cg.shared.global [%0], [%1], 16;" :: "r"(s), "l"(gmem));
}
#define FU(x) __float_as_uint(x)

// ---------------- LayerNorm: warp per row, optional fused add ----------------
__global__ void k_ln(const float* __restrict__ x, const float* __restrict__ add,
                     const float* __restrict__ gw, const float* __restrict__ bw,
                     float* __restrict__ out)
{
    int row  = blockIdx.x * 8 + (threadIdx.x >> 5);
    int lane = threadIdx.x & 31;
    const float4* xp = (const float4*)(x + (size_t)row * DD);
    float4 v = xp[lane];
    if (add) {
        float4 a = ((const float4*)(add + (size_t)row * DD))[lane];
        v.x += a.x; v.y += a.y; v.z += a.z; v.w += a.w;
    }
    float s = v.x + v.y + v.z + v.w;
    #pragma unroll
    for (int o = 16; o; o >>= 1) s += __shfl_xor_sync(0xffffffffu, s, o);
    float mean = s * (1.f/128.f);
    float dx = v.x-mean, dy = v.y-mean, dz = v.z-mean, dw = v.w-mean;
    float q = dx*dx + dy*dy + dz*dz + dw*dw;
    #pragma unroll
    for (int o = 16; o; o >>= 1) q += __shfl_xor_sync(0xffffffffu, q, o);
    float inv = rsqrtf(q * (1.f/128.f) + 1e-5f);
    float4 g4 = ((const float4*)gw)[lane];
    float4 b4 = ((const float4*)bw)[lane];
    float4 o4;
    o4.x = dx*inv*g4.x + b4.x;  o4.y = dy*inv*g4.y + b4.y;
    o4.z = dz*inv*g4.z + b4.z;  o4.w = dw*inv*g4.w + b4.w;
    ((float4*)(out + (size_t)row * DD))[lane] = o4;
}

// ---------------- tf32 GEMM, cp.async 2-stage pipeline (R7-proven) -----------
#define TBM 128
#define TBN 128
#define TILE (128*36)
__global__ void __launch_bounds__(256)
k_mma(const float* __restrict__ A, const float* __restrict__ W,
      const float* __restrict__ bias, const float* __restrict__ res,
      float* __restrict__ out, int M, int N, int K, int relu)
{
    extern __shared__ float smbuf[];
    float* As = smbuf;
    float* Bs = smbuf + 2*TILE;
    int tid  = threadIdx.x;
    int warp = tid >> 5, lane = tid & 31;
    int wm = warp >> 1, wn = warp & 1;
    int g = lane >> 2, t = lane & 3;
    int m0 = blockIdx.y * TBM;
    int n0 = blockIdx.x * TBN;
    int lr = tid >> 3, lc = (tid & 7) << 2;

    float acc[2][8][4] = {};
    const int nk = K >> 5;

    #pragma unroll
    for (int i = 0; i < 4; i++) {
        int r = lr + i * 32;
        cp_async16(&As[r*36 + lc], A + (size_t)(m0 + r) * K + lc);
        cp_async16(&Bs[r*36 + lc], W + (size_t)(n0 + r) * K + lc);
    }
    asm volatile("cp.async.commit_group;");

    for (int kt = 0; kt < nk; kt++) {
        int buf = (kt & 1) * TILE;
        if (kt + 1 < nk) {
            int nb = ((kt + 1) & 1) * TILE;
            int ko = (kt + 1) << 5;
            #pragma unroll
            for (int i = 0; i < 4; i++) {
                int r = lr + i * 32;
                cp_async16(&As[nb + r*36 + lc], A + (size_t)(m0 + r) * K + ko + lc);
                cp_async16(&Bs[nb + r*36 + lc], W + (size_t)(n0 + r) * K + ko + lc);
            }
            asm volatile("cp.async.commit_group;");
            asm volatile("cp.async.wait_group 1;");
        } else {
            asm volatile("cp.async.wait_group 0;");
        }
        __syncthreads();
        #pragma unroll
        for (int kk = 0; kk < 32; kk += 8) {
            uint32_t afrag[2][4];
            #pragma unroll
            for (int mi = 0; mi < 2; mi++) {
                int r = wm * 32 + mi * 16;
                afrag[mi][0] = FU(As[buf + (r + g    )*36 + kk + t    ]);
                afrag[mi][1] = FU(As[buf + (r + g + 8)*36 + kk + t    ]);
                afrag[mi][2] = FU(As[buf + (r + g    )*36 + kk + t + 4]);
                afrag[mi][3] = FU(As[buf + (r + g + 8)*36 + kk + t + 4]);
            }
            #pragma unroll
            for (int ni = 0; ni < 8; ni++) {
                int c = wn * 64 + ni * 8;
                uint32_t b0 = FU(Bs[buf + (c + g)*36 + kk + t    ]);
                uint32_t b1 = FU(Bs[buf + (c + g)*36 + kk + t + 4]);
                mma8(acc[0][ni], afrag[0], b0, b1);
                mma8(acc[1][ni], afrag[1], b0, b1);
            }
        }
        __syncthreads();
    }

    #pragma unroll
    for (int mi = 0; mi < 2; mi++) {
        #pragma unroll
        for (int ni = 0; ni < 8; ni++) {
            int r = m0 + wm * 32 + mi * 16 + g;
            int c = n0 + wn * 64 + ni * 8 + 2 * t;
            float bv0 = bias ? bias[c]     : 0.f;
            float bv1 = bias ? bias[c + 1] : 0.f;
            #pragma unroll
            for (int half = 0; half < 2; half++) {
                int row = r + half * 8;
                float v0 = acc[mi][ni][half*2 + 0] + bv0;
                float v1 = acc[mi][ni][half*2 + 1] + bv1;
                if (relu) { v0 = fmaxf(v0, 0.f); v1 = fmaxf(v1, 0.f); }
                if (res) {
                    const float2 rr = *(const float2*)(res + (size_t)row * N + c);
                    v0 += rr.x; v1 += rr.y;
                }
                *(float2*)(out + (size_t)row * N + c) = make_float2(v0, v1);
            }
        }
    }
}

// ---------------- tf32 GEMM -> bf16 output (optional bias) -------------------
__global__ void __launch_bounds__(256)
k_mma_bf(const float* __restrict__ A, const float* __restrict__ W,
         const float* __restrict__ bias, __nv_bfloat16* __restrict__ out,
         int N, int K)
{
    extern __shared__ float smbuf[];
    float* As = smbuf;
    float* Bs = smbuf + 2*TILE;
    int tid  = threadIdx.x;
    int warp = tid >> 5, lane = tid & 31;
    int wm = warp >> 1, wn = warp & 1;
    int g = lane >> 2, t = lane & 3;
    int m0 = blockIdx.y * TBM;
    int n0 = blockIdx.x * TBN;
    int lr = tid >> 3, lc = (tid & 7) << 2;

    float acc[2][8][4] = {};
    const int nk = K >> 5;

    #pragma unroll
    for (int i = 0; i < 4; i++) {
        int r = lr + i * 32;
        cp_async16(&As[r*36 + lc], A + (size_t)(m0 + r) * K + lc);
        cp_async16(&Bs[r*36 + lc], W + (size_t)(n0 + r) * K + lc);
    }
    asm volatile("cp.async.commit_group;");

    for (int kt = 0; kt < nk; kt++) {
        int buf = (kt & 1) * TILE;
        if (kt + 1 < nk) {
            int nb = ((kt + 1) & 1) * TILE;
            int ko = (kt + 1) << 5;
            #pragma unroll
            for (int i = 0; i < 4; i++) {
                int r = lr + i * 32;
                cp_async16(&As[nb + r*36 + lc], A + (size_t)(m0 + r) * K + ko + lc);
                cp_async16(&Bs[nb + r*36 + lc], W + (size_t)(n0 + r) * K + ko + lc);
            }
            asm volatile("cp.async.commit_group;");
            asm volatile("cp.async.wait_group 1;");
        } else {
            asm volatile("cp.async.wait_group 0;");
        }
        __syncthreads();
        #pragma unroll
        for (int kk = 0; kk < 32; kk += 8) {
            uint32_t afrag[2][4];
            #pragma unroll
            for (int mi = 0; mi < 2; mi++) {
                int r = wm * 32 + mi * 16;
                afrag[mi][0] = FU(As[buf + (r + g    )*36 + kk + t    ]);
                afrag[mi][1] = FU(As[buf + (r + g + 8)*36 + kk + t    ]);
                afrag[mi][2] = FU(As[buf + (r + g    )*36 + kk + t + 4]);
                afrag[mi][3] = FU(As[buf + (r + g + 8)*36 + kk + t + 4]);
            }
            #pragma unroll
            for (int ni = 0; ni < 8; ni++) {
                int c = wn * 64 + ni * 8;
                uint32_t b0 = FU(Bs[buf + (c + g)*36 + kk + t    ]);
                uint32_t b1 = FU(Bs[buf + (c + g)*36 + kk + t + 4]);
                mma8(acc[0][ni], afrag[0], b0, b1);
                mma8(acc[1][ni], afrag[1], b0, b1);
            }
        }
        __syncthreads();
    }

    #pragma unroll
    for (int mi = 0; mi < 2; mi++) {
        #pragma unroll
        for (int ni = 0; ni < 8; ni++) {
            int r = m0 + wm * 32 + mi * 16 + g;
            int c = n0 + wn * 64 + ni * 8 + 2 * t;
            float bv0 = bias ? bias[c]     : 0.f;
            float bv1 = bias ? bias[c + 1] : 0.f;
            #pragma unroll
            for (int half = 0; half < 2; half++) {
                int row = r + half * 8;
                __nv_bfloat162 bv = __floats2bfloat162_rn(acc[mi][ni][half*2 + 0] + bv0,
                                                          acc[mi][ni][half*2 + 1] + bv1);
                *(__nv_bfloat162*)(out + (size_t)row * N + c) = bv;
            }
        }
    }
}

// ---------------- small SIMT GEMM (q2/k2) ------------------------------------
#define BM 64
#define BN 64
#define BK 16
__global__ void k_gemm(const float* __restrict__ A, const float* __restrict__ W,
                       const float* __restrict__ bias, float* __restrict__ out,
                       int M, int N, int K)
{
    __shared__ float As[BK][BM];
    __shared__ float Bs[BK][BN];
    int tid = threadIdx.x;
    int tx = tid & 15, ty = tid >> 4;
    int m0 = blockIdx.y * BM, n0 = blockIdx.x * BN;
    int lr = tid >> 2;
    int lk = (tid & 3) * 4;
    float acc[4][4] = {};
    for (int k0 = 0; k0 < K; k0 += BK) {
        float4 a4 = *(const float4*)(A + (size_t)(m0 + lr) * K + k0 + lk);
        float4 b4 = *(const float4*)(W + (size_t)(n0 + lr) * K + k0 + lk);
        As[lk+0][lr] = a4.x; As[lk+1][lr] = a4.y; As[lk+2][lr] = a4.z; As[lk+3][lr] = a4.w;
        Bs[lk+0][lr] = b4.x; Bs[lk+1][lr] = b4.y; Bs[lk+2][lr] = b4.z; Bs[lk+3][lr] = b4.w;
        __syncthreads();
        #pragma unroll
        for (int k = 0; k < BK; k++) {
            float4 ra = *(const float4*)&As[k][ty*4];
            float4 rb = *(const float4*)&Bs[k][tx*4];
            float av[4] = {ra.x, ra.y, ra.z, ra.w};
            float bv[4] = {rb.x, rb.y, rb.z, rb.w};
            #pragma unroll
            for (int i = 0; i < 4; i++)
                #pragma unroll
                for (int j = 0; j < 4; j++)
                    acc[i][j] += av[i] * bv[j];
        }
        __syncthreads();
    }
    #pragma unroll
    for (int i = 0; i < 4; i++) {
        int m = m0 + ty*4 + i;
        #pragma unroll
        for (int j = 0; j < 4; j++) {
            int n = n0 + tx*4 + j;
            out[(size_t)m * N + n] = acc[i][j] + bias[n];
        }
    }
}

// ============== attention v4 (R10-proven) + bf16 qkv loads ===================
#define AQS 36
#define AVS 132
#define APW 68
__global__ void __launch_bounds__(128, 3)
k_attn_mma()
{
    extern __shared__ float sm[];
    float* Qs = sm;                  // [128][36]
    float* Ks = sm + 4608;           // [128][36]
    float* VT = sm + 9216;           // [32][132]
    float* Pb = sm;                  // union: per-warp [32][68]

    int n = blockIdx.x >> 2, h = blockIdx.x & 3;
    int tid = threadIdx.x;
    int warp = tid >> 5, lane = tid & 31;
    int g = lane >> 2, t = lane & 3;
    int m0 = warp * 32;
    const __nv_bfloat16* base = g_qkvb + (size_t)n * NP * 3 * DD;

    // bf162-pair loads (offsets h*32+2*dp are 2-aligned)
    for (int idx = tid; idx < NP*16; idx += 128) {
        int j = idx >> 4, dp = idx & 15, d = 2*dp;
        float2 q2 = __bfloat1622float2(*(const __nv_bfloat162*)(base + j*384 +       h*32 + d));
        float2 k2 = __bfloat1622float2(*(const __nv_bfloat162*)(base + j*384 + 128 + h*32 + d));
        float2 v2 = __bfloat1622float2(*(const __nv_bfloat162*)(base + j*384 + 256 + h*32 + d));
        Qs[j*AQS + d] = q2.x;  Qs[j*AQS + d + 1] = q2.y;
        Ks[j*AQS + d] = k2.x;  Ks[j*AQS + d + 1] = k2.y;
        VT[ d     *AVS + j] = v2.x;
        VT[(d + 1)*AVS + j] = v2.y;
    }
    __syncthreads();

    float s[2][16][4] = {};
    #pragma unroll
    for (int kk = 0; kk < 32; kk += 8) {
        uint32_t afrag[2][4];
        #pragma unroll
        for (int mi = 0; mi < 2; mi++) {
            int r = m0 + mi * 16;
            afrag[mi][0] = FU(Qs[(r + g    )*AQS + kk + t    ]);
            afrag[mi][1] = FU(Qs[(r + g + 8)*AQS + kk + t    ]);
            afrag[mi][2] = FU(Qs[(r + g    )*AQS + kk + t + 4]);
            afrag[mi][3] = FU(Qs[(r + g + 8)*AQS + kk + t + 4]);
        }
        #pragma unroll
        for (int ni = 0; ni < 16; ni++) {
            int c = ni * 8;
            uint32_t b0 = FU(Ks[(c + g)*AQS + kk + t    ]);
            uint32_t b1 = FU(Ks[(c + g)*AQS + kk + t + 4]);
            mma8(s[0][ni], afrag[0], b0, b1);
            mma8(s[1][ni], afrag[1], b0, b1);
        }
    }
    __syncthreads();

    const float scale = 0.17677669529663687f;
    float mx[2][2] = {{-INFINITY,-INFINITY},{-INFINITY,-INFINITY}};
    #pragma unroll
    for (int mi = 0; mi < 2; mi++)
        #pragma unroll
        for (int ni = 0; ni < 16; ni++) {
            #pragma unroll
            for (int q = 0; q < 4; q++) s[mi][ni][q] *= scale;
            mx[mi][0] = fmaxf(mx[mi][0], fmaxf(s[mi][ni][0], s[mi][ni][1]));
            mx[mi][1] = fmaxf(mx[mi][1], fmaxf(s[mi][ni][2], s[mi][ni][3]));
        }
    #pragma unroll
    for (int mi = 0; mi < 2; mi++)
        #pragma unroll
        for (int hf = 0; hf < 2; hf++) {
            mx[mi][hf] = fmaxf(mx[mi][hf], __shfl_xor_sync(0xffffffffu, mx[mi][hf], 1));
            mx[mi][hf] = fmaxf(mx[mi][hf], __shfl_xor_sync(0xffffffffu, mx[mi][hf], 2));
        }
    float sum[2][2] = {};
    #pragma unroll
    for (int mi = 0; mi < 2; mi++)
        #pragma unroll
        for (int ni = 0; ni < 16; ni++) {
            s[mi][ni][0] = __expf(s[mi][ni][0] - mx[mi][0]);
            s[mi][ni][1] = __expf(s[mi][ni][1] - mx[mi][0]);
            s[mi][ni][2] = __expf(s[mi][ni][2] - mx[mi][1]);
            s[mi][ni][3] = __expf(s[mi][ni][3] - mx[mi][1]);
            sum[mi][0] += s[mi][ni][0] + s[mi][ni][1];
            sum[mi][1] += s[mi][ni][2] + s[mi][ni][3];
        }
    float inv[2][2];
    #pragma unroll
    for (int mi = 0; mi < 2; mi++)
        #pragma unroll
        for (int hf = 0; hf < 2; hf++) {
            float ss = sum[mi][hf];
            ss += __shfl_xor_sync(0xffffffffu, ss, 1);
            ss += __shfl_xor_sync(0xffffffffu, ss, 2);
            inv[mi][hf] = 1.f / ss;
        }

    float* Pw = Pb + warp * (32 * APW);
    float o[2][4][4] = {};
    #pragma unroll
    for (int hf = 0; hf < 2; hf++) {
        #pragma unroll
        for (int mi = 0; mi < 2; mi++) {
            int lr = mi * 16 + g;
            #pragma unroll
            for (int ni = 0; ni < 8; ni++) {
                int c = ni * 8 + 2 * t;
                Pw[ lr      *APW + c    ] = s[mi][hf*8 + ni][0];
                Pw[ lr      *APW + c + 1] = s[mi][hf*8 + ni][1];
                Pw[(lr + 8) *APW + c    ] = s[mi][hf*8 + ni][2];
                Pw[(lr + 8) *APW + c + 1] = s[mi][hf*8 + ni][3];
            }
        }
        __syncwarp();
        #pragma unroll
        for (int kk = 0; kk < 64; kk += 8) {
            uint32_t afrag[2][4];
            #pragma unroll
            for (int mi = 0; mi < 2; mi++) {
                int lr = mi * 16;
                afrag[mi][0] = FU(Pw[(lr + g    )*APW + kk + t    ]);
                afrag[mi][1] = FU(Pw[(lr + g + 8)*APW + kk + t    ]);
                afrag[mi][2] = FU(Pw[(lr + g    )*APW + kk + t + 4]);
                afrag[mi][3] = FU(Pw[(lr + g + 8)*APW + kk + t + 4]);
            }
            int j0 = hf*64 + kk + t, j1 = hf*64 + kk + t + 4;
            #pragma unroll
            for (int ni = 0; ni < 4; ni++) {
                int c = ni * 8;
                uint32_t b0 = FU(VT[(c + g)*AVS + j0]);
                uint32_t b1 = FU(VT[(c + g)*AVS + j1]);
                mma8(o[0][ni], afrag[0], b0, b1);
                mma8(o[1][ni], afrag[1], b0, b1);
            }
        }
        __syncwarp();
    }

    #pragma unroll
    for (int mi = 0; mi < 2; mi++) {
        int r0 = n*NP + m0 + mi * 16 + g;
        #pragma unroll
        for (int ni = 0; ni < 4; ni++) {
            int d = ni * 8 + 2 * t;
            *(float2*)(g_o + (size_t) r0      *DD + h*32 + d) =
                make_float2(o[mi][ni][0]*inv[mi][0], o[mi][ni][1]*inv[mi][0]);
            *(float2*)(g_o + (size_t)(r0 + 8) *DD + h*32 + d) =
                make_float2(o[mi][ni][2]*inv[mi][1], o[mi][ni][3]*inv[mi][1]);
        }
    }
}

// ---------------- mean over Np -----------------------------------------------
__global__ void k_mean()
{
    int n = blockIdx.x, d = threadIdx.x;
    float s = 0.f;
    for (int p = 0; p < NP; p++) s += g_Htemp[((size_t)n*NP + p)*DD + d];
    g_Hs[n*DD + d] = s * (1.f/128.f);
}

// ---------------- W_att = gat_w[h]^T @ att{src,dst}[h] -----------------------
__global__ void k_watt(const float* __restrict__ gw, const float* __restrict__ asv,
                       const float* __restrict__ adv)
{
    int idx = blockIdx.x * 256 + threadIdx.x;
    int r = idx >> 7, d = idx & 127;
    int h = r & 3;
    const float* att = (r < 4) ? asv : adv;
    float s = 0.f;
    for (int f = 0; f < 128; f++)
        s += att[h*FF + f] * gw[h*FF*DD + f*DD + d];
    g_watt[r*DD + d] = s;
}

// ---------------- asrc/adst = H_temp @ W_att^T -------------------------------
__global__ void k_asd()
{
    __shared__ float4 W4[8][32];
    int tid = threadIdx.x, warp = tid >> 5, lane = tid & 31;
    for (int i = tid; i < 256; i += 256)
        ((float4*)W4)[i] = ((const float4*)g_watt)[i];
    __syncthreads();
    int tok = blockIdx.x * 8 + warp;
    float4 v = ((const float4*)(g_Htemp + (size_t)tok * DD))[lane];
    int p = tok & 127, bs = tok >> 7;
    int s = bs & 63, b = bs >> 6;
    #pragma unroll
    for (int r = 0; r < 8; r++) {
        float4 w = W4[r][lane];
        float a = v.x*w.x + v.y*w.y + v.z*w.z + v.w*w.w;
        #pragma unroll
        for (int o = 16; o; o >>= 1) a += __shfl_xor_sync(0xffffffffu, a, o);
        if (lane == 0) {
            int h = r & 3;
            float* dst = (r < 4) ? g_asrc : g_adst;
            dst[(((b*4 + h)*128 + p)*64) + s] = a;
        }
    }
}

// ---------------- graph adjacency --------------------------------------------
__global__ void k_graph(const float* __restrict__ adj)
{
    __shared__ float k2s[CC*DK];
    __shared__ float Amat[CC*65];
    int b = blockIdx.x, c = threadIdx.x;
    for (int idx = c; idx < CC*DK; idx += 64) k2s[idx] = g_k2[(size_t)b*CC*DK + idx];
    __syncthreads();
    float qreg[DK];
    #pragma unroll
    for (int d = 0; d < DK; d++) qreg[d] = g_q2[(size_t)b*CC*DK + c*DK + d];
    for (int e = 0; e < CC; e++) {
        float a = 0.f;
        #pragma unroll
        for (int d = 0; d < DK; d++) a += qreg[d] * k2s[e*DK + d];
        Amat[c*65 + e] = tanhf(a * 0.125f) + adj[c*CC + e];
    }
    for (int e = 0; e < CC; e++) g_mask[(size_t)b*CC*CC + c*CC + e] = 0.f;
    for (int kk = 0; kk < 8; kk++) {
        float best = -INFINITY; int bi = 0;
        for (int e = 0; e < CC; e++) {
            float v = Amat[c*65 + e];
            if (v > best) { best = v; bi = e; }
        }
        if (bi != c && best != 0.f) g_mask[(size_t)b*CC*CC + c*CC + bi] = 1.f;
        Amat[c*65 + bi] = -INFINITY;
    }
}

// ============== GAT v2 (R12-proven, bf16 xh) =================================
#define XST 68
#define AST 68
#define OST 132
#define GU  8704
__global__ void __launch_bounds__(256)
k_gat(const float* __restrict__ gbias, const float* __restrict__ sg,
      const float* __restrict__ sb, float* __restrict__ out)
{
    extern __shared__ float sm[];
    float* U   = sm;
    float* Awt = sm + GU;
    float* Asv = sm + GU + 4352;
    float* Adv = sm + GU + 4416;
    float* XhT = U;
    float* Os  = U;

    int b = blockIdx.x >> 7, p = blockIdx.x & 127;
    int tid = threadIdx.x, w = tid >> 5, lane = tid & 31;
    int wm = w >> 2, wn = w & 3;
    int g = lane >> 2, t4 = lane & 3;

    float mr0[8], mr1[8];
    #pragma unroll
    for (int i = 0; i < 8; i++) {
        int t = w*8 + i;
        mr0[i] = g_mask[(size_t)b*CC*CC + lane*CC + t];
        mr1[i] = g_mask[(size_t)b*CC*CC + (lane+32)*CC + t];
    }

    float acc[2][4][4] = {};
    for (int h = 0; h < HS; h++) {
        __syncthreads();
        for (int idx = tid; idx < CC*FF/2; idx += 256) {
            int s = idx >> 6, fp = idx & 63;
            const __nv_bfloat162 v2 = *(const __nv_bfloat162*)
                (g_xhb + (size_t)(((b*CC + s)*NP + p))*(HS*FF) + h*FF + 2*fp);
            float2 vf = __bfloat1622float2(v2);
            XhT[(2*fp    )*XST + s] = vf.x;
            XhT[(2*fp + 1)*XST + s] = vf.y;
        }
        if (tid < 64)            Asv[tid]      = g_asrc[(((b*4 + h)*128 + p)*64) + tid];
        else if (tid < 128)      Adv[tid - 64] = g_adst[(((b*4 + h)*128 + p)*64) + tid - 64];
        __syncthreads();

        #pragma unroll
        for (int i = 0; i < 8; i++) {
            int t = w*8 + i;
            float adt = Adv[t];
            float e0 = Asv[lane]      + adt; e0 = e0 > 0.f ? e0 : 0.2f*e0;
            float e1 = Asv[lane + 32] + adt; e1 = e1 > 0.f ? e1 : 0.2f*e1;
            float me = fmaxf(mr0[i] > 0.5f ? e0 : GAT_NEG, mr1[i] > 0.5f ? e1 : GAT_NEG);
            #pragma unroll
            for (int o = 16; o; o >>= 1) me = fmaxf(me, __shfl_xor_sync(0xffffffffu, me, o));
            float w0 = (mr0[i] > 0.5f) ? __expf(e0 - me) : 0.f;
            float w1 = (mr1[i] > 0.5f) ? __expf(e1 - me) : 0.f;
            float ws = w0 + w1;
            #pragma unroll
            for (int o = 16; o; o >>= 1) ws += __shfl_xor_sync(0xffffffffu, ws, o);
            float inv = ws > 0.f ? 1.f / ws : 0.f;
            Awt[t*AST + lane]      = w0 * inv;
            Awt[t*AST + lane + 32] = w1 * inv;
        }
        __syncthreads();

        #pragma unroll
        for (int kk = 0; kk < CC; kk += 8) {
            uint32_t afrag[2][4];
            #pragma unroll
            for (int mi = 0; mi < 2; mi++) {
                int r = wm * 32 + mi * 16;
                afrag[mi][0] = FU(Awt[(r + g    )*AST + kk + t4    ]);
                afrag[mi][1] = FU(Awt[(r + g + 8)*AST + kk + t4    ]);
                afrag[mi][2] = FU(Awt[(r + g    )*AST + kk + t4 + 4]);
                afrag[mi][3] = FU(Awt[(r + g + 8)*AST + kk + t4 + 4]);
            }
            #pragma unroll
            for (int ni = 0; ni < 4; ni++) {
                int c = wn * 32 + ni * 8;
                uint32_t b0 = FU(XhT[(c + g)*XST + kk + t4    ]);
                uint32_t b1 = FU(XhT[(c + g)*XST + kk + t4 + 4]);
                mma8(acc[0][ni], afrag[0], b0, b1);
                mma8(acc[1][ni], afrag[1], b0, b1);
            }
        }
    }

    __syncthreads();
    for (int idx = tid; idx < CC*DD; idx += 256) {
        int r = idx >> 7, f = idx & 127;
        Os[r*OST + f] = g_Htemp[(((size_t)(b*CC + r))*NP + p)*DD + f] + gbias[f];
    }
    __syncthreads();
    #pragma unroll
    for (int mi = 0; mi < 2; mi++)
        #pragma unroll
        for (int ni = 0; ni < 4; ni++) {
            int r = wm*32 + mi*16 + g;
            int c = wn*32 + ni*8 + 2*t4;
            #pragma unroll
            for (int half = 0; half < 2; half++) {
                int row = r + half*8;
                Os[row*OST + c    ] += acc[mi][ni][half*2 + 0] * 0.25f;
                Os[row*OST + c + 1] += acc[mi][ni][half*2 + 1] * 0.25f;
            }
        }
    __syncthreads();
    {
        float4 g4 = ((const float4*)sg)[lane];
        float4 b4 = ((const float4*)sb)[lane];
        for (int r = w; r < CC; r += 8) {
            float4 v = *(float4*)&Os[r*OST + lane*4];
            float s1 = v.x + v.y + v.z + v.w;
            #pragma unroll
            for (int o = 16; o; o >>= 1) s1 += __shfl_xor_sync(0xffffffffu, s1, o);
            float mean = s1 * (1.f/128.f);
            float dx=v.x-mean, dy=v.y-mean, dz=v.z-mean, dw=v.w-mean;
            float q = dx*dx+dy*dy+dz*dz+dw*dw;
            #pragma unroll
            for (int o = 16; o; o >>= 1) q += __shfl_xor_sync(0xffffffffu, q, o);
            float inv = rsqrtf(q * (1.f/128.f) + 1e-5f);
            float4 ov;
            ov.x = dx*inv*g4.x + b4.x; ov.y = dy*inv*g4.y + b4.y;
            ov.z = dz*inv*g4.z + b4.z; ov.w = dw*inv*g4.w + b4.w;
            ((float4*)(out + (((size_t)(b*CC + r))*NP + p)*DD))[lane] = ov;
        }
    }
}

// ---------------- host launch -------------------------------------------------
extern "C" void kernel_launch(void* const* d_in, const int* in_sizes, int n_in,
                              void* d_out, int out_size)
{
    const float* H_in      = (const float*)d_in[0];
    const float* static_adj= (const float*)d_in[1];
    const float* attn_in_w = (const float*)d_in[2];
    const float* attn_in_b = (const float*)d_in[3];
    const float* attn_out_w= (const float*)d_in[4];
    const float* attn_out_b= (const float*)d_in[5];
    const float* ln1_g     = (const float*)d_in[6];
    const float* ln1_b     = (const float*)d_in[7];
    const float* ln2_g     = (const float*)d_in[8];
    const float* ln2_b     = (const float*)d_in[9];
    const float* ff1_w     = (const float*)d_in[10];
    const float* ff1_b     = (const float*)d_in[11];
    const float* ff2_w     = (const float*)d_in[12];
    const float* ff2_b     = (const float*)d_in[13];
    const float* tnorm_g   = (const float*)d_in[14];
    const float* tnorm_b   = (const float*)d_in[15];
    const float* q_w       = (const float*)d_in[16];
    const float* q_b       = (const float*)d_in[17];
    const float* k_w       = (const float*)d_in[18];
    const float* k_b       = (const float*)d_in[19];
    const float* gat_w     = (const float*)d_in[20];
    const float* gat_att_src = (const float*)d_in[21];
    const float* gat_att_dst = (const float*)d_in[22];
    const float* gat_bias  = (const float*)d_in[23];
    const float* snorm_g   = (const float*)d_in[24];
    const float* snorm_b   = (const float*)d_in[25];

    float *h_, *o_, *x_, *ff_, *Htemp_, *Hs_, *q2_, *k2_;
    __nv_bfloat16 *xhb_, *qkvb_;
    cudaGetSymbolAddress((void**)&h_,     g_h);
    cudaGetSymbolAddress((void**)&qkvb_,  g_qkvb);
    cudaGetSymbolAddress((void**)&o_,     g_o);
    cudaGetSymbolAddress((void**)&x_,     g_x);
    cudaGetSymbolAddress((void**)&ff_,    g_ff);
    cudaGetSymbolAddress((void**)&Htemp_, g_Htemp);
    cudaGetSymbolAddress((void**)&xhb_,   g_xhb);
    cudaGetSymbolAddress((void**)&Hs_,    g_Hs);
    cudaGetSymbolAddress((void**)&q2_,    g_q2);
    cudaGetSymbolAddress((void**)&k2_,    g_k2);

    const int mma_smem  = 4 * TILE * 4;                // 73728
    const int attn_smem = 13440 * 4;                   // 53760
    const int gat_smem  = (GU + 4352 + 128) * 4;       // 52736
    cudaFuncSetAttribute(k_mma, cudaFuncAttributeMaxDynamicSharedMemorySize, mma_smem);
    cudaFuncSetAttribute(k_mma_bf, cudaFuncAttributeMaxDynamicSharedMemorySize, mma_smem);
    cudaFuncSetAttribute(k_attn_mma, cudaFuncAttributeMaxDynamicSharedMemorySize, attn_smem);
    cudaFuncSetAttribute(k_gat,  cudaFuncAttributeMaxDynamicSharedMemorySize, gat_smem);

    // 0) W_att vectors
    k_watt<<<4, 256>>>(gat_w, gat_att_src, gat_att_dst);
    // 1) h = ln1(x0)
    k_ln<<<NTOK/8, 256>>>(H_in, nullptr, ln1_g, ln1_b, h_);
    // 2) qkv = h @ Wqkv^T + b  (bf16 output)
    k_mma_bf<<<dim3(3, NTOK/TBM), 256, mma_smem>>>(h_, attn_in_w, attn_in_b, qkvb_,
                                                   384, 128);
    // 3) temporal attention v4 (bf16 qkv)
    k_attn_mma<<<NSEQ*HT, 128, attn_smem>>>();
    // 4) x1 = x0 + o @ Wout^T + b
    k_mma<<<dim3(1, NTOK/TBM), 256, mma_smem>>>(o_, attn_out_w, attn_out_b, H_in, x_,
                                                NTOK, 128, 128, 0);
    // 5) h = ln2(x1)
    k_ln<<<NTOK/8, 256>>>(x_, nullptr, ln2_g, ln2_b, h_);
    // 6) ff = relu(h @ W1^T + b1)
    k_mma<<<dim3(4, NTOK/TBM), 256, mma_smem>>>(h_, ff1_w, ff1_b, nullptr, ff_,
                                                NTOK, 512, 128, 1);
    // 7) x2 = x1 + ff @ W2^T + b2
    k_mma<<<dim3(1, NTOK/TBM), 256, mma_smem>>>(ff_, ff2_w, ff2_b, x_, x_,
                                                NTOK, 128, 512, 0);
    // 8) H_temp = ln(x0 + x2, tnorm)
    k_ln<<<NTOK/8, 256>>>(x_, H_in, tnorm_g, tnorm_b, Htemp_);
    // 9) xh = H_temp @ gat_w^T  (bf16 output)
    k_mma_bf<<<dim3(4, NTOK/TBM), 256, mma_smem>>>(Htemp_, gat_w, nullptr, xhb_,
                                                   512, 128);
    // 10) asrc/adst
    k_asd<<<NTOK/8, 256>>>();
    // 11) Hs = mean_p(H_temp)
    k_mean<<<NSEQ, 128>>>();
    // 12) q2, k2
    k_gemm<<<dim3(1, NSEQ/BM), 256>>>(Hs_, q_w, q_b, q2_, NSEQ, 64, 128);
    k_gemm<<<dim3(1, NSEQ/BM), 256>>>(Hs_, k_w, k_b, k2_, NSEQ, 64, 128);
    // 13) adjacency / top-k / mask
    k_graph<<<BB, 64>>>(static_adj);
    // 14) GAT v2 + snorm LN -> output
    k_gat<<<BB*NP, 256, gat_smem>>>(gat_bias, snorm_g, snorm_b, (float*)d_out);
}

// round 14
// speedup vs baseline: 1.1825x; 1.0537x over previous
#include <cuda_runtime.h>
#include <cuda_bf16.h>
#include <math.h>
#include <stdint.h>

#define BB   16
#define CC   64
#define NP   128
#define DD   128
#define HT   4
#define DH   32
#define HS   4
#define FF   128
#define DK   64
#define NTOK (BB*CC*NP)      // 131072
#define NSEQ (BB*CC)         // 1024
#define GAT_NEG -1e30f

// ---------------- scratch ----------------------------------------------------
__device__ float g_h[NTOK*DD];
__device__ __nv_bfloat16 g_qkvb[(size_t)NTOK*3*DD];
__device__ float g_o[NTOK*DD];
__device__ float g_x[NTOK*DD];
__device__ float g_ff[(size_t)NTOK*4*DD];
__device__ float g_Htemp[NTOK*DD];
__device__ __nv_bfloat16 g_xhb[(size_t)NTOK*HS*FF];
__device__ float g_Hs[NSEQ*DD];
__device__ float g_q2[NSEQ*DK];
__device__ float g_k2[NSEQ*DK];
__device__ float g_mask[BB*CC*CC];
__device__ float g_watt[8*DD];
__device__ float g_asrc[BB*HS*NP*CC];
__device__ float g_adst[BB*HS*NP*CC];

// ---------------- helpers ----------------------------------------------------
__device__ __forceinline__ void mma8(float c[4], const uint32_t a[4],
                                     uint32_t b0, uint32_t b1) {
    asm volatile(
        "mma.sync.aligned.m16n8k8.row.col.f32.tf32.tf32.f32 "
        "{%0,%1,%2,%3}, {%4,%5,%6,%7}, {%8,%9}, {%0,%1,%2,%3};"
        : "+f"(c[0]), "+f"(c[1]), "+f"(c[2]), "+f"(c[3])
        : "r"(a[0]), "r"(a[1]), "r"(a[2]), "r"(a[3]), "r"(b0), "r"(b1));
}
__device__ __forceinline__ void cp_async16(float* smem, const float* gmem) {
    uint32_t s = (uint32_t)__cvta_generic_to_shared(smem);
    asm volatile("cp.async.cg.shared.global [%0], [%1], 16;" :: "r"(s), "l"(gmem));
}
#define FU(x) __float_as_uint(x)

// ---------------- LayerNorm: warp per row (ln1/ln2) --------------------------
__global__ void k_ln(const float* __restrict__ x, const float* __restrict__ add,
                     const float* __restrict__ gw, const float* __restrict__ bw,
                     float* __restrict__ out)
{
    int row  = blockIdx.x * 8 + (threadIdx.x >> 5);
    int lane = threadIdx.x & 31;
    const float4* xp = (const float4*)(x + (size_t)row * DD);
    float4 v = xp[lane];
    if (add) {
        float4 a = ((const float4*)(add + (size_t)row * DD))[lane];
        v.x += a.x; v.y += a.y; v.z += a.z; v.w += a.w;
    }
    float s = v.x + v.y + v.z + v.w;
    #pragma unroll
    for (int o = 16; o; o >>= 1) s += __shfl_xor_sync(0xffffffffu, s, o);
    float mean = s * (1.f/128.f);
    float dx = v.x-mean, dy = v.y-mean, dz = v.z-mean, dw = v.w-mean;
    float q = dx*dx + dy*dy + dz*dz + dw*dw;
    #pragma unroll
    for (int o = 16; o; o >>= 1) q += __shfl_xor_sync(0xffffffffu, q, o);
    float inv = rsqrtf(q * (1.f/128.f) + 1e-5f);
    float4 g4 = ((const float4*)gw)[lane];
    float4 b4 = ((const float4*)bw)[lane];
    float4 o4;
    o4.x = dx*inv*g4.x + b4.x;  o4.y = dy*inv*g4.y + b4.y;
    o4.z = dz*inv*g4.z + b4.z;  o4.w = dw*inv*g4.w + b4.w;
    ((float4*)(out + (size_t)row * DD))[lane] = o4;
}

// -------- tnorm LN + fused asrc/adst (replaces step-8 k_ln + k_asd) ----------
__global__ void k_ln_asd(const float* __restrict__ x, const float* __restrict__ add,
                         const float* __restrict__ gw, const float* __restrict__ bw,
                         float* __restrict__ out)
{
    __shared__ float4 W4[8][32];
    int tid = threadIdx.x;
    int warp = tid >> 5, lane = tid & 31;
    for (int i = tid; i < 256; i += 256)
        ((float4*)W4)[i] = ((const float4*)g_watt)[i];
    __syncthreads();

    int row = blockIdx.x * 8 + warp;
    float4 v = ((const float4*)(x + (size_t)row * DD))[lane];
    float4 a = ((const float4*)(add + (size_t)row * DD))[lane];
    v.x += a.x; v.y += a.y; v.z += a.z; v.w += a.w;
    float s = v.x + v.y + v.z + v.w;
    #pragma unroll
    for (int o = 16; o; o >>= 1) s += __shfl_xor_sync(0xffffffffu, s, o);
    float mean = s * (1.f/128.f);
    float dx = v.x-mean, dy = v.y-mean, dz = v.z-mean, dw = v.w-mean;
    float q = dx*dx + dy*dy + dz*dz + dw*dw;
    #pragma unroll
    for (int o = 16; o; o >>= 1) q += __shfl_xor_sync(0xffffffffu, q, o);
    float inv = rsqrtf(q * (1.f/128.f) + 1e-5f);
    float4 g4 = ((const float4*)gw)[lane];
    float4 b4 = ((const float4*)bw)[lane];
    float4 o4;
    o4.x = dx*inv*g4.x + b4.x;  o4.y = dy*inv*g4.y + b4.y;
    o4.z = dz*inv*g4.z + b4.z;  o4.w = dw*inv*g4.w + b4.w;
    ((float4*)(out + (size_t)row * DD))[lane] = o4;

    // fused asrc/adst: 8 dot products of this row with W_att
    int p = row & 127, bs = row >> 7;
    int sidx = bs & 63, b = bs >> 6;
    #pragma unroll
    for (int r = 0; r < 8; r++) {
        float4 w = W4[r][lane];
        float d = o4.x*w.x + o4.y*w.y + o4.z*w.z + o4.w*w.w;
        #pragma unroll
        for (int o = 16; o; o >>= 1) d += __shfl_xor_sync(0xffffffffu, d, o);
        if (lane == 0) {
            int h = r & 3;
            float* dst = (r < 4) ? g_asrc : g_adst;
            dst[(((b*4 + h)*128 + p)*64) + sidx] = d;
        }
    }
}

// ---------------- tf32 GEMM, cp.async 2-stage pipeline (R7-proven) -----------
#define TBM 128
#define TBN 128
#define TILE (128*36)
__global__ void __launch_bounds__(256)
k_mma(const float* __restrict__ A, const float* __restrict__ W,
      const float* __restrict__ bias, const float* __restrict__ res,
      float* __restrict__ out, int M, int N, int K, int relu)
{
    extern __shared__ float smbuf[];
    float* As = smbuf;
    float* Bs = smbuf + 2*TILE;
    int tid  = threadIdx.x;
    int warp = tid >> 5, lane = tid & 31;
    int wm = warp >> 1, wn = warp & 1;
    int g = lane >> 2, t = lane & 3;
    int m0 = blockIdx.y * TBM;
    int n0 = blockIdx.x * TBN;
    int lr = tid >> 3, lc = (tid & 7) << 2;

    float acc[2][8][4] = {};
    const int nk = K >> 5;

    #pragma unroll
    for (int i = 0; i < 4; i++) {
        int r = lr + i * 32;
        cp_async16(&As[r*36 + lc], A + (size_t)(m0 + r) * K + lc);
        cp_async16(&Bs[r*36 + lc], W + (size_t)(n0 + r) * K + lc);
    }
    asm volatile("cp.async.commit_group;");

    for (int kt = 0; kt < nk; kt++) {
        int buf = (kt & 1) * TILE;
        if (kt + 1 < nk) {
            int nb = ((kt + 1) & 1) * TILE;
            int ko = (kt + 1) << 5;
            #pragma unroll
            for (int i = 0; i < 4; i++) {
                int r = lr + i * 32;
                cp_async16(&As[nb + r*36 + lc], A + (size_t)(m0 + r) * K + ko + lc);
                cp_async16(&Bs[nb + r*36 + lc], W + (size_t)(n0 + r) * K + ko + lc);
            }
            asm volatile("cp.async.commit_group;");
            asm volatile("cp.async.wait_group 1;");
        } else {
            asm volatile("cp.async.wait_group 0;");
        }
        __syncthreads();
        #pragma unroll
        for (int kk = 0; kk < 32; kk += 8) {
            uint32_t afrag[2][4];
            #pragma unroll
            for (int mi = 0; mi < 2; mi++) {
                int r = wm * 32 + mi * 16;
                afrag[mi][0] = FU(As[buf + (r + g    )*36 + kk + t    ]);
                afrag[mi][1] = FU(As[buf + (r + g + 8)*36 + kk + t    ]);
                afrag[mi][2] = FU(As[buf + (r + g    )*36 + kk + t + 4]);
                afrag[mi][3] = FU(As[buf + (r + g + 8)*36 + kk + t + 4]);
            }
            #pragma unroll
            for (int ni = 0; ni < 8; ni++) {
                int c = wn * 64 + ni * 8;
                uint32_t b0 = FU(Bs[buf + (c + g)*36 + kk + t    ]);
                uint32_t b1 = FU(Bs[buf + (c + g)*36 + kk + t + 4]);
                mma8(acc[0][ni], afrag[0], b0, b1);
                mma8(acc[1][ni], afrag[1], b0, b1);
            }
        }
        __syncthreads();
    }

    #pragma unroll
    for (int mi = 0; mi < 2; mi++) {
        #pragma unroll
        for (int ni = 0; ni < 8; ni++) {
            int r = m0 + wm * 32 + mi * 16 + g;
            int c = n0 + wn * 64 + ni * 8 + 2 * t;
            float bv0 = bias ? bias[c]     : 0.f;
            float bv1 = bias ? bias[c + 1] : 0.f;
            #pragma unroll
            for (int half = 0; half < 2; half++) {
                int row = r + half * 8;
                float v0 = acc[mi][ni][half*2 + 0] + bv0;
                float v1 = acc[mi][ni][half*2 + 1] + bv1;
                if (relu) { v0 = fmaxf(v0, 0.f); v1 = fmaxf(v1, 0.f); }
                if (res) {
                    const float2 rr = *(const float2*)(res + (size_t)row * N + c);
                    v0 += rr.x; v1 += rr.y;
                }
                *(float2*)(out + (size_t)row * N + c) = make_float2(v0, v1);
            }
        }
    }
}

// ---------------- tf32 GEMM -> bf16 output (optional bias) -------------------
__global__ void __launch_bounds__(256)
k_mma_bf(const float* __restrict__ A, const float* __restrict__ W,
         const float* __restrict__ bias, __nv_bfloat16* __restrict__ out,
         int N, int K)
{
    extern __shared__ float smbuf[];
    float* As = smbuf;
    float* Bs = smbuf + 2*TILE;
    int tid  = threadIdx.x;
    int warp = tid >> 5, lane = tid & 31;
    int wm = warp >> 1, wn = warp & 1;
    int g = lane >> 2, t = lane & 3;
    int m0 = blockIdx.y * TBM;
    int n0 = blockIdx.x * TBN;
    int lr = tid >> 3, lc = (tid & 7) << 2;

    float acc[2][8][4] = {};
    const int nk = K >> 5;

    #pragma unroll
    for (int i = 0; i < 4; i++) {
        int r = lr + i * 32;
        cp_async16(&As[r*36 + lc], A + (size_t)(m0 + r) * K + lc);
        cp_async16(&Bs[r*36 + lc], W + (size_t)(n0 + r) * K + lc);
    }
    asm volatile("cp.async.commit_group;");

    for (int kt = 0; kt < nk; kt++) {
        int buf = (kt & 1) * TILE;
        if (kt + 1 < nk) {
            int nb = ((kt + 1) & 1) * TILE;
            int ko = (kt + 1) << 5;
            #pragma unroll
            for (int i = 0; i < 4; i++) {
                int r = lr + i * 32;
                cp_async16(&As[nb + r*36 + lc], A + (size_t)(m0 + r) * K + ko + lc);
                cp_async16(&Bs[nb + r*36 + lc], W + (size_t)(n0 + r) * K + ko + lc);
            }
            asm volatile("cp.async.commit_group;");
            asm volatile("cp.async.wait_group 1;");
        } else {
            asm volatile("cp.async.wait_group 0;");
        }
        __syncthreads();
        #pragma unroll
        for (int kk = 0; kk < 32; kk += 8) {
            uint32_t afrag[2][4];
            #pragma unroll
            for (int mi = 0; mi < 2; mi++) {
                int r = wm * 32 + mi * 16;
                afrag[mi][0] = FU(As[buf + (r + g    )*36 + kk + t    ]);
                afrag[mi][1] = FU(As[buf + (r + g + 8)*36 + kk + t    ]);
                afrag[mi][2] = FU(As[buf + (r + g    )*36 + kk + t + 4]);
                afrag[mi][3] = FU(As[buf + (r + g + 8)*36 + kk + t + 4]);
            }
            #pragma unroll
            for (int ni = 0; ni < 8; ni++) {
                int c = wn * 64 + ni * 8;
                uint32_t b0 = FU(Bs[buf + (c + g)*36 + kk + t    ]);
                uint32_t b1 = FU(Bs[buf + (c + g)*36 + kk + t + 4]);
                mma8(acc[0][ni], afrag[0], b0, b1);
                mma8(acc[1][ni], afrag[1], b0, b1);
            }
        }
        __syncthreads();
    }

    #pragma unroll
    for (int mi = 0; mi < 2; mi++) {
        #pragma unroll
        for (int ni = 0; ni < 8; ni++) {
            int r = m0 + wm * 32 + mi * 16 + g;
            int c = n0 + wn * 64 + ni * 8 + 2 * t;
            float bv0 = bias ? bias[c]     : 0.f;
            float bv1 = bias ? bias[c + 1] : 0.f;
            #pragma unroll
            for (int half = 0; half < 2; half++) {
                int row = r + half * 8;
                __nv_bfloat162 bv = __floats2bfloat162_rn(acc[mi][ni][half*2 + 0] + bv0,
                                                          acc[mi][ni][half*2 + 1] + bv1);
                *(__nv_bfloat162*)(out + (size_t)row * N + c) = bv;
            }
        }
    }
}

// ---------------- small SIMT GEMM (q2/k2) ------------------------------------
#define BM 64
#define BN 64
#define BK 16
__global__ void k_gemm(const float* __restrict__ A, const float* __restrict__ W,
                       const float* __restrict__ bias, float* __restrict__ out,
                       int M, int N, int K)
{
    __shared__ float As[BK][BM];
    __shared__ float Bs[BK][BN];
    int tid = threadIdx.x;
    int tx = tid & 15, ty = tid >> 4;
    int m0 = blockIdx.y * BM, n0 = blockIdx.x * BN;
    int lr = tid >> 2;
    int lk = (tid & 3) * 4;
    float acc[4][4] = {};
    for (int k0 = 0; k0 < K; k0 += BK) {
        float4 a4 = *(const float4*)(A + (size_t)(m0 + lr) * K + k0 + lk);
        float4 b4 = *(const float4*)(W + (size_t)(n0 + lr) * K + k0 + lk);
        As[lk+0][lr] = a4.x; As[lk+1][lr] = a4.y; As[lk+2][lr] = a4.z; As[lk+3][lr] = a4.w;
        Bs[lk+0][lr] = b4.x; Bs[lk+1][lr] = b4.y; Bs[lk+2][lr] = b4.z; Bs[lk+3][lr] = b4.w;
        __syncthreads();
        #pragma unroll
        for (int k = 0; k < BK; k++) {
            float4 ra = *(const float4*)&As[k][ty*4];
            float4 rb = *(const float4*)&Bs[k][tx*4];
            float av[4] = {ra.x, ra.y, ra.z, ra.w};
            float bv[4] = {rb.x, rb.y, rb.z, rb.w};
            #pragma unroll
            for (int i = 0; i < 4; i++)
                #pragma unroll
                for (int j = 0; j < 4; j++)
                    acc[i][j] += av[i] * bv[j];
        }
        __syncthreads();
    }
    #pragma unroll
    for (int i = 0; i < 4; i++) {
        int m = m0 + ty*4 + i;
        #pragma unroll
        for (int j = 0; j < 4; j++) {
            int n = n0 + tx*4 + j;
            out[(size_t)m * N + n] = acc[i][j] + bias[n];
        }
    }
}

// ============== attention v4 + vectorized bf16 loads =========================
#define AQS 36
#define AVS 132
#define APW 68
__global__ void __launch_bounds__(128, 3)
k_attn_mma()
{
    extern __shared__ float sm[];
    float* Qs = sm;                  // [128][36]
    float* Ks = sm + 4608;           // [128][36]
    float* VT = sm + 9216;           // [32][132]
    float* Pb = sm;                  // union: per-warp [32][68]

    int n = blockIdx.x >> 2, h = blockIdx.x & 3;
    int tid = threadIdx.x;
    int warp = tid >> 5, lane = tid & 31;
    int g = lane >> 2, t = lane & 3;
    int m0 = warp * 32;
    const __nv_bfloat16* base = g_qkvb + (size_t)n * NP * 3 * DD;

    // uint4 loads: 8 bf16 per access, 512 accesses per matrix
    for (int idx = tid; idx < NP*4; idx += 128) {
        int j = idx >> 2, dc = (idx & 3) * 8;
        uint4 qv = *(const uint4*)(base + j*384 +       h*32 + dc);
        uint4 kv = *(const uint4*)(base + j*384 + 128 + h*32 + dc);
        uint4 vv = *(const uint4*)(base + j*384 + 256 + h*32 + dc);
        float2 q0 = __bfloat1622float2(*(__nv_bfloat162*)&qv.x);
        float2 q1 = __bfloat1622float2(*(__nv_bfloat162*)&qv.y);
        float2 q2 = __bfloat1622float2(*(__nv_bfloat162*)&qv.z);
        float2 q3 = __bfloat1622float2(*(__nv_bfloat162*)&qv.w);
        *(float4*)&Qs[j*AQS + dc    ] = make_float4(q0.x, q0.y, q1.x, q1.y);
        *(float4*)&Qs[j*AQS + dc + 4] = make_float4(q2.x, q2.y, q3.x, q3.y);
        float2 k0 = __bfloat1622float2(*(__nv_bfloat162*)&kv.x);
        float2 k1 = __bfloat1622float2(*(__nv_bfloat162*)&kv.y);
        float2 k2 = __bfloat1622float2(*(__nv_bfloat162*)&kv.z);
        float2 k3 = __bfloat1622float2(*(__nv_bfloat162*)&kv.w);
        *(float4*)&Ks[j*AQS + dc    ] = make_float4(k0.x, k0.y, k1.x, k1.y);
        *(float4*)&Ks[j*AQS + dc + 4] = make_float4(k2.x, k2.y, k3.x, k3.y);
        float2 v0 = __bfloat1622float2(*(__nv_bfloat162*)&vv.x);
        float2 v1 = __bfloat1622float2(*(__nv_bfloat162*)&vv.y);
        float2 v2 = __bfloat1622float2(*(__nv_bfloat162*)&vv.z);
        float2 v3 = __bfloat1622float2(*(__nv_bfloat162*)&vv.w);
        VT[(dc    )*AVS + j] = v0.x;  VT[(dc + 1)*AVS + j] = v0.y;
        VT[(dc + 2)*AVS + j] = v1.x;  VT[(dc + 3)*AVS + j] = v1.y;
        VT[(dc + 4)*AVS + j] = v2.x;  VT[(dc + 5)*AVS + j] = v2.y;
        VT[(dc + 6)*AVS + j] = v3.x;  VT[(dc + 7)*AVS + j] = v3.y;
    }
    __syncthreads();

    float s[2][16][4] = {};
    #pragma unroll
    for (int kk = 0; kk < 32; kk += 8) {
        uint32_t afrag[2][4];
        #pragma unroll
        for (int mi = 0; mi < 2; mi++) {
            int r = m0 + mi * 16;
            afrag[mi][0] = FU(Qs[(r + g    )*AQS + kk + t    ]);
            afrag[mi][1] = FU(Qs[(r + g + 8)*AQS + kk + t    ]);
            afrag[mi][2] = FU(Qs[(r + g    )*AQS + kk + t + 4]);
            afrag[mi][3] = FU(Qs[(r + g + 8)*AQS + kk + t + 4]);
        }
        #pragma unroll
        for (int ni = 0; ni < 16; ni++) {
            int c = ni * 8;
            uint32_t b0 = FU(Ks[(c + g)*AQS + kk + t    ]);
            uint32_t b1 = FU(Ks[(c + g)*AQS + kk + t + 4]);
            mma8(s[0][ni], afrag[0], b0, b1);
            mma8(s[1][ni], afrag[1], b0, b1);
        }
    }
    __syncthreads();

    const float scale = 0.17677669529663687f;
    float mx[2][2] = {{-INFINITY,-INFINITY},{-INFINITY,-INFINITY}};
    #pragma unroll
    for (int mi = 0; mi < 2; mi++)
        #pragma unroll
        for (int ni = 0; ni < 16; ni++) {
            #pragma unroll
            for (int q = 0; q < 4; q++) s[mi][ni][q] *= scale;
            mx[mi][0] = fmaxf(mx[mi][0], fmaxf(s[mi][ni][0], s[mi][ni][1]));
            mx[mi][1] = fmaxf(mx[mi][1], fmaxf(s[mi][ni][2], s[mi][ni][3]));
        }
    #pragma unroll
    for (int mi = 0; mi < 2; mi++)
        #pragma unroll
        for (int hf = 0; hf < 2; hf++) {
            mx[mi][hf] = fmaxf(mx[mi][hf], __shfl_xor_sync(0xffffffffu, mx[mi][hf], 1));
            mx[mi][hf] = fmaxf(mx[mi][hf], __shfl_xor_sync(0xffffffffu, mx[mi][hf], 2));
        }
    float sum[2][2] = {};
    #pragma unroll
    for (int mi = 0; mi < 2; mi++)
        #pragma unroll
        for (int ni = 0; ni < 16; ni++) {
            s[mi][ni][0] = __expf(s[mi][ni][0] - mx[mi][0]);
            s[mi][ni][1] = __expf(s[mi][ni][1] - mx[mi][0]);
            s[mi][ni][2] = __expf(s[mi][ni][2] - mx[mi][1]);
            s[mi][ni][3] = __expf(s[mi][ni][3] - mx[mi][1]);
            sum[mi][0] += s[mi][ni][0] + s[mi][ni][1];
            sum[mi][1] += s[mi][ni][2] + s[mi][ni][3];
        }
    float inv[2][2];
    #pragma unroll
    for (int mi = 0; mi < 2; mi++)
        #pragma unroll
        for (int hf = 0; hf < 2; hf++) {
            float ss = sum[mi][hf];
            ss += __shfl_xor_sync(0xffffffffu, ss, 1);
            ss += __shfl_xor_sync(0xffffffffu, ss, 2);
            inv[mi][hf] = 1.f / ss;
        }

    float* Pw = Pb + warp * (32 * APW);
    float o[2][4][4] = {};
    #pragma unroll
    for (int hf = 0; hf < 2; hf++) {
        #pragma unroll
        for (int mi = 0; mi < 2; mi++) {
            int lr = mi * 16 + g;
            #pragma unroll
            for (int ni = 0; ni < 8; ni++) {
                int c = ni * 8 + 2 * t;
                Pw[ lr      *APW + c    ] = s[mi][hf*8 + ni][0];
                Pw[ lr      *APW + c + 1] = s[mi][hf*8 + ni][1];
                Pw[(lr + 8) *APW + c    ] = s[mi][hf*8 + ni][2];
                Pw[(lr + 8) *APW + c + 1] = s[mi][hf*8 + ni][3];
            }
        }
        __syncwarp();
        #pragma unroll
        for (int kk = 0; kk < 64; kk += 8) {
            uint32_t afrag[2][4];
            #pragma unroll
            for (int mi = 0; mi < 2; mi++) {
                int lr = mi * 16;
                afrag[mi][0] = FU(Pw[(lr + g    )*APW + kk + t    ]);
                afrag[mi][1] = FU(Pw[(lr + g + 8)*APW + kk + t    ]);
                afrag[mi][2] = FU(Pw[(lr + g    )*APW + kk + t + 4]);
                afrag[mi][3] = FU(Pw[(lr + g + 8)*APW + kk + t + 4]);
            }
            int j0 = hf*64 + kk + t, j1 = hf*64 + kk + t + 4;
            #pragma unroll
            for (int ni = 0; ni < 4; ni++) {
                int c = ni * 8;
                uint32_t b0 = FU(VT[(c + g)*AVS + j0]);
                uint32_t b1 = FU(VT[(c + g)*AVS + j1]);
                mma8(o[0][ni], afrag[0], b0, b1);
                mma8(o[1][ni], afrag[1], b0, b1);
            }
        }
        __syncwarp();
    }

    #pragma unroll
    for (int mi = 0; mi < 2; mi++) {
        int r0 = n*NP + m0 + mi * 16 + g;
        #pragma unroll
        for (int ni = 0; ni < 4; ni++) {
            int d = ni * 8 + 2 * t;
            *(float2*)(g_o + (size_t) r0      *DD + h*32 + d) =
                make_float2(o[mi][ni][0]*inv[mi][0], o[mi][ni][1]*inv[mi][0]);
            *(float2*)(g_o + (size_t)(r0 + 8) *DD + h*32 + d) =
                make_float2(o[mi][ni][2]*inv[mi][1], o[mi][ni][3]*inv[mi][1]);
        }
    }
}

// ---------------- mean over Np -----------------------------------------------
__global__ void k_mean()
{
    int n = blockIdx.x, d = threadIdx.x;
    float s = 0.f;
    for (int p = 0; p < NP; p++) s += g_Htemp[((size_t)n*NP + p)*DD + d];
    g_Hs[n*DD + d] = s * (1.f/128.f);
}

// ---------------- W_att = gat_w[h]^T @ att{src,dst}[h] -----------------------
__global__ void k_watt(const float* __restrict__ gw, const float* __restrict__ asv,
                       const float* __restrict__ adv)
{
    int idx = blockIdx.x * 256 + threadIdx.x;
    int r = idx >> 7, d = idx & 127;
    int h = r & 3;
    const float* att = (r < 4) ? asv : adv;
    float s = 0.f;
    for (int f = 0; f < 128; f++)
        s += att[h*FF + f] * gw[h*FF*DD + f*DD + d];
    g_watt[r*DD + d] = s;
}

// ---------------- graph adjacency --------------------------------------------
__global__ void k_graph(const float* __restrict__ adj)
{
    __shared__ float k2s[CC*DK];
    __shared__ float Amat[CC*65];
    int b = blockIdx.x, c = threadIdx.x;
    for (int idx = c; idx < CC*DK; idx += 64) k2s[idx] = g_k2[(size_t)b*CC*DK + idx];
    __syncthreads();
    float qreg[DK];
    #pragma unroll
    for (int d = 0; d < DK; d++) qreg[d] = g_q2[(size_t)b*CC*DK + c*DK + d];
    for (int e = 0; e < CC; e++) {
        float a = 0.f;
        #pragma unroll
        for (int d = 0; d < DK; d++) a += qreg[d] * k2s[e*DK + d];
        Amat[c*65 + e] = tanhf(a * 0.125f) + adj[c*CC + e];
    }
    for (int e = 0; e < CC; e++) g_mask[(size_t)b*CC*CC + c*CC + e] = 0.f;
    for (int kk = 0; kk < 8; kk++) {
        float best = -INFINITY; int bi = 0;
        for (int e = 0; e < CC; e++) {
            float v = Amat[c*65 + e];
            if (v > best) { best = v; bi = e; }
        }
        if (bi != c && best != 0.f) g_mask[(size_t)b*CC*CC + c*CC + bi] = 1.f;
        Amat[c*65 + bi] = -INFINITY;
    }
}

// ============== GAT v2 (R12-proven, bf16 xh) =================================
#define XST 68
#define AST 68
#define OST 132
#define GU  8704
__global__ void __launch_bounds__(256)
k_gat(const float* __restrict__ gbias, const float* __restrict__ sg,
      const float* __restrict__ sb, float* __restrict__ out)
{
    extern __shared__ float sm[];
    float* U   = sm;
    float* Awt = sm + GU;
    float* Asv = sm + GU + 4352;
    float* Adv = sm + GU + 4416;
    float* XhT = U;
    float* Os  = U;

    int b = blockIdx.x >> 7, p = blockIdx.x & 127;
    int tid = threadIdx.x, w = tid >> 5, lane = tid & 31;
    int wm = w >> 2, wn = w & 3;
    int g = lane >> 2, t4 = lane & 3;

    float mr0[8], mr1[8];
    #pragma unroll
    for (int i = 0; i < 8; i++) {
        int t = w*8 + i;
        mr0[i] = g_mask[(size_t)b*CC*CC + lane*CC + t];
        mr1[i] = g_mask[(size_t)b*CC*CC + (lane+32)*CC + t];
    }

    float acc[2][4][4] = {};
    for (int h = 0; h < HS; h++) {
        __syncthreads();
        for (int idx = tid; idx < CC*FF/2; idx += 256) {
            int s = idx >> 6, fp = idx & 63;
            const __nv_bfloat162 v2 = *(const __nv_bfloat162*)
                (g_xhb + (size_t)(((b*CC + s)*NP + p))*(HS*FF) + h*FF + 2*fp);
            float2 vf = __bfloat1622float2(v2);
            XhT[(2*fp    )*XST + s] = vf.x;
            XhT[(2*fp + 1)*XST + s] = vf.y;
        }
        if (tid < 64)            Asv[tid]      = g_asrc[(((b*4 + h)*128 + p)*64) + tid];
        else if (tid < 128)      Adv[tid - 64] = g_adst[(((b*4 + h)*128 + p)*64) + tid - 64];
        __syncthreads();

        #pragma unroll
        for (int i = 0; i < 8; i++) {
            int t = w*8 + i;
            float adt = Adv[t];
            float e0 = Asv[lane]      + adt; e0 = e0 > 0.f ? e0 : 0.2f*e0;
            float e1 = Asv[lane + 32] + adt; e1 = e1 > 0.f ? e1 : 0.2f*e1;
            float me = fmaxf(mr0[i] > 0.5f ? e0 : GAT_NEG, mr1[i] > 0.5f ? e1 : GAT_NEG);
            #pragma unroll
            for (int o = 16; o; o >>= 1) me = fmaxf(me, __shfl_xor_sync(0xffffffffu, me, o));
            float w0 = (mr0[i] > 0.5f) ? __expf(e0 - me) : 0.f;
            float w1 = (mr1[i] > 0.5f) ? __expf(e1 - me) : 0.f;
            float ws = w0 + w1;
            #pragma unroll
            for (int o = 16; o; o >>= 1) ws += __shfl_xor_sync(0xffffffffu, ws, o);
            float inv = ws > 0.f ? 1.f / ws : 0.f;
            Awt[t*AST + lane]      = w0 * inv;
            Awt[t*AST + lane + 32] = w1 * inv;
        }
        __syncthreads();

        #pragma unroll
        for (int kk = 0; kk < CC; kk += 8) {
            uint32_t afrag[2][4];
            #pragma unroll
            for (int mi = 0; mi < 2; mi++) {
                int r = wm * 32 + mi * 16;
                afrag[mi][0] = FU(Awt[(r + g    )*AST + kk + t4    ]);
                afrag[mi][1] = FU(Awt[(r + g + 8)*AST + kk + t4    ]);
                afrag[mi][2] = FU(Awt[(r + g    )*AST + kk + t4 + 4]);
                afrag[mi][3] = FU(Awt[(r + g + 8)*AST + kk + t4 + 4]);
            }
            #pragma unroll
            for (int ni = 0; ni < 4; ni++) {
                int c = wn * 32 + ni * 8;
                uint32_t b0 = FU(XhT[(c + g)*XST + kk + t4    ]);
                uint32_t b1 = FU(XhT[(c + g)*XST + kk + t4 + 4]);
                mma8(acc[0][ni], afrag[0], b0, b1);
                mma8(acc[1][ni], afrag[1], b0, b1);
            }
        }
    }

    __syncthreads();
    for (int idx = tid; idx < CC*DD; idx += 256) {
        int r = idx >> 7, f = idx & 127;
        Os[r*OST + f] = g_Htemp[(((size_t)(b*CC + r))*NP + p)*DD + f] + gbias[f];
    }
    __syncthreads();
    #pragma unroll
    for (int mi = 0; mi < 2; mi++)
        #pragma unroll
        for (int ni = 0; ni < 4; ni++) {
            int r = wm*32 + mi*16 + g;
            int c = wn*32 + ni*8 + 2*t4;
            #pragma unroll
            for (int half = 0; half < 2; half++) {
                int row = r + half*8;
                Os[row*OST + c    ] += acc[mi][ni][half*2 + 0] * 0.25f;
                Os[row*OST + c + 1] += acc[mi][ni][half*2 + 1] * 0.25f;
            }
        }
    __syncthreads();
    {
        float4 g4 = ((const float4*)sg)[lane];
        float4 b4 = ((const float4*)sb)[lane];
        for (int r = w; r < CC; r += 8) {
            float4 v = *(float4*)&Os[r*OST + lane*4];
            float s1 = v.x + v.y + v.z + v.w;
            #pragma unroll
            for (int o = 16; o; o >>= 1) s1 += __shfl_xor_sync(0xffffffffu, s1, o);
            float mean = s1 * (1.f/128.f);
            float dx=v.x-mean, dy=v.y-mean, dz=v.z-mean, dw=v.w-mean;
            float q = dx*dx+dy*dy+dz*dz+dw*dw;
            #pragma unroll
            for (int o = 16; o; o >>= 1) q += __shfl_xor_sync(0xffffffffu, q, o);
            float inv = rsqrtf(q * (1.f/128.f) + 1e-5f);
            float4 ov;
            ov.x = dx*inv*g4.x + b4.x; ov.y = dy*inv*g4.y + b4.y;
            ov.z = dz*inv*g4.z + b4.z; ov.w = dw*inv*g4.w + b4.w;
            ((float4*)(out + (((size_t)(b*CC + r))*NP + p)*DD))[lane] = ov;
        }
    }
}

// ---------------- host launch -------------------------------------------------
extern "C" void kernel_launch(void* const* d_in, const int* in_sizes, int n_in,
                              void* d_out, int out_size)
{
    const float* H_in      = (const float*)d_in[0];
    const float* static_adj= (const float*)d_in[1];
    const float* attn_in_w = (const float*)d_in[2];
    const float* attn_in_b = (const float*)d_in[3];
    const float* attn_out_w= (const float*)d_in[4];
    const float* attn_out_b= (const float*)d_in[5];
    const float* ln1_g     = (const float*)d_in[6];
    const float* ln1_b     = (const float*)d_in[7];
    const float* ln2_g     = (const float*)d_in[8];
    const float* ln2_b     = (const float*)d_in[9];
    const float* ff1_w     = (const float*)d_in[10];
    const float* ff1_b     = (const float*)d_in[11];
    const float* ff2_w     = (const float*)d_in[12];
    const float* ff2_b     = (const float*)d_in[13];
    const float* tnorm_g   = (const float*)d_in[14];
    const float* tnorm_b   = (const float*)d_in[15];
    const float* q_w       = (const float*)d_in[16];
    const float* q_b       = (const float*)d_in[17];
    const float* k_w       = (const float*)d_in[18];
    const float* k_b       = (const float*)d_in[19];
    const float* gat_w     = (const float*)d_in[20];
    const float* gat_att_src = (const float*)d_in[21];
    const float* gat_att_dst = (const float*)d_in[22];
    const float* gat_bias  = (const float*)d_in[23];
    const float* snorm_g   = (const float*)d_in[24];
    const float* snorm_b   = (const float*)d_in[25];

    float *h_, *o_, *x_, *ff_, *Htemp_, *Hs_, *q2_, *k2_;
    __nv_bfloat16 *xhb_, *qkvb_;
    cudaGetSymbolAddress((void**)&h_,     g_h);
    cudaGetSymbolAddress((void**)&qkvb_,  g_qkvb);
    cudaGetSymbolAddress((void**)&o_,     g_o);
    cudaGetSymbolAddress((void**)&x_,     g_x);
    cudaGetSymbolAddress((void**)&ff_,    g_ff);
    cudaGetSymbolAddress((void**)&Htemp_, g_Htemp);
    cudaGetSymbolAddress((void**)&xhb_,   g_xhb);
    cudaGetSymbolAddress((void**)&Hs_,    g_Hs);
    cudaGetSymbolAddress((void**)&q2_,    g_q2);
    cudaGetSymbolAddress((void**)&k2_,    g_k2);

    const int mma_smem  = 4 * TILE * 4;                // 73728
    const int attn_smem = 13440 * 4;                   // 53760
    const int gat_smem  = (GU + 4352 + 128) * 4;       // 52736
    cudaFuncSetAttribute(k_mma, cudaFuncAttributeMaxDynamicSharedMemorySize, mma_smem);
    cudaFuncSetAttribute(k_mma_bf, cudaFuncAttributeMaxDynamicSharedMemorySize, mma_smem);
    cudaFuncSetAttribute(k_attn_mma, cudaFuncAttributeMaxDynamicSharedMemorySize, attn_smem);
    cudaFuncSetAttribute(k_gat,  cudaFuncAttributeMaxDynamicSharedMemorySize, gat_smem);

    // 0) W_att vectors
    k_watt<<<4, 256>>>(gat_w, gat_att_src, gat_att_dst);
    // 1) h = ln1(x0)
    k_ln<<<NTOK/8, 256>>>(H_in, nullptr, ln1_g, ln1_b, h_);
    // 2) qkv = h @ Wqkv^T + b  (bf16 output)
    k_mma_bf<<<dim3(3, NTOK/TBM), 256, mma_smem>>>(h_, attn_in_w, attn_in_b, qkvb_,
                                                   384, 128);
    // 3) temporal attention v4 (vectorized bf16 loads)
    k_attn_mma<<<NSEQ*HT, 128, attn_smem>>>();
    // 4) x1 = x0 + o @ Wout^T + b
    k_mma<<<dim3(1, NTOK/TBM), 256, mma_smem>>>(o_, attn_out_w, attn_out_b, H_in, x_,
                                                NTOK, 128, 128, 0);
    // 5) h = ln2(x1)
    k_ln<<<NTOK/8, 256>>>(x_, nullptr, ln2_g, ln2_b, h_);
    // 6) ff = relu(h @ W1^T + b1)
    k_mma<<<dim3(4, NTOK/TBM), 256, mma_smem>>>(h_, ff1_w, ff1_b, nullptr, ff_,
                                                NTOK, 512, 128, 1);
    // 7) x2 = x1 + ff @ W2^T + b2
    k_mma<<<dim3(1, NTOK/TBM), 256, mma_smem>>>(ff_, ff2_w, ff2_b, x_, x_,
                                                NTOK, 128, 512, 0);
    // 8) H_temp = ln(x0 + x2, tnorm) + fused asrc/adst
    k_ln_asd<<<NTOK/8, 256>>>(x_, H_in, tnorm_g, tnorm_b, Htemp_);
    // 9) xh = H_temp @ gat_w^T  (bf16 output)
    k_mma_bf<<<dim3(4, NTOK/TBM), 256, mma_smem>>>(Htemp_, gat_w, nullptr, xhb_,
                                                   512, 128);
    // 10) Hs = mean_p(H_temp)
    k_mean<<<NSEQ, 128>>>();
    // 11) q2, k2
    k_gemm<<<dim3(1, NSEQ/BM), 256>>>(Hs_, q_w, q_b, q2_, NSEQ, 64, 128);
    k_gemm<<<dim3(1, NSEQ/BM), 256>>>(Hs_, k_w, k_b, k2_, NSEQ, 64, 128);
    // 12) adjacency / top-k / mask
    k_graph<<<BB, 64>>>(static_adj);
    // 13) GAT v2 + snorm LN -> output
    k_gat<<<BB*NP, 256, gat_smem>>>(gat_bias, snorm_g, snorm_b, (float*)d_out);
}

// round 15
// speedup vs baseline: 1.1958x; 1.0113x over previous
#include <cuda_runtime.h>
#include <cuda_bf16.h>
#include <math.h>
#include <stdint.h>

#define BB   16
#define CC   64
#define NP   128
#define DD   128
#define HT   4
#define DH   32
#define HS   4
#define FF   128
#define DK   64
#define NTOK (BB*CC*NP)      // 131072
#define NSEQ (BB*CC)         // 1024
#define GAT_NEG -1e30f

// ---------------- scratch ----------------------------------------------------
__device__ float g_h[NTOK*DD];
__device__ __nv_bfloat16 g_qkvb[(size_t)NTOK*3*DD];
__device__ __nv_bfloat16 g_ob[NTOK*DD];
__device__ float g_x[NTOK*DD];
__device__ __nv_bfloat16 g_ffb[(size_t)NTOK*4*DD];
__device__ float g_Htemp[NTOK*DD];
__device__ __nv_bfloat16 g_xhb[(size_t)NTOK*HS*FF];
__device__ float g_Hs[NSEQ*DD];
__device__ float g_q2[NSEQ*DK];
__device__ float g_k2[NSEQ*DK];
__device__ float g_mask[BB*CC*CC];
__device__ float g_watt[8*DD];
__device__ float g_asrc[BB*HS*NP*CC];
__device__ float g_adst[BB*HS*NP*CC];

// ---------------- helpers ----------------------------------------------------
__device__ __forceinline__ void mma8(float c[4], const uint32_t a[4],
                                     uint32_t b0, uint32_t b1) {
    asm volatile(
        "mma.sync.aligned.m16n8k8.row.col.f32.tf32.tf32.f32 "
        "{%0,%1,%2,%3}, {%4,%5,%6,%7}, {%8,%9}, {%0,%1,%2,%3};"
        : "+f"(c[0]), "+f"(c[1]), "+f"(c[2]), "+f"(c[3])
        : "r"(a[0]), "r"(a[1]), "r"(a[2]), "r"(a[3]), "r"(b0), "r"(b1));
}
__device__ __forceinline__ void cp_async16(void* smem, const void* gmem) {
    uint32_t s = (uint32_t)__cvta_generic_to_shared(smem);
    asm volatile("cp.async.cg.shared.global [%0], [%1], 16;" :: "r"(s), "l"(gmem));
}
#define FU(x) __float_as_uint(x)
#define BF2F(x) __bfloat162float(x)

// ---------------- LayerNorm: warp per row (ln1/ln2) --------------------------
__global__ void k_ln(const float* __restrict__ x, const float* __restrict__ add,
                     const float* __restrict__ gw, const float* __restrict__ bw,
                     float* __restrict__ out)
{
    int row  = blockIdx.x * 8 + (threadIdx.x >> 5);
    int lane = threadIdx.x & 31;
    const float4* xp = (const float4*)(x + (size_t)row * DD);
    float4 v = xp[lane];
    if (add) {
        float4 a = ((const float4*)(add + (size_t)row * DD))[lane];
        v.x += a.x; v.y += a.y; v.z += a.z; v.w += a.w;
    }
    float s = v.x + v.y + v.z + v.w;
    #pragma unroll
    for (int o = 16; o; o >>= 1) s += __shfl_xor_sync(0xffffffffu, s, o);
    float mean = s * (1.f/128.f);
    float dx = v.x-mean, dy = v.y-mean, dz = v.z-mean, dw = v.w-mean;
    float q = dx*dx + dy*dy + dz*dz + dw*dw;
    #pragma unroll
    for (int o = 16; o; o >>= 1) q += __shfl_xor_sync(0xffffffffu, q, o);
    float inv = rsqrtf(q * (1.f/128.f) + 1e-5f);
    float4 g4 = ((const float4*)gw)[lane];
    float4 b4 = ((const float4*)bw)[lane];
    float4 o4;
    o4.x = dx*inv*g4.x + b4.x;  o4.y = dy*inv*g4.y + b4.y;
    o4.z = dz*inv*g4.z + b4.z;  o4.w = dw*inv*g4.w + b4.w;
    ((float4*)(out + (size_t)row * DD))[lane] = o4;
}

// -------- tnorm LN + fused asrc/adst (R14-proven) ----------------------------
__global__ void k_ln_asd(const float* __restrict__ x, const float* __restrict__ add,
                         const float* __restrict__ gw, const float* __restrict__ bw,
                         float* __restrict__ out)
{
    __shared__ float4 W4[8][32];
    int tid = threadIdx.x;
    int warp = tid >> 5, lane = tid & 31;
    for (int i = tid; i < 256; i += 256)
        ((float4*)W4)[i] = ((const float4*)g_watt)[i];
    __syncthreads();

    int row = blockIdx.x * 8 + warp;
    float4 v = ((const float4*)(x + (size_t)row * DD))[lane];
    float4 a = ((const float4*)(add + (size_t)row * DD))[lane];
    v.x += a.x; v.y += a.y; v.z += a.z; v.w += a.w;
    float s = v.x + v.y + v.z + v.w;
    #pragma unroll
    for (int o = 16; o; o >>= 1) s += __shfl_xor_sync(0xffffffffu, s, o);
    float mean = s * (1.f/128.f);
    float dx = v.x-mean, dy = v.y-mean, dz = v.z-mean, dw = v.w-mean;
    float q = dx*dx + dy*dy + dz*dz + dw*dw;
    #pragma unroll
    for (int o = 16; o; o >>= 1) q += __shfl_xor_sync(0xffffffffu, q, o);
    float inv = rsqrtf(q * (1.f/128.f) + 1e-5f);
    float4 g4 = ((const float4*)gw)[lane];
    float4 b4 = ((const float4*)bw)[lane];
    float4 o4;
    o4.x = dx*inv*g4.x + b4.x;  o4.y = dy*inv*g4.y + b4.y;
    o4.z = dz*inv*g4.z + b4.z;  o4.w = dw*inv*g4.w + b4.w;
    ((float4*)(out + (size_t)row * DD))[lane] = o4;

    int p = row & 127, bs = row >> 7;
    int sidx = bs & 63, b = bs >> 6;
    #pragma unroll
    for (int r = 0; r < 8; r++) {
        float4 w = W4[r][lane];
        float d = o4.x*w.x + o4.y*w.y + o4.z*w.z + o4.w*w.w;
        #pragma unroll
        for (int o = 16; o; o >>= 1) d += __shfl_xor_sync(0xffffffffu, d, o);
        if (lane == 0) {
            int h = r & 3;
            float* dst = (r < 4) ? g_asrc : g_adst;
            dst[(((b*4 + h)*128 + p)*64) + sidx] = d;
        }
    }
}

// ---------------- tf32 GEMM -> bf16 out (fp32 A, optional bias/relu) ---------
#define TBM 128
#define TBN 128
#define TILE (128*36)
__global__ void __launch_bounds__(256)
k_mma_bf(const float* __restrict__ A, const float* __restrict__ W,
         const float* __restrict__ bias, __nv_bfloat16* __restrict__ out,
         int N, int K, int relu)
{
    extern __shared__ float smbuf[];
    float* As = smbuf;
    float* Bs = smbuf + 2*TILE;
    int tid  = threadIdx.x;
    int warp = tid >> 5, lane = tid & 31;
    int wm = warp >> 1, wn = warp & 1;
    int g = lane >> 2, t = lane & 3;
    int m0 = blockIdx.y * TBM;
    int n0 = blockIdx.x * TBN;
    int lr = tid >> 3, lc = (tid & 7) << 2;

    float acc[2][8][4] = {};
    const int nk = K >> 5;

    #pragma unroll
    for (int i = 0; i < 4; i++) {
        int r = lr + i * 32;
        cp_async16(&As[r*36 + lc], A + (size_t)(m0 + r) * K + lc);
        cp_async16(&Bs[r*36 + lc], W + (size_t)(n0 + r) * K + lc);
    }
    asm volatile("cp.async.commit_group;");

    for (int kt = 0; kt < nk; kt++) {
        int buf = (kt & 1) * TILE;
        if (kt + 1 < nk) {
            int nb = ((kt + 1) & 1) * TILE;
            int ko = (kt + 1) << 5;
            #pragma unroll
            for (int i = 0; i < 4; i++) {
                int r = lr + i * 32;
                cp_async16(&As[nb + r*36 + lc], A + (size_t)(m0 + r) * K + ko + lc);
                cp_async16(&Bs[nb + r*36 + lc], W + (size_t)(n0 + r) * K + ko + lc);
            }
            asm volatile("cp.async.commit_group;");
            asm volatile("cp.async.wait_group 1;");
        } else {
            asm volatile("cp.async.wait_group 0;");
        }
        __syncthreads();
        #pragma unroll
        for (int kk = 0; kk < 32; kk += 8) {
            uint32_t afrag[2][4];
            #pragma unroll
            for (int mi = 0; mi < 2; mi++) {
                int r = wm * 32 + mi * 16;
                afrag[mi][0] = FU(As[buf + (r + g    )*36 + kk + t    ]);
                afrag[mi][1] = FU(As[buf + (r + g + 8)*36 + kk + t    ]);
                afrag[mi][2] = FU(As[buf + (r + g    )*36 + kk + t + 4]);
                afrag[mi][3] = FU(As[buf + (r + g + 8)*36 + kk + t + 4]);
            }
            #pragma unroll
            for (int ni = 0; ni < 8; ni++) {
                int c = wn * 64 + ni * 8;
                uint32_t b0 = FU(Bs[buf + (c + g)*36 + kk + t    ]);
                uint32_t b1 = FU(Bs[buf + (c + g)*36 + kk + t + 4]);
                mma8(acc[0][ni], afrag[0], b0, b1);
                mma8(acc[1][ni], afrag[1], b0, b1);
            }
        }
        __syncthreads();
    }

    #pragma unroll
    for (int mi = 0; mi < 2; mi++) {
        #pragma unroll
        for (int ni = 0; ni < 8; ni++) {
            int r = m0 + wm * 32 + mi * 16 + g;
            int c = n0 + wn * 64 + ni * 8 + 2 * t;
            float bv0 = bias ? bias[c]     : 0.f;
            float bv1 = bias ? bias[c + 1] : 0.f;
            #pragma unroll
            for (int half = 0; half < 2; half++) {
                int row = r + half * 8;
                float v0 = acc[mi][ni][half*2 + 0] + bv0;
                float v1 = acc[mi][ni][half*2 + 1] + bv1;
                if (relu) { v0 = fmaxf(v0, 0.f); v1 = fmaxf(v1, 0.f); }
                *(__nv_bfloat162*)(out + (size_t)row * N + c) = __floats2bfloat162_rn(v0, v1);
            }
        }
    }
}

// ---------------- tf32 GEMM with bf16 A operand -> fp32 out (+bias,+res) -----
// A bf16 smem tile stride 40 (80 B/row, conflict-free fragment banks).
#define TA 40
#define TILEA (128*TA)      // bf16 elements per A buffer
__global__ void __launch_bounds__(256)
k_mma_bfA(const __nv_bfloat16* __restrict__ A, const float* __restrict__ W,
          const float* __restrict__ bias, const float* __restrict__ res,
          float* __restrict__ out, int N, int K)
{
    extern __shared__ float smbuf[];
    __nv_bfloat16* AsB = (__nv_bfloat16*)smbuf;          // 2*128*40 bf16 = 20480 B
    float* Bs = smbuf + (2*TILEA*2)/4;                   // after 20480 B
    int tid  = threadIdx.x;
    int warp = tid >> 5, lane = tid & 31;
    int wm = warp >> 1, wn = warp & 1;
    int g = lane >> 2, t = lane & 3;
    int m0 = blockIdx.y * TBM;
    int n0 = blockIdx.x * TBN;
    int lr = tid >> 3, lc = (tid & 7) << 2;       // W fill
    int ar = tid >> 1, ac = (tid & 1) * 16;       // A fill: 2 chunks/row-pair... see below

    float acc[2][8][4] = {};
    const int nk = K >> 5;

    // A fill: 128 rows x 32 bf16 cols = 512 x 16B-chunks(8 bf16); 256 thr x 2
    #pragma unroll
    for (int i = 0; i < 2; i++) {
        int idx = tid + i * 256;
        int r = idx >> 2, c8 = (idx & 3) * 8;
        cp_async16(AsB + r*TA + c8, A + (size_t)(m0 + r) * K + c8);
    }
    #pragma unroll
    for (int i = 0; i < 4; i++) {
        int r = lr + i * 32;
        cp_async16(&Bs[r*36 + lc], W + (size_t)(n0 + r) * K + lc);
    }
    asm volatile("cp.async.commit_group;");

    for (int kt = 0; kt < nk; kt++) {
        int abuf = (kt & 1) * TILEA;
        int bbuf = (kt & 1) * TILE;
        if (kt + 1 < nk) {
            int nab = ((kt + 1) & 1) * TILEA;
            int nbb = ((kt + 1) & 1) * TILE;
            int ko = (kt + 1) << 5;
            #pragma unroll
            for (int i = 0; i < 2; i++) {
                int idx = tid + i * 256;
                int r = idx >> 2, c8 = (idx & 3) * 8;
                cp_async16(AsB + nab + r*TA + c8, A + (size_t)(m0 + r) * K + ko + c8);
            }
            #pragma unroll
            for (int i = 0; i < 4; i++) {
                int r = lr + i * 32;
                cp_async16(&Bs[nbb + r*36 + lc], W + (size_t)(n0 + r) * K + ko + lc);
            }
            asm volatile("cp.async.commit_group;");
            asm volatile("cp.async.wait_group 1;");
        } else {
            asm volatile("cp.async.wait_group 0;");
        }
        __syncthreads();
        #pragma unroll
        for (int kk = 0; kk < 32; kk += 8) {
            uint32_t afrag[2][4];
            #pragma unroll
            for (int mi = 0; mi < 2; mi++) {
                int r = wm * 32 + mi * 16;
                afrag[mi][0] = FU(BF2F(AsB[abuf + (r + g    )*TA + kk + t    ]));
                afrag[mi][1] = FU(BF2F(AsB[abuf + (r + g + 8)*TA + kk + t    ]));
                afrag[mi][2] = FU(BF2F(AsB[abuf + (r + g    )*TA + kk + t + 4]));
                afrag[mi][3] = FU(BF2F(AsB[abuf + (r + g + 8)*TA + kk + t + 4]));
            }
            #pragma unroll
            for (int ni = 0; ni < 8; ni++) {
                int c = wn * 64 + ni * 8;
                uint32_t b0 = FU(Bs[bbuf + (c + g)*36 + kk + t    ]);
                uint32_t b1 = FU(Bs[bbuf + (c + g)*36 + kk + t + 4]);
                mma8(acc[0][ni], afrag[0], b0, b1);
                mma8(acc[1][ni], afrag[1], b0, b1);
            }
        }
        __syncthreads();
    }

    #pragma unroll
    for (int mi = 0; mi < 2; mi++) {
        #pragma unroll
        for (int ni = 0; ni < 8; ni++) {
            int r = m0 + wm * 32 + mi * 16 + g;
            int c = n0 + wn * 64 + ni * 8 + 2 * t;
            float bv0 = bias[c], bv1 = bias[c + 1];
            #pragma unroll
            for (int half = 0; half < 2; half++) {
                int row = r + half * 8;
                float v0 = acc[mi][ni][half*2 + 0] + bv0;
                float v1 = acc[mi][ni][half*2 + 1] + bv1;
                const float2 rr = *(const float2*)(res + (size_t)row * N + c);
                v0 += rr.x; v1 += rr.y;
                *(float2*)(out + (size_t)row * N + c) = make_float2(v0, v1);
            }
        }
    }
}

// ---------------- small SIMT GEMM (q2/k2) ------------------------------------
#define BM 64
#define BN 64
#define BK 16
__global__ void k_gemm(const float* __restrict__ A, const float* __restrict__ W,
                       const float* __restrict__ bias, float* __restrict__ out,
                       int M, int N, int K)
{
    __shared__ float As[BK][BM];
    __shared__ float Bs[BK][BN];
    int tid = threadIdx.x;
    int tx = tid & 15, ty = tid >> 4;
    int m0 = blockIdx.y * BM, n0 = blockIdx.x * BN;
    int lr = tid >> 2;
    int lk = (tid & 3) * 4;
    float acc[4][4] = {};
    for (int k0 = 0; k0 < K; k0 += BK) {
        float4 a4 = *(const float4*)(A + (size_t)(m0 + lr) * K + k0 + lk);
        float4 b4 = *(const float4*)(W + (size_t)(n0 + lr) * K + k0 + lk);
        As[lk+0][lr] = a4.x; As[lk+1][lr] = a4.y; As[lk+2][lr] = a4.z; As[lk+3][lr] = a4.w;
        Bs[lk+0][lr] = b4.x; Bs[lk+1][lr] = b4.y; Bs[lk+2][lr] = b4.z; Bs[lk+3][lr] = b4.w;
        __syncthreads();
        #pragma unroll
        for (int k = 0; k < BK; k++) {
            float4 ra = *(const float4*)&As[k][ty*4];
            float4 rb = *(const float4*)&Bs[k][tx*4];
            float av[4] = {ra.x, ra.y, ra.z, ra.w};
            float bv[4] = {rb.x, rb.y, rb.z, rb.w};
            #pragma unroll
            for (int i = 0; i < 4; i++)
                #pragma unroll
                for (int j = 0; j < 4; j++)
                    acc[i][j] += av[i] * bv[j];
        }
        __syncthreads();
    }
    #pragma unroll
    for (int i = 0; i < 4; i++) {
        int m = m0 + ty*4 + i;
        #pragma unroll
        for (int j = 0; j < 4; j++) {
            int n = n0 + tx*4 + j;
            out[(size_t)m * N + n] = acc[i][j] + bias[n];
        }
    }
}

// ============== attention v4 (R14-proven) + bf16 output ======================
#define AQS 36
#define AVS 132
#define APW 68
__global__ void __launch_bounds__(128, 3)
k_attn_mma()
{
    extern __shared__ float sm[];
    float* Qs = sm;
    float* Ks = sm + 4608;
    float* VT = sm + 9216;
    float* Pb = sm;

    int n = blockIdx.x >> 2, h = blockIdx.x & 3;
    int tid = threadIdx.x;
    int warp = tid >> 5, lane = tid & 31;
    int g = lane >> 2, t = lane & 3;
    int m0 = warp * 32;
    const __nv_bfloat16* base = g_qkvb + (size_t)n * NP * 3 * DD;

    for (int idx = tid; idx < NP*4; idx += 128) {
        int j = idx >> 2, dc = (idx & 3) * 8;
        uint4 qv = *(const uint4*)(base + j*384 +       h*32 + dc);
        uint4 kv = *(const uint4*)(base + j*384 + 128 + h*32 + dc);
        uint4 vv = *(const uint4*)(base + j*384 + 256 + h*32 + dc);
        float2 q0 = __bfloat1622float2(*(__nv_bfloat162*)&qv.x);
        float2 q1 = __bfloat1622float2(*(__nv_bfloat162*)&qv.y);
        float2 q2 = __bfloat1622float2(*(__nv_bfloat162*)&qv.z);
        float2 q3 = __bfloat1622float2(*(__nv_bfloat162*)&qv.w);
        *(float4*)&Qs[j*AQS + dc    ] = make_float4(q0.x, q0.y, q1.x, q1.y);
        *(float4*)&Qs[j*AQS + dc + 4] = make_float4(q2.x, q2.y, q3.x, q3.y);
        float2 k0 = __bfloat1622float2(*(__nv_bfloat162*)&kv.x);
        float2 k1 = __bfloat1622float2(*(__nv_bfloat162*)&kv.y);
        float2 k2 = __bfloat1622float2(*(__nv_bfloat162*)&kv.z);
        float2 k3 = __bfloat1622float2(*(__nv_bfloat162*)&kv.w);
        *(float4*)&Ks[j*AQS + dc    ] = make_float4(k0.x, k0.y, k1.x, k1.y);
        *(float4*)&Ks[j*AQS + dc + 4] = make_float4(k2.x, k2.y, k3.x, k3.y);
        float2 v0 = __bfloat1622float2(*(__nv_bfloat162*)&vv.x);
        float2 v1 = __bfloat1622float2(*(__nv_bfloat162*)&vv.y);
        float2 v2 = __bfloat1622float2(*(__nv_bfloat162*)&vv.z);
        float2 v3 = __bfloat1622float2(*(__nv_bfloat162*)&vv.w);
        VT[(dc    )*AVS + j] = v0.x;  VT[(dc + 1)*AVS + j] = v0.y;
        VT[(dc + 2)*AVS + j] = v1.x;  VT[(dc + 3)*AVS + j] = v1.y;
        VT[(dc + 4)*AVS + j] = v2.x;  VT[(dc + 5)*AVS + j] = v2.y;
        VT[(dc + 6)*AVS + j] = v3.x;  VT[(dc + 7)*AVS + j] = v3.y;
    }
    __syncthreads();

    float s[2][16][4] = {};
    #pragma unroll
    for (int kk = 0; kk < 32; kk += 8) {
        uint32_t afrag[2][4];
        #pragma unroll
        for (int mi = 0; mi < 2; mi++) {
            int r = m0 + mi * 16;
            afrag[mi][0] = FU(Qs[(r + g    )*AQS + kk + t    ]);
            afrag[mi][1] = FU(Qs[(r + g + 8)*AQS + kk + t    ]);
            afrag[mi][2] = FU(Qs[(r + g    )*AQS + kk + t + 4]);
            afrag[mi][3] = FU(Qs[(r + g + 8)*AQS + kk + t + 4]);
        }
        #pragma unroll
        for (int ni = 0; ni < 16; ni++) {
            int c = ni * 8;
            uint32_t b0 = FU(Ks[(c + g)*AQS + kk + t    ]);
            uint32_t b1 = FU(Ks[(c + g)*AQS + kk + t + 4]);
            mma8(s[0][ni], afrag[0], b0, b1);
            mma8(s[1][ni], afrag[1], b0, b1);
        }
    }
    __syncthreads();

    const float scale = 0.17677669529663687f;
    float mx[2][2] = {{-INFINITY,-INFINITY},{-INFINITY,-INFINITY}};
    #pragma unroll
    for (int mi = 0; mi < 2; mi++)
        #pragma unroll
        for (int ni = 0; ni < 16; ni++) {
            #pragma unroll
            for (int q = 0; q < 4; q++) s[mi][ni][q] *= scale;
            mx[mi][0] = fmaxf(mx[mi][0], fmaxf(s[mi][ni][0], s[mi][ni][1]));
            mx[mi][1] = fmaxf(mx[mi][1], fmaxf(s[mi][ni][2], s[mi][ni][3]));
        }
    #pragma unroll
    for (int mi = 0; mi < 2; mi++)
        #pragma unroll
        for (int hf = 0; hf < 2; hf++) {
            mx[mi][hf] = fmaxf(mx[mi][hf], __shfl_xor_sync(0xffffffffu, mx[mi][hf], 1));
            mx[mi][hf] = fmaxf(mx[mi][hf], __shfl_xor_sync(0xffffffffu, mx[mi][hf], 2));
        }
    float sum[2][2] = {};
    #pragma unroll
    for (int mi = 0; mi < 2; mi++)
        #pragma unroll
        for (int ni = 0; ni < 16; ni++) {
            s[mi][ni][0] = __expf(s[mi][ni][0] - mx[mi][0]);
            s[mi][ni][1] = __expf(s[mi][ni][1] - mx[mi][0]);
            s[mi][ni][2] = __expf(s[mi][ni][2] - mx[mi][1]);
            s[mi][ni][3] = __expf(s[mi][ni][3] - mx[mi][1]);
            sum[mi][0] += s[mi][ni][0] + s[mi][ni][1];
            sum[mi][1] += s[mi][ni][2] + s[mi][ni][3];
        }
    float inv[2][2];
    #pragma unroll
    for (int mi = 0; mi < 2; mi++)
        #pragma unroll
        for (int hf = 0; hf < 2; hf++) {
            float ss = sum[mi][hf];
            ss += __shfl_xor_sync(0xffffffffu, ss, 1);
            ss += __shfl_xor_sync(0xffffffffu, ss, 2);
            inv[mi][hf] = 1.f / ss;
        }

    float* Pw = Pb + warp * (32 * APW);
    float o[2][4][4] = {};
    #pragma unroll
    for (int hf = 0; hf < 2; hf++) {
        #pragma unroll
        for (int mi = 0; mi < 2; mi++) {
            int lr = mi * 16 + g;
            #pragma unroll
            for (int ni = 0; ni < 8; ni++) {
                int c = ni * 8 + 2 * t;
                Pw[ lr      *APW + c    ] = s[mi][hf*8 + ni][0];
                Pw[ lr      *APW + c + 1] = s[mi][hf*8 + ni][1];
                Pw[(lr + 8) *APW + c    ] = s[mi][hf*8 + ni][2];
                Pw[(lr + 8) *APW + c + 1] = s[mi][hf*8 + ni][3];
            }
        }
        __syncwarp();
        #pragma unroll
        for (int kk = 0; kk < 64; kk += 8) {
            uint32_t afrag[2][4];
            #pragma unroll
            for (int mi = 0; mi < 2; mi++) {
                int lr = mi * 16;
                afrag[mi][0] = FU(Pw[(lr + g    )*APW + kk + t    ]);
                afrag[mi][1] = FU(Pw[(lr + g + 8)*APW + kk + t    ]);
                afrag[mi][2] = FU(Pw[(lr + g    )*APW + kk + t + 4]);
                afrag[mi][3] = FU(Pw[(lr + g + 8)*APW + kk + t + 4]);
            }
            int j0 = hf*64 + kk + t, j1 = hf*64 + kk + t + 4;
            #pragma unroll
            for (int ni = 0; ni < 4; ni++) {
                int c = ni * 8;
                uint32_t b0 = FU(VT[(c + g)*AVS + j0]);
                uint32_t b1 = FU(VT[(c + g)*AVS + j1]);
                mma8(o[0][ni], afrag[0], b0, b1);
                mma8(o[1][ni], afrag[1], b0, b1);
            }
        }
        __syncwarp();
    }

    #pragma unroll
    for (int mi = 0; mi < 2; mi++) {
        int r0 = n*NP + m0 + mi * 16 + g;
        #pragma unroll
        for (int ni = 0; ni < 4; ni++) {
            int d = ni * 8 + 2 * t;
            *(__nv_bfloat162*)(g_ob + (size_t) r0      *DD + h*32 + d) =
                __floats2bfloat162_rn(o[mi][ni][0]*inv[mi][0], o[mi][ni][1]*inv[mi][0]);
            *(__nv_bfloat162*)(g_ob + (size_t)(r0 + 8) *DD + h*32 + d) =
                __floats2bfloat162_rn(o[mi][ni][2]*inv[mi][1], o[mi][ni][3]*inv[mi][1]);
        }
    }
}

// ---------------- mean over Np -----------------------------------------------
__global__ void k_mean()
{
    int n = blockIdx.x, d = threadIdx.x;
    float s = 0.f;
    for (int p = 0; p < NP; p++) s += g_Htemp[((size_t)n*NP + p)*DD + d];
    g_Hs[n*DD + d] = s * (1.f/128.f);
}

// ---------------- W_att = gat_w[h]^T @ att{src,dst}[h] -----------------------
__global__ void k_watt(const float* __restrict__ gw, const float* __restrict__ asv,
                       const float* __restrict__ adv)
{
    int idx = blockIdx.x * 256 + threadIdx.x;
    int r = idx >> 7, d = idx & 127;
    int h = r & 3;
    const float* att = (r < 4) ? asv : adv;
    float s = 0.f;
    for (int f = 0; f < 128; f++)
        s += att[h*FF + f] * gw[h*FF*DD + f*DD + d];
    g_watt[r*DD + d] = s;
}

// ---------------- graph adjacency --------------------------------------------
__global__ void k_graph(const float* __restrict__ adj)
{
    __shared__ float k2s[CC*DK];
    __shared__ float Amat[CC*65];
    int b = blockIdx.x, c = threadIdx.x;
    for (int idx = c; idx < CC*DK; idx += 64) k2s[idx] = g_k2[(size_t)b*CC*DK + idx];
    __syncthreads();
    float qreg[DK];
    #pragma unroll
    for (int d = 0; d < DK; d++) qreg[d] = g_q2[(size_t)b*CC*DK + c*DK + d];
    for (int e = 0; e < CC; e++) {
        float a = 0.f;
        #pragma unroll
        for (int d = 0; d < DK; d++) a += qreg[d] * k2s[e*DK + d];
        Amat[c*65 + e] = tanhf(a * 0.125f) + adj[c*CC + e];
    }
    for (int e = 0; e < CC; e++) g_mask[(size_t)b*CC*CC + c*CC + e] = 0.f;
    for (int kk = 0; kk < 8; kk++) {
        float best = -INFINITY; int bi = 0;
        for (int e = 0; e < CC; e++) {
            float v = Amat[c*65 + e];
            if (v > best) { best = v; bi = e; }
        }
        if (bi != c && best != 0.f) g_mask[(size_t)b*CC*CC + c*CC + bi] = 1.f;
        Amat[c*65 + bi] = -INFINITY;
    }
}

// ============== GAT v2 (R12-proven, bf16 xh) =================================
#define XST 68
#define AST 68
#define OST 132
#define GU  8704
__global__ void __launch_bounds__(256)
k_gat(const float* __restrict__ gbias, const float* __restrict__ sg,
      const float* __restrict__ sb, float* __restrict__ out)
{
    extern __shared__ float sm[];
    float* U   = sm;
    float* Awt = sm + GU;
    float* Asv = sm + GU + 4352;
    float* Adv = sm + GU + 4416;
    float* XhT = U;
    float* Os  = U;

    int b = blockIdx.x >> 7, p = blockIdx.x & 127;
    int tid = threadIdx.x, w = tid >> 5, lane = tid & 31;
    int wm = w >> 2, wn = w & 3;
    int g = lane >> 2, t4 = lane & 3;

    float mr0[8], mr1[8];
    #pragma unroll
    for (int i = 0; i < 8; i++) {
        int t = w*8 + i;
        mr0[i] = g_mask[(size_t)b*CC*CC + lane*CC + t];
        mr1[i] = g_mask[(size_t)b*CC*CC + (lane+32)*CC + t];
    }

    float acc[2][4][4] = {};
    for (int h = 0; h < HS; h++) {
        __syncthreads();
        for (int idx = tid; idx < CC*FF/2; idx += 256) {
            int s = idx >> 6, fp = idx & 63;
            const __nv_bfloat162 v2 = *(const __nv_bfloat162*)
                (g_xhb + (size_t)(((b*CC + s)*NP + p))*(HS*FF) + h*FF + 2*fp);
            float2 vf = __bfloat1622float2(v2);
            XhT[(2*fp    )*XST + s] = vf.x;
            XhT[(2*fp + 1)*XST + s] = vf.y;
        }
        if (tid < 64)            Asv[tid]      = g_asrc[(((b*4 + h)*128 + p)*64) + tid];
        else if (tid < 128)      Adv[tid - 64] = g_adst[(((b*4 + h)*128 + p)*64) + tid - 64];
        __syncthreads();

        #pragma unroll
        for (int i = 0; i < 8; i++) {
            int t = w*8 + i;
            float adt = Adv[t];
            float e0 = Asv[lane]      + adt; e0 = e0 > 0.f ? e0 : 0.2f*e0;
            float e1 = Asv[lane + 32] + adt; e1 = e1 > 0.f ? e1 : 0.2f*e1;
            float me = fmaxf(mr0[i] > 0.5f ? e0 : GAT_NEG, mr1[i] > 0.5f ? e1 : GAT_NEG);
            #pragma unroll
            for (int o = 16; o; o >>= 1) me = fmaxf(me, __shfl_xor_sync(0xffffffffu, me, o));
            float w0 = (mr0[i] > 0.5f) ? __expf(e0 - me) : 0.f;
            float w1 = (mr1[i] > 0.5f) ? __expf(e1 - me) : 0.f;
            float ws = w0 + w1;
            #pragma unroll
            for (int o = 16; o; o >>= 1) ws += __shfl_xor_sync(0xffffffffu, ws, o);
            float inv = ws > 0.f ? 1.f / ws : 0.f;
            Awt[t*AST + lane]      = w0 * inv;
            Awt[t*AST + lane + 32] = w1 * inv;
        }
        __syncthreads();

        #pragma unroll
        for (int kk = 0; kk < CC; kk += 8) {
            uint32_t afrag[2][4];
            #pragma unroll
            for (int mi = 0; mi < 2; mi++) {
                int r = wm * 32 + mi * 16;
                afrag[mi][0] = FU(Awt[(r + g    )*AST + kk + t4    ]);
                afrag[mi][1] = FU(Awt[(r + g + 8)*AST + kk + t4    ]);
                afrag[mi][2] = FU(Awt[(r + g    )*AST + kk + t4 + 4]);
                afrag[mi][3] = FU(Awt[(r + g + 8)*AST + kk + t4 + 4]);
            }
            #pragma unroll
            for (int ni = 0; ni < 4; ni++) {
                int c = wn * 32 + ni * 8;
                uint32_t b0 = FU(XhT[(c + g)*XST + kk + t4    ]);
                uint32_t b1 = FU(XhT[(c + g)*XST + kk + t4 + 4]);
                mma8(acc[0][ni], afrag[0], b0, b1);
                mma8(acc[1][ni], afrag[1], b0, b1);
            }
        }
    }

    __syncthreads();
    for (int idx = tid; idx < CC*DD; idx += 256) {
        int r = idx >> 7, f = idx & 127;
        Os[r*OST + f] = g_Htemp[(((size_t)(b*CC + r))*NP + p)*DD + f] + gbias[f];
    }
    __syncthreads();
    #pragma unroll
    for (int mi = 0; mi < 2; mi++)
        #pragma unroll
        for (int ni = 0; ni < 4; ni++) {
            int r = wm*32 + mi*16 + g;
            int c = wn*32 + ni*8 + 2*t4;
            #pragma unroll
            for (int half = 0; half < 2; half++) {
                int row = r + half*8;
                Os[row*OST + c    ] += acc[mi][ni][half*2 + 0] * 0.25f;
                Os[row*OST + c + 1] += acc[mi][ni][half*2 + 1] * 0.25f;
            }
        }
    __syncthreads();
    {
        float4 g4 = ((const float4*)sg)[lane];
        float4 b4 = ((const float4*)sb)[lane];
        for (int r = w; r < CC; r += 8) {
            float4 v = *(float4*)&Os[r*OST + lane*4];
            float s1 = v.x + v.y + v.z + v.w;
            #pragma unroll
            for (int o = 16; o; o >>= 1) s1 += __shfl_xor_sync(0xffffffffu, s1, o);
            float mean = s1 * (1.f/128.f);
            float dx=v.x-mean, dy=v.y-mean, dz=v.z-mean, dw=v.w-mean;
            float q = dx*dx+dy*dy+dz*dz+dw*dw;
            #pragma unroll
            for (int o = 16; o; o >>= 1) q += __shfl_xor_sync(0xffffffffu, q, o);
            float inv = rsqrtf(q * (1.f/128.f) + 1e-5f);
            float4 ov;
            ov.x = dx*inv*g4.x + b4.x; ov.y = dy*inv*g4.y + b4.y;
            ov.z = dz*inv*g4.z + b4.z; ov.w = dw*inv*g4.w + b4.w;
            ((float4*)(out + (((size_t)(b*CC + r))*NP + p)*DD))[lane] = ov;
        }
    }
}

// ---------------- host launch -------------------------------------------------
extern "C" void kernel_launch(void* const* d_in, const int* in_sizes, int n_in,
                              void* d_out, int out_size)
{
    const float* H_in      = (const float*)d_in[0];
    const float* static_adj= (const float*)d_in[1];
    const float* attn_in_w = (const float*)d_in[2];
    const float* attn_in_b = (const float*)d_in[3];
    const float* attn_out_w= (const float*)d_in[4];
    const float* attn_out_b= (const float*)d_in[5];
    const float* ln1_g     = (const float*)d_in[6];
    const float* ln1_b     = (const float*)d_in[7];
    const float* ln2_g     = (const float*)d_in[8];
    const float* ln2_b     = (const float*)d_in[9];
    const float* ff1_w     = (const float*)d_in[10];
    const float* ff1_b     = (const float*)d_in[11];
    const float* ff2_w     = (const float*)d_in[12];
    const float* ff2_b     = (const float*)d_in[13];
    const float* tnorm_g   = (const float*)d_in[14];
    const float* tnorm_b   = (const float*)d_in[15];
    const float* q_w       = (const float*)d_in[16];
    const float* q_b       = (const float*)d_in[17];
    const float* k_w       = (const float*)d_in[18];
    const float* k_b       = (const float*)d_in[19];
    const float* gat_w     = (const float*)d_in[20];
    const float* gat_att_src = (const float*)d_in[21];
    const float* gat_att_dst = (const float*)d_in[22];
    const float* gat_bias  = (const float*)d_in[23];
    const float* snorm_g   = (const float*)d_in[24];
    const float* snorm_b   = (const float*)d_in[25];

    float *h_, *x_, *Htemp_, *Hs_, *q2_, *k2_;
    __nv_bfloat16 *xhb_, *qkvb_, *ob_, *ffb_;
    cudaGetSymbolAddress((void**)&h_,     g_h);
    cudaGetSymbolAddress((void**)&qkvb_,  g_qkvb);
    cudaGetSymbolAddress((void**)&ob_,    g_ob);
    cudaGetSymbolAddress((void**)&x_,     g_x);
    cudaGetSymbolAddress((void**)&ffb_,   g_ffb);
    cudaGetSymbolAddress((void**)&Htemp_, g_Htemp);
    cudaGetSymbolAddress((void**)&xhb_,   g_xhb);
    cudaGetSymbolAddress((void**)&Hs_,    g_Hs);
    cudaGetSymbolAddress((void**)&q2_,    g_q2);
    cudaGetSymbolAddress((void**)&k2_,    g_k2);

    const int mma_smem  = 4 * TILE * 4;                 // 73728
    const int mmaA_smem = 2*TILEA*2 + 2*TILE*4;         // 20480 + 36864 = 57344
    const int attn_smem = 13440 * 4;                    // 53760
    const int gat_smem  = (GU + 4352 + 128) * 4;        // 52736
    cudaFuncSetAttribute(k_mma_bf,  cudaFuncAttributeMaxDynamicSharedMemorySize, mma_smem);
    cudaFuncSetAttribute(k_mma_bfA, cudaFuncAttributeMaxDynamicSharedMemorySize, mmaA_smem);
    cudaFuncSetAttribute(k_attn_mma, cudaFuncAttributeMaxDynamicSharedMemorySize, attn_smem);
    cudaFuncSetAttribute(k_gat,  cudaFuncAttributeMaxDynamicSharedMemorySize, gat_smem);

    // 0) W_att vectors
    k_watt<<<4, 256>>>(gat_w, gat_att_src, gat_att_dst);
    // 1) h = ln1(x0)
    k_ln<<<NTOK/8, 256>>>(H_in, nullptr, ln1_g, ln1_b, h_);
    // 2) qkv = h @ Wqkv^T + b  (bf16 out)
    k_mma_bf<<<dim3(3, NTOK/TBM), 256, mma_smem>>>(h_, attn_in_w, attn_in_b, qkvb_,
                                                   384, 128, 0);
    // 3) temporal attention (bf16 in/out)
    k_attn_mma<<<NSEQ*HT, 128, attn_smem>>>();
    // 4) x1 = x0 + o @ Wout^T + b  (bf16 A)
    k_mma_bfA<<<dim3(1, NTOK/TBM), 256, mmaA_smem>>>(ob_, attn_out_w, attn_out_b,
                                                     H_in, x_, 128, 128);
    // 5) h = ln2(x1)
    k_ln<<<NTOK/8, 256>>>(x_, nullptr, ln2_g, ln2_b, h_);
    // 6) ff = relu(h @ W1^T + b1)  (bf16 out)
    k_mma_bf<<<dim3(4, NTOK/TBM), 256, mma_smem>>>(h_, ff1_w, ff1_b, ffb_,
                                                   512, 128, 1);
    // 7) x2 = x1 + ff @ W2^T + b2  (bf16 A)
    k_mma_bfA<<<dim3(1, NTOK/TBM), 256, mmaA_smem>>>(ffb_, ff2_w, ff2_b,
                                                     x_, x_, 128, 512);
    // 8) H_temp = ln(x0 + x2, tnorm) + fused asrc/adst
    k_ln_asd<<<NTOK/8, 256>>>(x_, H_in, tnorm_g, tnorm_b, Htemp_);
    // 9) xh = H_temp @ gat_w^T  (bf16 out)
    k_mma_bf<<<dim3(4, NTOK/TBM), 256, mma_smem>>>(Htemp_, gat_w, nullptr, xhb_,
                                                   512, 128, 0);
    // 10) Hs = mean_p(H_temp)
    k_mean<<<NSEQ, 128>>>();
    // 11) q2, k2
    k_gemm<<<dim3(1, NSEQ/BM), 256>>>(Hs_, q_w, q_b, q2_, NSEQ, 64, 128);
    k_gemm<<<dim3(1, NSEQ/BM), 256>>>(Hs_, k_w, k_b, k2_, NSEQ, 64, 128);
    // 12) adjacency / top-k / mask
    k_graph<<<BB, 64>>>(static_adj);
    // 13) GAT v2 + snorm LN -> output
    k_gat<<<BB*NP, 256, gat_smem>>>(gat_bias, snorm_g, snorm_b, (float*)d_out);
}

// round 16
// speedup vs baseline: 1.2012x; 1.0045x over previous
#include <cuda_runtime.h>
#include <cuda_bf16.h>
#include <math.h>
#include <stdint.h>

#define BB   16
#define CC   64
#define NP   128
#define DD   128
#define HT   4
#define DH   32
#define HS   4
#define FF   128
#define DK   64
#define NTOK (BB*CC*NP)      // 131072
#define NSEQ (BB*CC)         // 1024
#define GAT_NEG -1e30f

// ---------------- scratch ----------------------------------------------------
__device__ __nv_bfloat16 g_hb[NTOK*DD];
__device__ __nv_bfloat16 g_qkvb[(size_t)NTOK*3*DD];
__device__ __nv_bfloat16 g_ob[NTOK*DD];
__device__ float g_x[NTOK*DD];
__device__ __nv_bfloat16 g_ffb[(size_t)NTOK*4*DD];
__device__ float g_Htemp[NTOK*DD];
__device__ __nv_bfloat16 g_xhb[(size_t)NTOK*HS*FF];
__device__ float g_Hs[NSEQ*DD];
__device__ float g_q2[NSEQ*DK];
__device__ float g_k2[NSEQ*DK];
__device__ float g_mask[BB*CC*CC];
__device__ float g_watt[8*DD];
__device__ float g_asrc[BB*HS*NP*CC];
__device__ float g_adst[BB*HS*NP*CC];

// ---------------- helpers ----------------------------------------------------
__device__ __forceinline__ void mma8(float c[4], const uint32_t a[4],
                                     uint32_t b0, uint32_t b1) {
    asm volatile(
        "mma.sync.aligned.m16n8k8.row.col.f32.tf32.tf32.f32 "
        "{%0,%1,%2,%3}, {%4,%5,%6,%7}, {%8,%9}, {%0,%1,%2,%3};"
        : "+f"(c[0]), "+f"(c[1]), "+f"(c[2]), "+f"(c[3])
        : "r"(a[0]), "r"(a[1]), "r"(a[2]), "r"(a[3]), "r"(b0), "r"(b1));
}
__device__ __forceinline__ void cp_async16(void* smem, const void* gmem) {
    uint32_t s = (uint32_t)__cvta_generic_to_shared(smem);
    asm volatile("cp.async.cg.shared.global [%0], [%1], 16;" :: "r"(s), "l"(gmem));
}
#define FU(x) __float_as_uint(x)
#define BF2F(x) __bfloat162float(x)

// ---------------- LayerNorm: warp per row, bf16 out (ln1/ln2) ----------------
__global__ void k_ln(const float* __restrict__ x,
                     const float* __restrict__ gw, const float* __restrict__ bw,
                     __nv_bfloat16* __restrict__ out)
{
    int row  = blockIdx.x * 8 + (threadIdx.x >> 5);
    int lane = threadIdx.x & 31;
    float4 v = ((const float4*)(x + (size_t)row * DD))[lane];
    float s = v.x + v.y + v.z + v.w;
    #pragma unroll
    for (int o = 16; o; o >>= 1) s += __shfl_xor_sync(0xffffffffu, s, o);
    float mean = s * (1.f/128.f);
    float dx = v.x-mean, dy = v.y-mean, dz = v.z-mean, dw = v.w-mean;
    float q = dx*dx + dy*dy + dz*dz + dw*dw;
    #pragma unroll
    for (int o = 16; o; o >>= 1) q += __shfl_xor_sync(0xffffffffu, q, o);
    float inv = rsqrtf(q * (1.f/128.f) + 1e-5f);
    float4 g4 = ((const float4*)gw)[lane];
    float4 b4 = ((const float4*)bw)[lane];
    __nv_bfloat162 b01 = __floats2bfloat162_rn(dx*inv*g4.x + b4.x, dy*inv*g4.y + b4.y);
    __nv_bfloat162 b23 = __floats2bfloat162_rn(dz*inv*g4.z + b4.z, dw*inv*g4.w + b4.w);
    uint2 st;
    st.x = *(uint32_t*)&b01;
    st.y = *(uint32_t*)&b23;
    *(uint2*)(out + (size_t)row * DD + lane*4) = st;
}

// -------- tnorm LN + fused asrc/adst (R14-proven; fp32 out) ------------------
__global__ void k_ln_asd(const float* __restrict__ x, const float* __restrict__ add,
                         const float* __restrict__ gw, const float* __restrict__ bw,
                         float* __restrict__ out)
{
    __shared__ float4 W4[8][32];
    int tid = threadIdx.x;
    int warp = tid >> 5, lane = tid & 31;
    for (int i = tid; i < 256; i += 256)
        ((float4*)W4)[i] = ((const float4*)g_watt)[i];
    __syncthreads();

    int row = blockIdx.x * 8 + warp;
    float4 v = ((const float4*)(x + (size_t)row * DD))[lane];
    float4 a = ((const float4*)(add + (size_t)row * DD))[lane];
    v.x += a.x; v.y += a.y; v.z += a.z; v.w += a.w;
    float s = v.x + v.y + v.z + v.w;
    #pragma unroll
    for (int o = 16; o; o >>= 1) s += __shfl_xor_sync(0xffffffffu, s, o);
    float mean = s * (1.f/128.f);
    float dx = v.x-mean, dy = v.y-mean, dz = v.z-mean, dw = v.w-mean;
    float q = dx*dx + dy*dy + dz*dz + dw*dw;
    #pragma unroll
    for (int o = 16; o; o >>= 1) q += __shfl_xor_sync(0xffffffffu, q, o);
    float inv = rsqrtf(q * (1.f/128.f) + 1e-5f);
    float4 g4 = ((const float4*)gw)[lane];
    float4 b4 = ((const float4*)bw)[lane];
    float4 o4;
    o4.x = dx*inv*g4.x + b4.x;  o4.y = dy*inv*g4.y + b4.y;
    o4.z = dz*inv*g4.z + b4.z;  o4.w = dw*inv*g4.w + b4.w;
    ((float4*)(out + (size_t)row * DD))[lane] = o4;

    int p = row & 127, bs = row >> 7;
    int sidx = bs & 63, b = bs >> 6;
    #pragma unroll
    for (int r = 0; r < 8; r++) {
        float4 w = W4[r][lane];
        float d = o4.x*w.x + o4.y*w.y + o4.z*w.z + o4.w*w.w;
        #pragma unroll
        for (int o = 16; o; o >>= 1) d += __shfl_xor_sync(0xffffffffu, d, o);
        if (lane == 0) {
            int h = r & 3;
            float* dst = (r < 4) ? g_asrc : g_adst;
            dst[(((b*4 + h)*128 + p)*64) + sidx] = d;
        }
    }
}

// ---------------- tf32 GEMM -> bf16 out (fp32 A) -----------------------------
#define TBM 128
#define TBN 128
#define TILE (128*36)
__global__ void __launch_bounds__(256)
k_mma_bf(const float* __restrict__ A, const float* __restrict__ W,
         const float* __restrict__ bias, __nv_bfloat16* __restrict__ out,
         int N, int K, int relu)
{
    extern __shared__ float smbuf[];
    float* As = smbuf;
    float* Bs = smbuf + 2*TILE;
    int tid  = threadIdx.x;
    int warp = tid >> 5, lane = tid & 31;
    int wm = warp >> 1, wn = warp & 1;
    int g = lane >> 2, t = lane & 3;
    int m0 = blockIdx.y * TBM;
    int n0 = blockIdx.x * TBN;
    int lr = tid >> 3, lc = (tid & 7) << 2;

    float acc[2][8][4] = {};
    const int nk = K >> 5;

    #pragma unroll
    for (int i = 0; i < 4; i++) {
        int r = lr + i * 32;
        cp_async16(&As[r*36 + lc], A + (size_t)(m0 + r) * K + lc);
        cp_async16(&Bs[r*36 + lc], W + (size_t)(n0 + r) * K + lc);
    }
    asm volatile("cp.async.commit_group;");

    for (int kt = 0; kt < nk; kt++) {
        int buf = (kt & 1) * TILE;
        if (kt + 1 < nk) {
            int nb = ((kt + 1) & 1) * TILE;
            int ko = (kt + 1) << 5;
            #pragma unroll
            for (int i = 0; i < 4; i++) {
                int r = lr + i * 32;
                cp_async16(&As[nb + r*36 + lc], A + (size_t)(m0 + r) * K + ko + lc);
                cp_async16(&Bs[nb + r*36 + lc], W + (size_t)(n0 + r) * K + ko + lc);
            }
            asm volatile("cp.async.commit_group;");
            asm volatile("cp.async.wait_group 1;");
        } else {
            asm volatile("cp.async.wait_group 0;");
        }
        __syncthreads();
        #pragma unroll
        for (int kk = 0; kk < 32; kk += 8) {
            uint32_t afrag[2][4];
            #pragma unroll
            for (int mi = 0; mi < 2; mi++) {
                int r = wm * 32 + mi * 16;
                afrag[mi][0] = FU(As[buf + (r + g    )*36 + kk + t    ]);
                afrag[mi][1] = FU(As[buf + (r + g + 8)*36 + kk + t    ]);
                afrag[mi][2] = FU(As[buf + (r + g    )*36 + kk + t + 4]);
                afrag[mi][3] = FU(As[buf + (r + g + 8)*36 + kk + t + 4]);
            }
            #pragma unroll
            for (int ni = 0; ni < 8; ni++) {
                int c = wn * 64 + ni * 8;
                uint32_t b0 = FU(Bs[buf + (c + g)*36 + kk + t    ]);
                uint32_t b1 = FU(Bs[buf + (c + g)*36 + kk + t + 4]);
                mma8(acc[0][ni], afrag[0], b0, b1);
                mma8(acc[1][ni], afrag[1], b0, b1);
            }
        }
        __syncthreads();
    }

    #pragma unroll
    for (int mi = 0; mi < 2; mi++) {
        #pragma unroll
        for (int ni = 0; ni < 8; ni++) {
            int r = m0 + wm * 32 + mi * 16 + g;
            int c = n0 + wn * 64 + ni * 8 + 2 * t;
            float bv0 = bias ? bias[c]     : 0.f;
            float bv1 = bias ? bias[c + 1] : 0.f;
            #pragma unroll
            for (int half = 0; half < 2; half++) {
                int row = r + half * 8;
                float v0 = acc[mi][ni][half*2 + 0] + bv0;
                float v1 = acc[mi][ni][half*2 + 1] + bv1;
                if (relu) { v0 = fmaxf(v0, 0.f); v1 = fmaxf(v1, 0.f); }
                *(__nv_bfloat162*)(out + (size_t)row * N + c) = __floats2bfloat162_rn(v0, v1);
            }
        }
    }
}

// ---------------- tf32 GEMM, bf16 A -> fp32 out (+bias,+res) (R15-proven) ----
#define TA 40
#define TILEA (128*TA)
__global__ void __launch_bounds__(256)
k_mma_bfA(const __nv_bfloat16* __restrict__ A, const float* __restrict__ W,
          const float* __restrict__ bias, const float* __restrict__ res,
          float* __restrict__ out, int N, int K)
{
    extern __shared__ float smbuf[];
    __nv_bfloat16* AsB = (__nv_bfloat16*)smbuf;
    float* Bs = smbuf + (2*TILEA*2)/4;
    int tid  = threadIdx.x;
    int warp = tid >> 5, lane = tid & 31;
    int wm = warp >> 1, wn = warp & 1;
    int g = lane >> 2, t = lane & 3;
    int m0 = blockIdx.y * TBM;
    int n0 = blockIdx.x * TBN;
    int lr = tid >> 3, lc = (tid & 7) << 2;

    float acc[2][8][4] = {};
    const int nk = K >> 5;

    #pragma unroll
    for (int i = 0; i < 2; i++) {
        int idx = tid + i * 256;
        int r = idx >> 2, c8 = (idx & 3) * 8;
        cp_async16(AsB + r*TA + c8, A + (size_t)(m0 + r) * K + c8);
    }
    #pragma unroll
    for (int i = 0; i < 4; i++) {
        int r = lr + i * 32;
        cp_async16(&Bs[r*36 + lc], W + (size_t)(n0 + r) * K + lc);
    }
    asm volatile("cp.async.commit_group;");

    for (int kt = 0; kt < nk; kt++) {
        int abuf = (kt & 1) * TILEA;
        int bbuf = (kt & 1) * TILE;
        if (kt + 1 < nk) {
            int nab = ((kt + 1) & 1) * TILEA;
            int nbb = ((kt + 1) & 1) * TILE;
            int ko = (kt + 1) << 5;
            #pragma unroll
            for (int i = 0; i < 2; i++) {
                int idx = tid + i * 256;
                int r = idx >> 2, c8 = (idx & 3) * 8;
                cp_async16(AsB + nab + r*TA + c8, A + (size_t)(m0 + r) * K + ko + c8);
            }
            #pragma unroll
            for (int i = 0; i < 4; i++) {
                int r = lr + i * 32;
                cp_async16(&Bs[nbb + r*36 + lc], W + (size_t)(n0 + r) * K + ko + lc);
            }
            asm volatile("cp.async.commit_group;");
            asm volatile("cp.async.wait_group 1;");
        } else {
            asm volatile("cp.async.wait_group 0;");
        }
        __syncthreads();
        #pragma unroll
        for (int kk = 0; kk < 32; kk += 8) {
            uint32_t afrag[2][4];
            #pragma unroll
            for (int mi = 0; mi < 2; mi++) {
                int r = wm * 32 + mi * 16;
                afrag[mi][0] = FU(BF2F(AsB[abuf + (r + g    )*TA + kk + t    ]));
                afrag[mi][1] = FU(BF2F(AsB[abuf + (r + g + 8)*TA + kk + t    ]));
                afrag[mi][2] = FU(BF2F(AsB[abuf + (r + g    )*TA + kk + t + 4]));
                afrag[mi][3] = FU(BF2F(AsB[abuf + (r + g + 8)*TA + kk + t + 4]));
            }
            #pragma unroll
            for (int ni = 0; ni < 8; ni++) {
                int c = wn * 64 + ni * 8;
                uint32_t b0 = FU(Bs[bbuf + (c + g)*36 + kk + t    ]);
                uint32_t b1 = FU(Bs[bbuf + (c + g)*36 + kk + t + 4]);
                mma8(acc[0][ni], afrag[0], b0, b1);
                mma8(acc[1][ni], afrag[1], b0, b1);
            }
        }
        __syncthreads();
    }

    #pragma unroll
    for (int mi = 0; mi < 2; mi++) {
        #pragma unroll
        for (int ni = 0; ni < 8; ni++) {
            int r = m0 + wm * 32 + mi * 16 + g;
            int c = n0 + wn * 64 + ni * 8 + 2 * t;
            float bv0 = bias[c], bv1 = bias[c + 1];
            #pragma unroll
            for (int half = 0; half < 2; half++) {
                int row = r + half * 8;
                float v0 = acc[mi][ni][half*2 + 0] + bv0;
                float v1 = acc[mi][ni][half*2 + 1] + bv1;
                const float2 rr = *(const float2*)(res + (size_t)row * N + c);
                v0 += rr.x; v1 += rr.y;
                *(float2*)(out + (size_t)row * N + c) = make_float2(v0, v1);
            }
        }
    }
}

// ---------------- tf32 GEMM, bf16 A -> bf16 out (+bias,+relu) ----------------
__global__ void __launch_bounds__(256)
k_mma_b2b(const __nv_bfloat16* __restrict__ A, const float* __restrict__ W,
          const float* __restrict__ bias, __nv_bfloat16* __restrict__ out,
          int N, int K, int relu)
{
    extern __shared__ float smbuf[];
    __nv_bfloat16* AsB = (__nv_bfloat16*)smbuf;
    float* Bs = smbuf + (2*TILEA*2)/4;
    int tid  = threadIdx.x;
    int warp = tid >> 5, lane = tid & 31;
    int wm = warp >> 1, wn = warp & 1;
    int g = lane >> 2, t = lane & 3;
    int m0 = blockIdx.y * TBM;
    int n0 = blockIdx.x * TBN;
    int lr = tid >> 3, lc = (tid & 7) << 2;

    float acc[2][8][4] = {};
    const int nk = K >> 5;

    #pragma unroll
    for (int i = 0; i < 2; i++) {
        int idx = tid + i * 256;
        int r = idx >> 2, c8 = (idx & 3) * 8;
        cp_async16(AsB + r*TA + c8, A + (size_t)(m0 + r) * K + c8);
    }
    #pragma unroll
    for (int i = 0; i < 4; i++) {
        int r = lr + i * 32;
        cp_async16(&Bs[r*36 + lc], W + (size_t)(n0 + r) * K + lc);
    }
    asm volatile("cp.async.commit_group;");

    for (int kt = 0; kt < nk; kt++) {
        int abuf = (kt & 1) * TILEA;
        int bbuf = (kt & 1) * TILE;
        if (kt + 1 < nk) {
            int nab = ((kt + 1) & 1) * TILEA;
            int nbb = ((kt + 1) & 1) * TILE;
            int ko = (kt + 1) << 5;
            #pragma unroll
            for (int i = 0; i < 2; i++) {
                int idx = tid + i * 256;
                int r = idx >> 2, c8 = (idx & 3) * 8;
                cp_async16(AsB + nab + r*TA + c8, A + (size_t)(m0 + r) * K + ko + c8);
            }
            #pragma unroll
            for (int i = 0; i < 4; i++) {
                int r = lr + i * 32;
                cp_async16(&Bs[nbb + r*36 + lc], W + (size_t)(n0 + r) * K + ko + lc);
            }
            asm volatile("cp.async.commit_group;");
            asm volatile("cp.async.wait_group 1;");
        } else {
            asm volatile("cp.async.wait_group 0;");
        }
        __syncthreads();
        #pragma unroll
        for (int kk = 0; kk < 32; kk += 8) {
            uint32_t afrag[2][4];
            #pragma unroll
            for (int mi = 0; mi < 2; mi++) {
                int r = wm * 32 + mi * 16;
                afrag[mi][0] = FU(BF2F(AsB[abuf + (r + g    )*TA + kk + t    ]));
                afrag[mi][1] = FU(BF2F(AsB[abuf + (r + g + 8)*TA + kk + t    ]));
                afrag[mi][2] = FU(BF2F(AsB[abuf + (r + g    )*TA + kk + t + 4]));
                afrag[mi][3] = FU(BF2F(AsB[abuf + (r + g + 8)*TA + kk + t + 4]));
            }
            #pragma unroll
            for (int ni = 0; ni < 8; ni++) {
                int c = wn * 64 + ni * 8;
                uint32_t b0 = FU(Bs[bbuf + (c + g)*36 + kk + t    ]);
                uint32_t b1 = FU(Bs[bbuf + (c + g)*36 + kk + t + 4]);
                mma8(acc[0][ni], afrag[0], b0, b1);
                mma8(acc[1][ni], afrag[1], b0, b1);
            }
        }
        __syncthreads();
    }

    #pragma unroll
    for (int mi = 0; mi < 2; mi++) {
        #pragma unroll
        for (int ni = 0; ni < 8; ni++) {
            int r = m0 + wm * 32 + mi * 16 + g;
            int c = n0 + wn * 64 + ni * 8 + 2 * t;
            float bv0 = bias[c], bv1 = bias[c + 1];
            #pragma unroll
            for (int half = 0; half < 2; half++) {
                int row = r + half * 8;
                float v0 = acc[mi][ni][half*2 + 0] + bv0;
                float v1 = acc[mi][ni][half*2 + 1] + bv1;
                if (relu) { v0 = fmaxf(v0, 0.f); v1 = fmaxf(v1, 0.f); }
                *(__nv_bfloat162*)(out + (size_t)row * N + c) = __floats2bfloat162_rn(v0, v1);
            }
        }
    }
}

// ---------------- small SIMT GEMM (q2/k2) ------------------------------------
#define BM 64
#define BN 64
#define BK 16
__global__ void k_gemm(const float* __restrict__ A, const float* __restrict__ W,
                       const float* __restrict__ bias, float* __restrict__ out,
                       int M, int N, int K)
{
    __shared__ float As[BK][BM];
    __shared__ float Bs[BK][BN];
    int tid = threadIdx.x;
    int tx = tid & 15, ty = tid >> 4;
    int m0 = blockIdx.y * BM, n0 = blockIdx.x * BN;
    int lr = tid >> 2;
    int lk = (tid & 3) * 4;
    float acc[4][4] = {};
    for (int k0 = 0; k0 < K; k0 += BK) {
        float4 a4 = *(const float4*)(A + (size_t)(m0 + lr) * K + k0 + lk);
        float4 b4 = *(const float4*)(W + (size_t)(n0 + lr) * K + k0 + lk);
        As[lk+0][lr] = a4.x; As[lk+1][lr] = a4.y; As[lk+2][lr] = a4.z; As[lk+3][lr] = a4.w;
        Bs[lk+0][lr] = b4.x; Bs[lk+1][lr] = b4.y; Bs[lk+2][lr] = b4.z; Bs[lk+3][lr] = b4.w;
        __syncthreads();
        #pragma unroll
        for (int k = 0; k < BK; k++) {
            float4 ra = *(const float4*)&As[k][ty*4];
            float4 rb = *(const float4*)&Bs[k][tx*4];
            float av[4] = {ra.x, ra.y, ra.z, ra.w};
            float bv[4] = {rb.x, rb.y, rb.z, rb.w};
            #pragma unroll
            for (int i = 0; i < 4; i++)
                #pragma unroll
                for (int j = 0; j < 4; j++)
                    acc[i][j] += av[i] * bv[j];
        }
        __syncthreads();
    }
    #pragma unroll
    for (int i = 0; i < 4; i++) {
        int m = m0 + ty*4 + i;
        #pragma unroll
        for (int j = 0; j < 4; j++) {
            int n = n0 + tx*4 + j;
            out[(size_t)m * N + n] = acc[i][j] + bias[n];
        }
    }
}

// ============== attention v4 (R15-proven, bf16 in/out) =======================
#define AQS 36
#define AVS 132
#define APW 68
__global__ void __launch_bounds__(128, 3)
k_attn_mma()
{
    extern __shared__ float sm[];
    float* Qs = sm;
    float* Ks = sm + 4608;
    float* VT = sm + 9216;
    float* Pb = sm;

    int n = blockIdx.x >> 2, h = blockIdx.x & 3;
    int tid = threadIdx.x;
    int warp = tid >> 5, lane = tid & 31;
    int g = lane >> 2, t = lane & 3;
    int m0 = warp * 32;
    const __nv_bfloat16* base = g_qkvb + (size_t)n * NP * 3 * DD;

    for (int idx = tid; idx < NP*4; idx += 128) {
        int j = idx >> 2, dc = (idx & 3) * 8;
        uint4 qv = *(const uint4*)(base + j*384 +       h*32 + dc);
        uint4 kv = *(const uint4*)(base + j*384 + 128 + h*32 + dc);
        uint4 vv = *(const uint4*)(base + j*384 + 256 + h*32 + dc);
        float2 q0 = __bfloat1622float2(*(__nv_bfloat162*)&qv.x);
        float2 q1 = __bfloat1622float2(*(__nv_bfloat162*)&qv.y);
        float2 q2 = __bfloat1622float2(*(__nv_bfloat162*)&qv.z);
        float2 q3 = __bfloat1622float2(*(__nv_bfloat162*)&qv.w);
        *(float4*)&Qs[j*AQS + dc    ] = make_float4(q0.x, q0.y, q1.x, q1.y);
        *(float4*)&Qs[j*AQS + dc + 4] = make_float4(q2.x, q2.y, q3.x, q3.y);
        float2 k0 = __bfloat1622float2(*(__nv_bfloat162*)&kv.x);
        float2 k1 = __bfloat1622float2(*(__nv_bfloat162*)&kv.y);
        float2 k2 = __bfloat1622float2(*(__nv_bfloat162*)&kv.z);
        float2 k3 = __bfloat1622float2(*(__nv_bfloat162*)&kv.w);
        *(float4*)&Ks[j*AQS + dc    ] = make_float4(k0.x, k0.y, k1.x, k1.y);
        *(float4*)&Ks[j*AQS + dc + 4] = make_float4(k2.x, k2.y, k3.x, k3.y);
        float2 v0 = __bfloat1622float2(*(__nv_bfloat162*)&vv.x);
        float2 v1 = __bfloat1622float2(*(__nv_bfloat162*)&vv.y);
        float2 v2 = __bfloat1622float2(*(__nv_bfloat162*)&vv.z);
        float2 v3 = __bfloat1622float2(*(__nv_bfloat162*)&vv.w);
        VT[(dc    )*AVS + j] = v0.x;  VT[(dc + 1)*AVS + j] = v0.y;
        VT[(dc + 2)*AVS + j] = v1.x;  VT[(dc + 3)*AVS + j] = v1.y;
        VT[(dc + 4)*AVS + j] = v2.x;  VT[(dc + 5)*AVS + j] = v2.y;
        VT[(dc + 6)*AVS + j] = v3.x;  VT[(dc + 7)*AVS + j] = v3.y;
    }
    __syncthreads();

    float s[2][16][4] = {};
    #pragma unroll
    for (int kk = 0; kk < 32; kk += 8) {
        uint32_t afrag[2][4];
        #pragma unroll
        for (int mi = 0; mi < 2; mi++) {
            int r = m0 + mi * 16;
            afrag[mi][0] = FU(Qs[(r + g    )*AQS + kk + t    ]);
            afrag[mi][1] = FU(Qs[(r + g + 8)*AQS + kk + t    ]);
            afrag[mi][2] = FU(Qs[(r + g    )*AQS + kk + t + 4]);
            afrag[mi][3] = FU(Qs[(r + g + 8)*AQS + kk + t + 4]);
        }
        #pragma unroll
        for (int ni = 0; ni < 16; ni++) {
            int c = ni * 8;
            uint32_t b0 = FU(Ks[(c + g)*AQS + kk + t    ]);
            uint32_t b1 = FU(Ks[(c + g)*AQS + kk + t + 4]);
            mma8(s[0][ni], afrag[0], b0, b1);
            mma8(s[1][ni], afrag[1], b0, b1);
        }
    }
    __syncthreads();

    const float scale = 0.17677669529663687f;
    float mx[2][2] = {{-INFINITY,-INFINITY},{-INFINITY,-INFINITY}};
    #pragma unroll
    for (int mi = 0; mi < 2; mi++)
        #pragma unroll
        for (int ni = 0; ni < 16; ni++) {
            #pragma unroll
            for (int q = 0; q < 4; q++) s[mi][ni][q] *= scale;
            mx[mi][0] = fmaxf(mx[mi][0], fmaxf(s[mi][ni][0], s[mi][ni][1]));
            mx[mi][1] = fmaxf(mx[mi][1], fmaxf(s[mi][ni][2], s[mi][ni][3]));
        }
    #pragma unroll
    for (int mi = 0; mi < 2; mi++)
        #pragma unroll
        for (int hf = 0; hf < 2; hf++) {
            mx[mi][hf] = fmaxf(mx[mi][hf], __shfl_xor_sync(0xffffffffu, mx[mi][hf], 1));
            mx[mi][hf] = fmaxf(mx[mi][hf], __shfl_xor_sync(0xffffffffu, mx[mi][hf], 2));
        }
    float sum[2][2] = {};
    #pragma unroll
    for (int mi = 0; mi < 2; mi++)
        #pragma unroll
        for (int ni = 0; ni < 16; ni++) {
            s[mi][ni][0] = __expf(s[mi][ni][0] - mx[mi][0]);
            s[mi][ni][1] = __expf(s[mi][ni][1] - mx[mi][0]);
            s[mi][ni][2] = __expf(s[mi][ni][2] - mx[mi][1]);
            s[mi][ni][3] = __expf(s[mi][ni][3] - mx[mi][1]);
            sum[mi][0] += s[mi][ni][0] + s[mi][ni][1];
            sum[mi][1] += s[mi][ni][2] + s[mi][ni][3];
        }
    float inv[2][2];
    #pragma unroll
    for (int mi = 0; mi < 2; mi++)
        #pragma unroll
        for (int hf = 0; hf < 2; hf++) {
            float ss = sum[mi][hf];
            ss += __shfl_xor_sync(0xffffffffu, ss, 1);
            ss += __shfl_xor_sync(0xffffffffu, ss, 2);
            inv[mi][hf] = 1.f / ss;
        }

    float* Pw = Pb + warp * (32 * APW);
    float o[2][4][4] = {};
    #pragma unroll
    for (int hf = 0; hf < 2; hf++) {
        #pragma unroll
        for (int mi = 0; mi < 2; mi++) {
            int lr = mi * 16 + g;
            #pragma unroll
            for (int ni = 0; ni < 8; ni++) {
                int c = ni * 8 + 2 * t;
                Pw[ lr      *APW + c    ] = s[mi][hf*8 + ni][0];
                Pw[ lr      *APW + c + 1] = s[mi][hf*8 + ni][1];
                Pw[(lr + 8) *APW + c    ] = s[mi][hf*8 + ni][2];
                Pw[(lr + 8) *APW + c + 1] = s[mi][hf*8 + ni][3];
            }
        }
        __syncwarp();
        #pragma unroll
        for (int kk = 0; kk < 64; kk += 8) {
            uint32_t afrag[2][4];
            #pragma unroll
            for (int mi = 0; mi < 2; mi++) {
                int lr = mi * 16;
                afrag[mi][0] = FU(Pw[(lr + g    )*APW + kk + t    ]);
                afrag[mi][1] = FU(Pw[(lr + g + 8)*APW + kk + t    ]);
                afrag[mi][2] = FU(Pw[(lr + g    )*APW + kk + t + 4]);
                afrag[mi][3] = FU(Pw[(lr + g + 8)*APW + kk + t + 4]);
            }
            int j0 = hf*64 + kk + t, j1 = hf*64 + kk + t + 4;
            #pragma unroll
            for (int ni = 0; ni < 4; ni++) {
                int c = ni * 8;
                uint32_t b0 = FU(VT[(c + g)*AVS + j0]);
                uint32_t b1 = FU(VT[(c + g)*AVS + j1]);
                mma8(o[0][ni], afrag[0], b0, b1);
                mma8(o[1][ni], afrag[1], b0, b1);
            }
        }
        __syncwarp();
    }

    #pragma unroll
    for (int mi = 0; mi < 2; mi++) {
        int r0 = n*NP + m0 + mi * 16 + g;
        #pragma unroll
        for (int ni = 0; ni < 4; ni++) {
            int d = ni * 8 + 2 * t;
            *(__nv_bfloat162*)(g_ob + (size_t) r0      *DD + h*32 + d) =
                __floats2bfloat162_rn(o[mi][ni][0]*inv[mi][0], o[mi][ni][1]*inv[mi][0]);
            *(__nv_bfloat162*)(g_ob + (size_t)(r0 + 8) *DD + h*32 + d) =
                __floats2bfloat162_rn(o[mi][ni][2]*inv[mi][1], o[mi][ni][3]*inv[mi][1]);
        }
    }
}

// ---------------- mean over Np -----------------------------------------------
__global__ void k_mean()
{
    int n = blockIdx.x, d = threadIdx.x;
    float s = 0.f;
    for (int p = 0; p < NP; p++) s += g_Htemp[((size_t)n*NP + p)*DD + d];
    g_Hs[n*DD + d] = s * (1.f/128.f);
}

// ---------------- W_att = gat_w[h]^T @ att{src,dst}[h] -----------------------
__global__ void k_watt(const float* __restrict__ gw, const float* __restrict__ asv,
                       const float* __restrict__ adv)
{
    int idx = blockIdx.x * 256 + threadIdx.x;
    int r = idx >> 7, d = idx & 127;
    int h = r & 3;
    const float* att = (r < 4) ? asv : adv;
    float s = 0.f;
    for (int f = 0; f < 128; f++)
        s += att[h*FF + f] * gw[h*FF*DD + f*DD + d];
    g_watt[r*DD + d] = s;
}

// ---------------- graph adjacency --------------------------------------------
__global__ void k_graph(const float* __restrict__ adj)
{
    __shared__ float k2s[CC*DK];
    __shared__ float Amat[CC*65];
    int b = blockIdx.x, c = threadIdx.x;
    for (int idx = c; idx < CC*DK; idx += 64) k2s[idx] = g_k2[(size_t)b*CC*DK + idx];
    __syncthreads();
    float qreg[DK];
    #pragma unroll
    for (int d = 0; d < DK; d++) qreg[d] = g_q2[(size_t)b*CC*DK + c*DK + d];
    for (int e = 0; e < CC; e++) {
        float a = 0.f;
        #pragma unroll
        for (int d = 0; d < DK; d++) a += qreg[d] * k2s[e*DK + d];
        Amat[c*65 + e] = tanhf(a * 0.125f) + adj[c*CC + e];
    }
    for (int e = 0; e < CC; e++) g_mask[(size_t)b*CC*CC + c*CC + e] = 0.f;
    for (int kk = 0; kk < 8; kk++) {
        float best = -INFINITY; int bi = 0;
        for (int e = 0; e < CC; e++) {
            float v = Amat[c*65 + e];
            if (v > best) { best = v; bi = e; }
        }
        if (bi != c && best != 0.f) g_mask[(size_t)b*CC*CC + c*CC + bi] = 1.f;
        Amat[c*65 + bi] = -INFINITY;
    }
}

// ============== GAT v2 (R12-proven, bf16 xh) =================================
#define XST 68
#define AST 68
#define OST 132
#define GU  8704
__global__ void __launch_bounds__(256)
k_gat(const float* __restrict__ gbias, const float* __restrict__ sg,
      const float* __restrict__ sb, float* __restrict__ out)
{
    extern __shared__ float sm[];
    float* U   = sm;
    float* Awt = sm + GU;
    float* Asv = sm + GU + 4352;
    float* Adv = sm + GU + 4416;
    float* XhT = U;
    float* Os  = U;

    int b = blockIdx.x >> 7, p = blockIdx.x & 127;
    int tid = threadIdx.x, w = tid >> 5, lane = tid & 31;
    int wm = w >> 2, wn = w & 3;
    int g = lane >> 2, t4 = lane & 3;

    float mr0[8], mr1[8];
    #pragma unroll
    for (int i = 0; i < 8; i++) {
        int t = w*8 + i;
        mr0[i] = g_mask[(size_t)b*CC*CC + lane*CC + t];
        mr1[i] = g_mask[(size_t)b*CC*CC + (lane+32)*CC + t];
    }

    float acc[2][4][4] = {};
    for (int h = 0; h < HS; h++) {
        __syncthreads();
        for (int idx = tid; idx < CC*FF/2; idx += 256) {
            int s = idx >> 6, fp = idx & 63;
            const __nv_bfloat162 v2 = *(const __nv_bfloat162*)
                (g_xhb + (size_t)(((b*CC + s)*NP + p))*(HS*FF) + h*FF + 2*fp);
            float2 vf = __bfloat1622float2(v2);
            XhT[(2*fp    )*XST + s] = vf.x;
            XhT[(2*fp + 1)*XST + s] = vf.y;
        }
        if (tid < 64)            Asv[tid]      = g_asrc[(((b*4 + h)*128 + p)*64) + tid];
        else if (tid < 128)      Adv[tid - 64] = g_adst[(((b*4 + h)*128 + p)*64) + tid - 64];
        __syncthreads();

        #pragma unroll
        for (int i = 0; i < 8; i++) {
            int t = w*8 + i;
            float adt = Adv[t];
            float e0 = Asv[lane]      + adt; e0 = e0 > 0.f ? e0 : 0.2f*e0;
            float e1 = Asv[lane + 32] + adt; e1 = e1 > 0.f ? e1 : 0.2f*e1;
            float me = fmaxf(mr0[i] > 0.5f ? e0 : GAT_NEG, mr1[i] > 0.5f ? e1 : GAT_NEG);
            #pragma unroll
            for (int o = 16; o; o >>= 1) me = fmaxf(me, __shfl_xor_sync(0xffffffffu, me, o));
            float w0 = (mr0[i] > 0.5f) ? __expf(e0 - me) : 0.f;
            float w1 = (mr1[i] > 0.5f) ? __expf(e1 - me) : 0.f;
            float ws = w0 + w1;
            #pragma unroll
            for (int o = 16; o; o >>= 1) ws += __shfl_xor_sync(0xffffffffu, ws, o);
            float inv = ws > 0.f ? 1.f / ws : 0.f;
            Awt[t*AST + lane]      = w0 * inv;
            Awt[t*AST + lane + 32] = w1 * inv;
        }
        __syncthreads();

        #pragma unroll
        for (int kk = 0; kk < CC; kk += 8) {
            uint32_t afrag[2][4];
            #pragma unroll
            for (int mi = 0; mi < 2; mi++) {
                int r = wm * 32 + mi * 16;
                afrag[mi][0] = FU(Awt[(r + g    )*AST + kk + t4    ]);
                afrag[mi][1] = FU(Awt[(r + g + 8)*AST + kk + t4    ]);
                afrag[mi][2] = FU(Awt[(r + g    )*AST + kk + t4 + 4]);
                afrag[mi][3] = FU(Awt[(r + g + 8)*AST + kk + t4 + 4]);
            }
            #pragma unroll
            for (int ni = 0; ni < 4; ni++) {
                int c = wn * 32 + ni * 8;
                uint32_t b0 = FU(XhT[(c + g)*XST + kk + t4    ]);
                uint32_t b1 = FU(XhT[(c + g)*XST + kk + t4 + 4]);
                mma8(acc[0][ni], afrag[0], b0, b1);
                mma8(acc[1][ni], afrag[1], b0, b1);
            }
        }
    }

    __syncthreads();
    for (int idx = tid; idx < CC*DD; idx += 256) {
        int r = idx >> 7, f = idx & 127;
        Os[r*OST + f] = g_Htemp[(((size_t)(b*CC + r))*NP + p)*DD + f] + gbias[f];
    }
    __syncthreads();
    #pragma unroll
    for (int mi = 0; mi < 2; mi++)
        #pragma unroll
        for (int ni = 0; ni < 4; ni++) {
            int r = wm*32 + mi*16 + g;
            int c = wn*32 + ni*8 + 2*t4;
            #pragma unroll
            for (int half = 0; half < 2; half++) {
                int row = r + half*8;
                Os[row*OST + c    ] += acc[mi][ni][half*2 + 0] * 0.25f;
                Os[row*OST + c + 1] += acc[mi][ni][half*2 + 1] * 0.25f;
            }
        }
    __syncthreads();
    {
        float4 g4 = ((const float4*)sg)[lane];
        float4 b4 = ((const float4*)sb)[lane];
        for (int r = w; r < CC; r += 8) {
            float4 v = *(float4*)&Os[r*OST + lane*4];
            float s1 = v.x + v.y + v.z + v.w;
            #pragma unroll
            for (int o = 16; o; o >>= 1) s1 += __shfl_xor_sync(0xffffffffu, s1, o);
            float mean = s1 * (1.f/128.f);
            float dx=v.x-mean, dy=v.y-mean, dz=v.z-mean, dw=v.w-mean;
            float q = dx*dx+dy*dy+dz*dz+dw*dw;
            #pragma unroll
            for (int o = 16; o; o >>= 1) q += __shfl_xor_sync(0xffffffffu, q, o);
            float inv = rsqrtf(q * (1.f/128.f) + 1e-5f);
            float4 ov;
            ov.x = dx*inv*g4.x + b4.x; ov.y = dy*inv*g4.y + b4.y;
            ov.z = dz*inv*g4.z + b4.z; ov.w = dw*inv*g4.w + b4.w;
            ((float4*)(out + (((size_t)(b*CC + r))*NP + p)*DD))[lane] = ov;
        }
    }
}

// ---------------- host launch -------------------------------------------------
extern "C" void kernel_launch(void* const* d_in, const int* in_sizes, int n_in,
                              void* d_out, int out_size)
{
    const float* H_in      = (const float*)d_in[0];
    const float* static_adj= (const float*)d_in[1];
    const float* attn_in_w = (const float*)d_in[2];
    const float* attn_in_b = (const float*)d_in[3];
    const float* attn_out_w= (const float*)d_in[4];
    const float* attn_out_b= (const float*)d_in[5];
    const float* ln1_g     = (const float*)d_in[6];
    const float* ln1_b     = (const float*)d_in[7];
    const float* ln2_g     = (const float*)d_in[8];
    const float* ln2_b     = (const float*)d_in[9];
    const float* ff1_w     = (const float*)d_in[10];
    const float* ff1_b     = (const float*)d_in[11];
    const float* ff2_w     = (const float*)d_in[12];
    const float* ff2_b     = (const float*)d_in[13];
    const float* tnorm_g   = (const float*)d_in[14];
    const float* tnorm_b   = (const float*)d_in[15];
    const float* q_w       = (const float*)d_in[16];
    const float* q_b       = (const float*)d_in[17];
    const float* k_w       = (const float*)d_in[18];
    const float* k_b       = (const float*)d_in[19];
    const float* gat_w     = (const float*)d_in[20];
    const float* gat_att_src = (const float*)d_in[21];
    const float* gat_att_dst = (const float*)d_in[22];
    const float* gat_bias  = (const float*)d_in[23];
    const float* snorm_g   = (const float*)d_in[24];
    const float* snorm_b   = (const float*)d_in[25];

    float *x_, *Htemp_, *Hs_, *q2_, *k2_;
    __nv_bfloat16 *hb_, *xhb_, *qkvb_, *ob_, *ffb_;
    cudaGetSymbolAddress((void**)&hb_,    g_hb);
    cudaGetSymbolAddress((void**)&qkvb_,  g_qkvb);
    cudaGetSymbolAddress((void**)&ob_,    g_ob);
    cudaGetSymbolAddress((void**)&x_,     g_x);
    cudaGetSymbolAddress((void**)&ffb_,   g_ffb);
    cudaGetSymbolAddress((void**)&Htemp_, g_Htemp);
    cudaGetSymbolAddress((void**)&xhb_,   g_xhb);
    cudaGetSymbolAddress((void**)&Hs_,    g_Hs);
    cudaGetSymbolAddress((void**)&q2_,    g_q2);
    cudaGetSymbolAddress((void**)&k2_,    g_k2);

    const int mma_smem  = 4 * TILE * 4;                 // 73728
    const int mmaA_smem = 2*TILEA*2 + 2*TILE*4;         // 57344
    const int attn_smem = 13440 * 4;                    // 53760
    const int gat_smem  = (GU + 4352 + 128) * 4;        // 52736
    cudaFuncSetAttribute(k_mma_bf,  cudaFuncAttributeMaxDynamicSharedMemorySize, mma_smem);
    cudaFuncSetAttribute(k_mma_bfA, cudaFuncAttributeMaxDynamicSharedMemorySize, mmaA_smem);
    cudaFuncSetAttribute(k_mma_b2b, cudaFuncAttributeMaxDynamicSharedMemorySize, mmaA_smem);
    cudaFuncSetAttribute(k_attn_mma, cudaFuncAttributeMaxDynamicSharedMemorySize, attn_smem);
    cudaFuncSetAttribute(k_gat,  cudaFuncAttributeMaxDynamicSharedMemorySize, gat_smem);

    // 0) W_att vectors
    k_watt<<<4, 256>>>(gat_w, gat_att_src, gat_att_dst);
    // 1) h = ln1(x0)  (bf16 out)
    k_ln<<<NTOK/8, 256>>>(H_in, ln1_g, ln1_b, hb_);
    // 2) qkv = h @ Wqkv^T + b  (bf16 in/out)
    k_mma_b2b<<<dim3(3, NTOK/TBM), 256, mmaA_smem>>>(hb_, attn_in_w, attn_in_b, qkvb_,
                                                     384, 128, 0);
    // 3) temporal attention (bf16 in/out)
    k_attn_mma<<<NSEQ*HT, 128, attn_smem>>>();
    // 4) x1 = x0 + o @ Wout^T + b  (bf16 A)
    k_mma_bfA<<<dim3(1, NTOK/TBM), 256, mmaA_smem>>>(ob_, attn_out_w, attn_out_b,
                                                     H_in, x_, 128, 128);
    // 5) h = ln2(x1)  (bf16 out)
    k_ln<<<NTOK/8, 256>>>(x_, ln2_g, ln2_b, hb_);
    // 6) ff = relu(h @ W1^T + b1)  (bf16 in/out)
    k_mma_b2b<<<dim3(4, NTOK/TBM), 256, mmaA_smem>>>(hb_, ff1_w, ff1_b, ffb_,
                                                     512, 128, 1);
    // 7) x2 = x1 + ff @ W2^T + b2  (bf16 A)
    k_mma_bfA<<<dim3(1, NTOK/TBM), 256, mmaA_smem>>>(ffb_, ff2_w, ff2_b,
                                                     x_, x_, 128, 512);
    // 8) H_temp = ln(x0 + x2, tnorm) + fused asrc/adst
    k_ln_asd<<<NTOK/8, 256>>>(x_, H_in, tnorm_g, tnorm_b, Htemp_);
    // 9) xh = H_temp @ gat_w^T  (bf16 out)
    k_mma_bf<<<dim3(4, NTOK/TBM), 256, mma_smem>>>(Htemp_, gat_w, nullptr, xhb_,
                                                   512, 128, 0);
    // 10) Hs = mean_p(H_temp)
    k_mean<<<NSEQ, 128>>>();
    // 11) q2, k2
    k_gemm<<<dim3(1, NSEQ/BM), 256>>>(Hs_, q_w, q_b, q2_, NSEQ, 64, 128);
    k_gemm<<<dim3(1, NSEQ/BM), 256>>>(Hs_, k_w, k_b, k2_, NSEQ, 64, 128);
    // 12) adjacency / top-k / mask
    k_graph<<<BB, 64>>>(static_adj);
    // 13) GAT v2 + snorm LN -> output
    k_gat<<<BB*NP, 256, gat_smem>>>(gat_bias, snorm_g, snorm_b, (float*)d_out);
}

// round 17
// speedup vs baseline: 1.3073x; 1.0883x over previous
#include <cuda_runtime.h>
#include <cuda_bf16.h>
#include <math.h>
#include <stdint.h>

#define BB   16
#define CC   64
#define NP   128
#define DD   128
#define HT   4
#define DH   32
#define HS   4
#define FF   128
#define DK   64
#define NTOK (BB*CC*NP)      // 131072
#define NSEQ (BB*CC)         // 1024
#define GAT_NEG -1e30f

// ---------------- scratch ----------------------------------------------------
__device__ __nv_bfloat16 g_hb[NTOK*DD];
__device__ __nv_bfloat16 g_qkvb[(size_t)NTOK*3*DD];
__device__ __nv_bfloat16 g_ob[NTOK*DD];
__device__ float g_x[NTOK*DD];
__device__ __nv_bfloat16 g_ffb[(size_t)NTOK*4*DD];
__device__ float g_Htemp[NTOK*DD];
__device__ __nv_bfloat16 g_xhb[(size_t)NTOK*HS*FF];
__device__ float g_Hs[NSEQ*DD];
__device__ float g_q2[NSEQ*DK];
__device__ float g_k2[NSEQ*DK];
__device__ float g_mask[BB*CC*CC];
__device__ float g_watt[8*DD];
__device__ float g_asrc[BB*HS*NP*CC];
__device__ float g_adst[BB*HS*NP*CC];

// ---------------- helpers ----------------------------------------------------
__device__ __forceinline__ void mma8(float c[4], const uint32_t a[4],
                                     uint32_t b0, uint32_t b1) {
    asm volatile(
        "mma.sync.aligned.m16n8k8.row.col.f32.tf32.tf32.f32 "
        "{%0,%1,%2,%3}, {%4,%5,%6,%7}, {%8,%9}, {%0,%1,%2,%3};"
        : "+f"(c[0]), "+f"(c[1]), "+f"(c[2]), "+f"(c[3])
        : "r"(a[0]), "r"(a[1]), "r"(a[2]), "r"(a[3]), "r"(b0), "r"(b1));
}
__device__ __forceinline__ void cp_async16(void* smem, const void* gmem) {
    uint32_t s = (uint32_t)__cvta_generic_to_shared(smem);
    asm volatile("cp.async.cg.shared.global [%0], [%1], 16;" :: "r"(s), "l"(gmem));
}
#define FU(x) __float_as_uint(x)
#define BF2F(x) __bfloat162float(x)

// ---------------- LayerNorm: warp per row, bf16 out (ln1/ln2) ----------------
__global__ void k_ln(const float* __restrict__ x,
                     const float* __restrict__ gw, const float* __restrict__ bw,
                     __nv_bfloat16* __restrict__ out)
{
    int row  = blockIdx.x * 8 + (threadIdx.x >> 5);
    int lane = threadIdx.x & 31;
    float4 v = ((const float4*)(x + (size_t)row * DD))[lane];
    float s = v.x + v.y + v.z + v.w;
    #pragma unroll
    for (int o = 16; o; o >>= 1) s += __shfl_xor_sync(0xffffffffu, s, o);
    float mean = s * (1.f/128.f);
    float dx = v.x-mean, dy = v.y-mean, dz = v.z-mean, dw = v.w-mean;
    float q = dx*dx + dy*dy + dz*dz + dw*dw;
    #pragma unroll
    for (int o = 16; o; o >>= 1) q += __shfl_xor_sync(0xffffffffu, q, o);
    float inv = rsqrtf(q * (1.f/128.f) + 1e-5f);
    float4 g4 = ((const float4*)gw)[lane];
    float4 b4 = ((const float4*)bw)[lane];
    __nv_bfloat162 b01 = __floats2bfloat162_rn(dx*inv*g4.x + b4.x, dy*inv*g4.y + b4.y);
    __nv_bfloat162 b23 = __floats2bfloat162_rn(dz*inv*g4.z + b4.z, dw*inv*g4.w + b4.w);
    uint2 st;
    st.x = *(uint32_t*)&b01;
    st.y = *(uint32_t*)&b23;
    *(uint2*)(out + (size_t)row * DD + lane*4) = st;
}

// -------- tnorm LN + fused asrc/adst (R14-proven; fp32 out) ------------------
__global__ void k_ln_asd(const float* __restrict__ x, const float* __restrict__ add,
                         const float* __restrict__ gw, const float* __restrict__ bw,
                         float* __restrict__ out)
{
    __shared__ float4 W4[8][32];
    int tid = threadIdx.x;
    int warp = tid >> 5, lane = tid & 31;
    for (int i = tid; i < 256; i += 256)
        ((float4*)W4)[i] = ((const float4*)g_watt)[i];
    __syncthreads();

    int row = blockIdx.x * 8 + warp;
    float4 v = ((const float4*)(x + (size_t)row * DD))[lane];
    float4 a = ((const float4*)(add + (size_t)row * DD))[lane];
    v.x += a.x; v.y += a.y; v.z += a.z; v.w += a.w;
    float s = v.x + v.y + v.z + v.w;
    #pragma unroll
    for (int o = 16; o; o >>= 1) s += __shfl_xor_sync(0xffffffffu, s, o);
    float mean = s * (1.f/128.f);
    float dx = v.x-mean, dy = v.y-mean, dz = v.z-mean, dw = v.w-mean;
    float q = dx*dx + dy*dy + dz*dz + dw*dw;
    #pragma unroll
    for (int o = 16; o; o >>= 1) q += __shfl_xor_sync(0xffffffffu, q, o);
    float inv = rsqrtf(q * (1.f/128.f) + 1e-5f);
    float4 g4 = ((const float4*)gw)[lane];
    float4 b4 = ((const float4*)bw)[lane];
    float4 o4;
    o4.x = dx*inv*g4.x + b4.x;  o4.y = dy*inv*g4.y + b4.y;
    o4.z = dz*inv*g4.z + b4.z;  o4.w = dw*inv*g4.w + b4.w;
    ((float4*)(out + (size_t)row * DD))[lane] = o4;

    int p = row & 127, bs = row >> 7;
    int sidx = bs & 63, b = bs >> 6;
    #pragma unroll
    for (int r = 0; r < 8; r++) {
        float4 w = W4[r][lane];
        float d = o4.x*w.x + o4.y*w.y + o4.z*w.z + o4.w*w.w;
        #pragma unroll
        for (int o = 16; o; o >>= 1) d += __shfl_xor_sync(0xffffffffu, d, o);
        if (lane == 0) {
            int h = r & 3;
            float* dst = (r < 4) ? g_asrc : g_adst;
            dst[(((b*4 + h)*128 + p)*64) + sidx] = d;
        }
    }
}

// ---------------- tf32 GEMM -> bf16 out (fp32 A) -----------------------------
#define TBM 128
#define TBN 128
#define TILE (128*36)
__global__ void __launch_bounds__(256)
k_mma_bf(const float* __restrict__ A, const float* __restrict__ W,
         const float* __restrict__ bias, __nv_bfloat16* __restrict__ out,
         int N, int K, int relu)
{
    extern __shared__ float smbuf[];
    float* As = smbuf;
    float* Bs = smbuf + 2*TILE;
    int tid  = threadIdx.x;
    int warp = tid >> 5, lane = tid & 31;
    int wm = warp >> 1, wn = warp & 1;
    int g = lane >> 2, t = lane & 3;
    int m0 = blockIdx.y * TBM;
    int n0 = blockIdx.x * TBN;
    int lr = tid >> 3, lc = (tid & 7) << 2;

    float acc[2][8][4] = {};
    const int nk = K >> 5;

    #pragma unroll
    for (int i = 0; i < 4; i++) {
        int r = lr + i * 32;
        cp_async16(&As[r*36 + lc], A + (size_t)(m0 + r) * K + lc);
        cp_async16(&Bs[r*36 + lc], W + (size_t)(n0 + r) * K + lc);
    }
    asm volatile("cp.async.commit_group;");

    for (int kt = 0; kt < nk; kt++) {
        int buf = (kt & 1) * TILE;
        if (kt + 1 < nk) {
            int nb = ((kt + 1) & 1) * TILE;
            int ko = (kt + 1) << 5;
            #pragma unroll
            for (int i = 0; i < 4; i++) {
                int r = lr + i * 32;
                cp_async16(&As[nb + r*36 + lc], A + (size_t)(m0 + r) * K + ko + lc);
                cp_async16(&Bs[nb + r*36 + lc], W + (size_t)(n0 + r) * K + ko + lc);
            }
            asm volatile("cp.async.commit_group;");
            asm volatile("cp.async.wait_group 1;");
        } else {
            asm volatile("cp.async.wait_group 0;");
        }
        __syncthreads();
        #pragma unroll
        for (int kk = 0; kk < 32; kk += 8) {
            uint32_t afrag[2][4];
            #pragma unroll
            for (int mi = 0; mi < 2; mi++) {
                int r = wm * 32 + mi * 16;
                afrag[mi][0] = FU(As[buf + (r + g    )*36 + kk + t    ]);
                afrag[mi][1] = FU(As[buf + (r + g + 8)*36 + kk + t    ]);
                afrag[mi][2] = FU(As[buf + (r + g    )*36 + kk + t + 4]);
                afrag[mi][3] = FU(As[buf + (r + g + 8)*36 + kk + t + 4]);
            }
            #pragma unroll
            for (int ni = 0; ni < 8; ni++) {
                int c = wn * 64 + ni * 8;
                uint32_t b0 = FU(Bs[buf + (c + g)*36 + kk + t    ]);
                uint32_t b1 = FU(Bs[buf + (c + g)*36 + kk + t + 4]);
                mma8(acc[0][ni], afrag[0], b0, b1);
                mma8(acc[1][ni], afrag[1], b0, b1);
            }
        }
        __syncthreads();
    }

    #pragma unroll
    for (int mi = 0; mi < 2; mi++) {
        #pragma unroll
        for (int ni = 0; ni < 8; ni++) {
            int r = m0 + wm * 32 + mi * 16 + g;
            int c = n0 + wn * 64 + ni * 8 + 2 * t;
            float bv0 = bias ? bias[c]     : 0.f;
            float bv1 = bias ? bias[c + 1] : 0.f;
            #pragma unroll
            for (int half = 0; half < 2; half++) {
                int row = r + half * 8;
                float v0 = acc[mi][ni][half*2 + 0] + bv0;
                float v1 = acc[mi][ni][half*2 + 1] + bv1;
                if (relu) { v0 = fmaxf(v0, 0.f); v1 = fmaxf(v1, 0.f); }
                *(__nv_bfloat162*)(out + (size_t)row * N + c) = __floats2bfloat162_rn(v0, v1);
            }
        }
    }
}

// ---------------- tf32 GEMM, bf16 A -> fp32 out (+bias,+res) (R15-proven) ----
#define TA 40
#define TILEA (128*TA)
__global__ void __launch_bounds__(256)
k_mma_bfA(const __nv_bfloat16* __restrict__ A, const float* __restrict__ W,
          const float* __restrict__ bias, const float* __restrict__ res,
          float* __restrict__ out, int N, int K)
{
    extern __shared__ float smbuf[];
    __nv_bfloat16* AsB = (__nv_bfloat16*)smbuf;
    float* Bs = smbuf + (2*TILEA*2)/4;
    int tid  = threadIdx.x;
    int warp = tid >> 5, lane = tid & 31;
    int wm = warp >> 1, wn = warp & 1;
    int g = lane >> 2, t = lane & 3;
    int m0 = blockIdx.y * TBM;
    int n0 = blockIdx.x * TBN;
    int lr = tid >> 3, lc = (tid & 7) << 2;

    float acc[2][8][4] = {};
    const int nk = K >> 5;

    #pragma unroll
    for (int i = 0; i < 2; i++) {
        int idx = tid + i * 256;
        int r = idx >> 2, c8 = (idx & 3) * 8;
        cp_async16(AsB + r*TA + c8, A + (size_t)(m0 + r) * K + c8);
    }
    #pragma unroll
    for (int i = 0; i < 4; i++) {
        int r = lr + i * 32;
        cp_async16(&Bs[r*36 + lc], W + (size_t)(n0 + r) * K + lc);
    }
    asm volatile("cp.async.commit_group;");

    for (int kt = 0; kt < nk; kt++) {
        int abuf = (kt & 1) * TILEA;
        int bbuf = (kt & 1) * TILE;
        if (kt + 1 < nk) {
            int nab = ((kt + 1) & 1) * TILEA;
            int nbb = ((kt + 1) & 1) * TILE;
            int ko = (kt + 1) << 5;
            #pragma unroll
            for (int i = 0; i < 2; i++) {
                int idx = tid + i * 256;
                int r = idx >> 2, c8 = (idx & 3) * 8;
                cp_async16(AsB + nab + r*TA + c8, A + (size_t)(m0 + r) * K + ko + c8);
            }
            #pragma unroll
            for (int i = 0; i < 4; i++) {
                int r = lr + i * 32;
                cp_async16(&Bs[nbb + r*36 + lc], W + (size_t)(n0 + r) * K + ko + lc);
            }
            asm volatile("cp.async.commit_group;");
            asm volatile("cp.async.wait_group 1;");
        } else {
            asm volatile("cp.async.wait_group 0;");
        }
        __syncthreads();
        #pragma unroll
        for (int kk = 0; kk < 32; kk += 8) {
            uint32_t afrag[2][4];
            #pragma unroll
            for (int mi = 0; mi < 2; mi++) {
                int r = wm * 32 + mi * 16;
                afrag[mi][0] = FU(BF2F(AsB[abuf + (r + g    )*TA + kk + t    ]));
                afrag[mi][1] = FU(BF2F(AsB[abuf + (r + g + 8)*TA + kk + t    ]));
                afrag[mi][2] = FU(BF2F(AsB[abuf + (r + g    )*TA + kk + t + 4]));
                afrag[mi][3] = FU(BF2F(AsB[abuf + (r + g + 8)*TA + kk + t + 4]));
            }
            #pragma unroll
            for (int ni = 0; ni < 8; ni++) {
                int c = wn * 64 + ni * 8;
                uint32_t b0 = FU(Bs[bbuf + (c + g)*36 + kk + t    ]);
                uint32_t b1 = FU(Bs[bbuf + (c + g)*36 + kk + t + 4]);
                mma8(acc[0][ni], afrag[0], b0, b1);
                mma8(acc[1][ni], afrag[1], b0, b1);
            }
        }
        __syncthreads();
    }

    #pragma unroll
    for (int mi = 0; mi < 2; mi++) {
        #pragma unroll
        for (int ni = 0; ni < 8; ni++) {
            int r = m0 + wm * 32 + mi * 16 + g;
            int c = n0 + wn * 64 + ni * 8 + 2 * t;
            float bv0 = bias[c], bv1 = bias[c + 1];
            #pragma unroll
            for (int half = 0; half < 2; half++) {
                int row = r + half * 8;
                float v0 = acc[mi][ni][half*2 + 0] + bv0;
                float v1 = acc[mi][ni][half*2 + 1] + bv1;
                const float2 rr = *(const float2*)(res + (size_t)row * N + c);
                v0 += rr.x; v1 += rr.y;
                *(float2*)(out + (size_t)row * N + c) = make_float2(v0, v1);
            }
        }
    }
}

// ---------------- tf32 GEMM, bf16 A -> bf16 out (+bias,+relu) ----------------
__global__ void __launch_bounds__(256)
k_mma_b2b(const __nv_bfloat16* __restrict__ A, const float* __restrict__ W,
          const float* __restrict__ bias, __nv_bfloat16* __restrict__ out,
          int N, int K, int relu)
{
    extern __shared__ float smbuf[];
    __nv_bfloat16* AsB = (__nv_bfloat16*)smbuf;
    float* Bs = smbuf + (2*TILEA*2)/4;
    int tid  = threadIdx.x;
    int warp = tid >> 5, lane = tid & 31;
    int wm = warp >> 1, wn = warp & 1;
    int g = lane >> 2, t = lane & 3;
    int m0 = blockIdx.y * TBM;
    int n0 = blockIdx.x * TBN;
    int lr = tid >> 3, lc = (tid & 7) << 2;

    float acc[2][8][4] = {};
    const int nk = K >> 5;

    #pragma unroll
    for (int i = 0; i < 2; i++) {
        int idx = tid + i * 256;
        int r = idx >> 2, c8 = (idx & 3) * 8;
        cp_async16(AsB + r*TA + c8, A + (size_t)(m0 + r) * K + c8);
    }
    #pragma unroll
    for (int i = 0; i < 4; i++) {
        int r = lr + i * 32;
        cp_async16(&Bs[r*36 + lc], W + (size_t)(n0 + r) * K + lc);
    }
    asm volatile("cp.async.commit_group;");

    for (int kt = 0; kt < nk; kt++) {
        int abuf = (kt & 1) * TILEA;
        int bbuf = (kt & 1) * TILE;
        if (kt + 1 < nk) {
            int nab = ((kt + 1) & 1) * TILEA;
            int nbb = ((kt + 1) & 1) * TILE;
            int ko = (kt + 1) << 5;
            #pragma unroll
            for (int i = 0; i < 2; i++) {
                int idx = tid + i * 256;
                int r = idx >> 2, c8 = (idx & 3) * 8;
                cp_async16(AsB + nab + r*TA + c8, A + (size_t)(m0 + r) * K + ko + c8);
            }
            #pragma unroll
            for (int i = 0; i < 4; i++) {
                int r = lr + i * 32;
                cp_async16(&Bs[nbb + r*36 + lc], W + (size_t)(n0 + r) * K + ko + lc);
            }
            asm volatile("cp.async.commit_group;");
            asm volatile("cp.async.wait_group 1;");
        } else {
            asm volatile("cp.async.wait_group 0;");
        }
        __syncthreads();
        #pragma unroll
        for (int kk = 0; kk < 32; kk += 8) {
            uint32_t afrag[2][4];
            #pragma unroll
            for (int mi = 0; mi < 2; mi++) {
                int r = wm * 32 + mi * 16;
                afrag[mi][0] = FU(BF2F(AsB[abuf + (r + g    )*TA + kk + t    ]));
                afrag[mi][1] = FU(BF2F(AsB[abuf + (r + g + 8)*TA + kk + t    ]));
                afrag[mi][2] = FU(BF2F(AsB[abuf + (r + g    )*TA + kk + t + 4]));
                afrag[mi][3] = FU(BF2F(AsB[abuf + (r + g + 8)*TA + kk + t + 4]));
            }
            #pragma unroll
            for (int ni = 0; ni < 8; ni++) {
                int c = wn * 64 + ni * 8;
                uint32_t b0 = FU(Bs[bbuf + (c + g)*36 + kk + t    ]);
                uint32_t b1 = FU(Bs[bbuf + (c + g)*36 + kk + t + 4]);
                mma8(acc[0][ni], afrag[0], b0, b1);
                mma8(acc[1][ni], afrag[1], b0, b1);
            }
        }
        __syncthreads();
    }

    #pragma unroll
    for (int mi = 0; mi < 2; mi++) {
        #pragma unroll
        for (int ni = 0; ni < 8; ni++) {
            int r = m0 + wm * 32 + mi * 16 + g;
            int c = n0 + wn * 64 + ni * 8 + 2 * t;
            float bv0 = bias[c], bv1 = bias[c + 1];
            #pragma unroll
            for (int half = 0; half < 2; half++) {
                int row = r + half * 8;
                float v0 = acc[mi][ni][half*2 + 0] + bv0;
                float v1 = acc[mi][ni][half*2 + 1] + bv1;
                if (relu) { v0 = fmaxf(v0, 0.f); v1 = fmaxf(v1, 0.f); }
                *(__nv_bfloat162*)(out + (size_t)row * N + c) = __floats2bfloat162_rn(v0, v1);
            }
        }
    }
}

// ---------------- small SIMT GEMM: q2 AND k2 in one launch -------------------
#define BM 64
#define BK 16
__global__ void k_gemm2(const float* __restrict__ A,
                        const float* __restrict__ Wq, const float* __restrict__ bq,
                        float* __restrict__ oq,
                        const float* __restrict__ Wk, const float* __restrict__ bk,
                        float* __restrict__ ok, int K)
{
    const float* W    = blockIdx.x ? Wk : Wq;
    const float* bias = blockIdx.x ? bk : bq;
    float* out        = blockIdx.x ? ok : oq;
    const int N = 64;
    __shared__ float As[BK][BM];
    __shared__ float Bs[BK][64];
    int tid = threadIdx.x;
    int tx = tid & 15, ty = tid >> 4;
    int m0 = blockIdx.y * BM;
    int lr = tid >> 2;
    int lk = (tid & 3) * 4;
    float acc[4][4] = {};
    for (int k0 = 0; k0 < K; k0 += BK) {
        float4 a4 = *(const float4*)(A + (size_t)(m0 + lr) * K + k0 + lk);
        float4 b4 = *(const float4*)(W + (size_t)lr * K + k0 + lk);
        As[lk+0][lr] = a4.x; As[lk+1][lr] = a4.y; As[lk+2][lr] = a4.z; As[lk+3][lr] = a4.w;
        Bs[lk+0][lr] = b4.x; Bs[lk+1][lr] = b4.y; Bs[lk+2][lr] = b4.z; Bs[lk+3][lr] = b4.w;
        __syncthreads();
        #pragma unroll
        for (int k = 0; k < BK; k++) {
            float4 ra = *(const float4*)&As[k][ty*4];
            float4 rb = *(const float4*)&Bs[k][tx*4];
            float av[4] = {ra.x, ra.y, ra.z, ra.w};
            float bv[4] = {rb.x, rb.y, rb.z, rb.w};
            #pragma unroll
            for (int i = 0; i < 4; i++)
                #pragma unroll
                for (int j = 0; j < 4; j++)
                    acc[i][j] += av[i] * bv[j];
        }
        __syncthreads();
    }
    #pragma unroll
    for (int i = 0; i < 4; i++) {
        int m = m0 + ty*4 + i;
        #pragma unroll
        for (int j = 0; j < 4; j++) {
            int n = tx*4 + j;
            out[(size_t)m * N + n] = acc[i][j] + bias[n];
        }
    }
}

// ============== attention v4 (R16-proven, bf16 in/out) =======================
#define AQS 36
#define AVS 132
#define APW 68
__global__ void __launch_bounds__(128, 3)
k_attn_mma()
{
    extern __shared__ float sm[];
    float* Qs = sm;
    float* Ks = sm + 4608;
    float* VT = sm + 9216;
    float* Pb = sm;

    int n = blockIdx.x >> 2, h = blockIdx.x & 3;
    int tid = threadIdx.x;
    int warp = tid >> 5, lane = tid & 31;
    int g = lane >> 2, t = lane & 3;
    int m0 = warp * 32;
    const __nv_bfloat16* base = g_qkvb + (size_t)n * NP * 3 * DD;

    for (int idx = tid; idx < NP*4; idx += 128) {
        int j = idx >> 2, dc = (idx & 3) * 8;
        uint4 qv = *(const uint4*)(base + j*384 +       h*32 + dc);
        uint4 kv = *(const uint4*)(base + j*384 + 128 + h*32 + dc);
        uint4 vv = *(const uint4*)(base + j*384 + 256 + h*32 + dc);
        float2 q0 = __bfloat1622float2(*(__nv_bfloat162*)&qv.x);
        float2 q1 = __bfloat1622float2(*(__nv_bfloat162*)&qv.y);
        float2 q2 = __bfloat1622float2(*(__nv_bfloat162*)&qv.z);
        float2 q3 = __bfloat1622float2(*(__nv_bfloat162*)&qv.w);
        *(float4*)&Qs[j*AQS + dc    ] = make_float4(q0.x, q0.y, q1.x, q1.y);
        *(float4*)&Qs[j*AQS + dc + 4] = make_float4(q2.x, q2.y, q3.x, q3.y);
        float2 k0 = __bfloat1622float2(*(__nv_bfloat162*)&kv.x);
        float2 k1 = __bfloat1622float2(*(__nv_bfloat162*)&kv.y);
        float2 k2 = __bfloat1622float2(*(__nv_bfloat162*)&kv.z);
        float2 k3 = __bfloat1622float2(*(__nv_bfloat162*)&kv.w);
        *(float4*)&Ks[j*AQS + dc    ] = make_float4(k0.x, k0.y, k1.x, k1.y);
        *(float4*)&Ks[j*AQS + dc + 4] = make_float4(k2.x, k2.y, k3.x, k3.y);
        float2 v0 = __bfloat1622float2(*(__nv_bfloat162*)&vv.x);
        float2 v1 = __bfloat1622float2(*(__nv_bfloat162*)&vv.y);
        float2 v2 = __bfloat1622float2(*(__nv_bfloat162*)&vv.z);
        float2 v3 = __bfloat1622float2(*(__nv_bfloat162*)&vv.w);
        VT[(dc    )*AVS + j] = v0.x;  VT[(dc + 1)*AVS + j] = v0.y;
        VT[(dc + 2)*AVS + j] = v1.x;  VT[(dc + 3)*AVS + j] = v1.y;
        VT[(dc + 4)*AVS + j] = v2.x;  VT[(dc + 5)*AVS + j] = v2.y;
        VT[(dc + 6)*AVS + j] = v3.x;  VT[(dc + 7)*AVS + j] = v3.y;
    }
    __syncthreads();

    float s[2][16][4] = {};
    #pragma unroll
    for (int kk = 0; kk < 32; kk += 8) {
        uint32_t afrag[2][4];
        #pragma unroll
        for (int mi = 0; mi < 2; mi++) {
            int r = m0 + mi * 16;
            afrag[mi][0] = FU(Qs[(r + g    )*AQS + kk + t    ]);
            afrag[mi][1] = FU(Qs[(r + g + 8)*AQS + kk + t    ]);
            afrag[mi][2] = FU(Qs[(r + g    )*AQS + kk + t + 4]);
            afrag[mi][3] = FU(Qs[(r + g + 8)*AQS + kk + t + 4]);
        }
        #pragma unroll
        for (int ni = 0; ni < 16; ni++) {
            int c = ni * 8;
            uint32_t b0 = FU(Ks[(c + g)*AQS + kk + t    ]);
            uint32_t b1 = FU(Ks[(c + g)*AQS + kk + t + 4]);
            mma8(s[0][ni], afrag[0], b0, b1);
            mma8(s[1][ni], afrag[1], b0, b1);
        }
    }
    __syncthreads();

    const float scale = 0.17677669529663687f;
    float mx[2][2] = {{-INFINITY,-INFINITY},{-INFINITY,-INFINITY}};
    #pragma unroll
    for (int mi = 0; mi < 2; mi++)
        #pragma unroll
        for (int ni = 0; ni < 16; ni++) {
            #pragma unroll
            for (int q = 0; q < 4; q++) s[mi][ni][q] *= scale;
            mx[mi][0] = fmaxf(mx[mi][0], fmaxf(s[mi][ni][0], s[mi][ni][1]));
            mx[mi][1] = fmaxf(mx[mi][1], fmaxf(s[mi][ni][2], s[mi][ni][3]));
        }
    #pragma unroll
    for (int mi = 0; mi < 2; mi++)
        #pragma unroll
        for (int hf = 0; hf < 2; hf++) {
            mx[mi][hf] = fmaxf(mx[mi][hf], __shfl_xor_sync(0xffffffffu, mx[mi][hf], 1));
            mx[mi][hf] = fmaxf(mx[mi][hf], __shfl_xor_sync(0xffffffffu, mx[mi][hf], 2));
        }
    float sum[2][2] = {};
    #pragma unroll
    for (int mi = 0; mi < 2; mi++)
        #pragma unroll
        for (int ni = 0; ni < 16; ni++) {
            s[mi][ni][0] = __expf(s[mi][ni][0] - mx[mi][0]);
            s[mi][ni][1] = __expf(s[mi][ni][1] - mx[mi][0]);
            s[mi][ni][2] = __expf(s[mi][ni][2] - mx[mi][1]);
            s[mi][ni][3] = __expf(s[mi][ni][3] - mx[mi][1]);
            sum[mi][0] += s[mi][ni][0] + s[mi][ni][1];
            sum[mi][1] += s[mi][ni][2] + s[mi][ni][3];
        }
    float inv[2][2];
    #pragma unroll
    for (int mi = 0; mi < 2; mi++)
        #pragma unroll
        for (int hf = 0; hf < 2; hf++) {
            float ss = sum[mi][hf];
            ss += __shfl_xor_sync(0xffffffffu, ss, 1);
            ss += __shfl_xor_sync(0xffffffffu, ss, 2);
            inv[mi][hf] = 1.f / ss;
        }

    float* Pw = Pb + warp * (32 * APW);
    float o[2][4][4] = {};
    #pragma unroll
    for (int hf = 0; hf < 2; hf++) {
        #pragma unroll
        for (int mi = 0; mi < 2; mi++) {
            int lr = mi * 16 + g;
            #pragma unroll
            for (int ni = 0; ni < 8; ni++) {
                int c = ni * 8 + 2 * t;
                Pw[ lr      *APW + c    ] = s[mi][hf*8 + ni][0];
                Pw[ lr      *APW + c + 1] = s[mi][hf*8 + ni][1];
                Pw[(lr + 8) *APW + c    ] = s[mi][hf*8 + ni][2];
                Pw[(lr + 8) *APW + c + 1] = s[mi][hf*8 + ni][3];
            }
        }
        __syncwarp();
        #pragma unroll
        for (int kk = 0; kk < 64; kk += 8) {
            uint32_t afrag[2][4];
            #pragma unroll
            for (int mi = 0; mi < 2; mi++) {
                int lr = mi * 16;
                afrag[mi][0] = FU(Pw[(lr + g    )*APW + kk + t    ]);
                afrag[mi][1] = FU(Pw[(lr + g + 8)*APW + kk + t    ]);
                afrag[mi][2] = FU(Pw[(lr + g    )*APW + kk + t + 4]);
                afrag[mi][3] = FU(Pw[(lr + g + 8)*APW + kk + t + 4]);
            }
            int j0 = hf*64 + kk + t, j1 = hf*64 + kk + t + 4;
            #pragma unroll
            for (int ni = 0; ni < 4; ni++) {
                int c = ni * 8;
                uint32_t b0 = FU(VT[(c + g)*AVS + j0]);
                uint32_t b1 = FU(VT[(c + g)*AVS + j1]);
                mma8(o[0][ni], afrag[0], b0, b1);
                mma8(o[1][ni], afrag[1], b0, b1);
            }
        }
        __syncwarp();
    }

    #pragma unroll
    for (int mi = 0; mi < 2; mi++) {
        int r0 = n*NP + m0 + mi * 16 + g;
        #pragma unroll
        for (int ni = 0; ni < 4; ni++) {
            int d = ni * 8 + 2 * t;
            *(__nv_bfloat162*)(g_ob + (size_t) r0      *DD + h*32 + d) =
                __floats2bfloat162_rn(o[mi][ni][0]*inv[mi][0], o[mi][ni][1]*inv[mi][0]);
            *(__nv_bfloat162*)(g_ob + (size_t)(r0 + 8) *DD + h*32 + d) =
                __floats2bfloat162_rn(o[mi][ni][2]*inv[mi][1], o[mi][ni][3]*inv[mi][1]);
        }
    }
}

// ---------------- mean over Np -----------------------------------------------
__global__ void k_mean()
{
    int n = blockIdx.x, d = threadIdx.x;
    float s = 0.f;
    for (int p = 0; p < NP; p++) s += g_Htemp[((size_t)n*NP + p)*DD + d];
    g_Hs[n*DD + d] = s * (1.f/128.f);
}

// ---------------- W_att = gat_w[h]^T @ att{src,dst}[h] -----------------------
__global__ void k_watt(const float* __restrict__ gw, const float* __restrict__ asv,
                       const float* __restrict__ adv)
{
    int idx = blockIdx.x * 256 + threadIdx.x;
    int r = idx >> 7, d = idx & 127;
    int h = r & 3;
    const float* att = (r < 4) ? asv : adv;
    float s = 0.f;
    for (int f = 0; f < 128; f++)
        s += att[h*FF + f] * gw[h*FF*DD + f*DD + d];
    g_watt[r*DD + d] = s;
}

// ---------------- graph adjacency --------------------------------------------
__global__ void k_graph(const float* __restrict__ adj)
{
    __shared__ float k2s[CC*DK];
    __shared__ float Amat[CC*65];
    int b = blockIdx.x, c = threadIdx.x;
    for (int idx = c; idx < CC*DK; idx += 64) k2s[idx] = g_k2[(size_t)b*CC*DK + idx];
    __syncthreads();
    float qreg[DK];
    #pragma unroll
    for (int d = 0; d < DK; d++) qreg[d] = g_q2[(size_t)b*CC*DK + c*DK + d];
    for (int e = 0; e < CC; e++) {
        float a = 0.f;
        #pragma unroll
        for (int d = 0; d < DK; d++) a += qreg[d] * k2s[e*DK + d];
        Amat[c*65 + e] = tanhf(a * 0.125f) + adj[c*CC + e];
    }
    for (int e = 0; e < CC; e++) g_mask[(size_t)b*CC*CC + c*CC + e] = 0.f;
    for (int kk = 0; kk < 8; kk++) {
        float best = -INFINITY; int bi = 0;
        for (int e = 0; e < CC; e++) {
            float v = Amat[c*65 + e];
            if (v > best) { best = v; bi = e; }
        }
        if (bi != c && best != 0.f) g_mask[(size_t)b*CC*CC + c*CC + bi] = 1.f;
        Amat[c*65 + bi] = -INFINITY;
    }
}

// ============== GAT v3: row-major bf16 Xh via cp.async, head-pipelined =======
// smem: XhB 2x[64][136] bf16 (union Os[64][132] f32) ; Awt[64][68] ; Asv/Adv
#define XSB 136
#define XBUF 8704          // bf16 elements per buffer (64*136)
#define AST 68
#define OST 132
#define GUF 8704           // float offset after 2 Xh buffers (34816 B)
__global__ void __launch_bounds__(256)
k_gat(const float* __restrict__ gbias, const float* __restrict__ sg,
      const float* __restrict__ sb, float* __restrict__ out)
{
    extern __shared__ float sm[];
    __nv_bfloat16* XhB = (__nv_bfloat16*)sm;
    float* Awt = sm + GUF;
    float* Asv = sm + GUF + 4352;
    float* Adv = Asv + 64;
    float* Os  = sm;

    int b = blockIdx.x >> 7, p = blockIdx.x & 127;
    int tid = threadIdx.x, w = tid >> 5, lane = tid & 31;
    int wm = w >> 2, wn = w & 3;
    int g = lane >> 2, t4 = lane & 3;

    float mr0[8], mr1[8];
    #pragma unroll
    for (int i = 0; i < 8; i++) {
        int t = w*8 + i;
        mr0[i] = g_mask[(size_t)b*CC*CC + lane*CC + t];
        mr1[i] = g_mask[(size_t)b*CC*CC + (lane+32)*CC + t];
    }

    // prefetch head 0 -> buf 0 (4 chunks of 16B per thread: 64 rows x 16 chunks)
    #pragma unroll
    for (int i = 0; i < 4; i++) {
        int idx = tid + i * 256;
        int s = idx >> 4, c8 = (idx & 15) * 8;
        cp_async16(XhB + s*XSB + c8,
                   g_xhb + (size_t)(((b*CC + s)*NP + p))*(HS*FF) + 0*FF + c8);
    }
    asm volatile("cp.async.commit_group;");

    float acc[2][4][4] = {};
    #pragma unroll
    for (int h = 0; h < HS; h++) {
        if (h + 1 < HS) {
            int nb = ((h + 1) & 1) * XBUF;
            #pragma unroll
            for (int i = 0; i < 4; i++) {
                int idx = tid + i * 256;
                int s = idx >> 4, c8 = (idx & 15) * 8;
                cp_async16(XhB + nb + s*XSB + c8,
                           g_xhb + (size_t)(((b*CC + s)*NP + p))*(HS*FF) + (h+1)*FF + c8);
            }
            asm volatile("cp.async.commit_group;");
            asm volatile("cp.async.wait_group 1;");
        } else {
            asm volatile("cp.async.wait_group 0;");
        }
        if (tid < 64)            Asv[tid]      = g_asrc[(((b*4 + h)*128 + p)*64) + tid];
        else if (tid < 128)      Adv[tid - 64] = g_adst[(((b*4 + h)*128 + p)*64) + tid - 64];
        __syncthreads();

        #pragma unroll
        for (int i = 0; i < 8; i++) {
            int t = w*8 + i;
            float adt = Adv[t];
            float e0 = Asv[lane]      + adt; e0 = e0 > 0.f ? e0 : 0.2f*e0;
            float e1 = Asv[lane + 32] + adt; e1 = e1 > 0.f ? e1 : 0.2f*e1;
            float me = fmaxf(mr0[i] > 0.5f ? e0 : GAT_NEG, mr1[i] > 0.5f ? e1 : GAT_NEG);
            #pragma unroll
            for (int o = 16; o; o >>= 1) me = fmaxf(me, __shfl_xor_sync(0xffffffffu, me, o));
            float w0 = (mr0[i] > 0.5f) ? __expf(e0 - me) : 0.f;
            float w1 = (mr1[i] > 0.5f) ? __expf(e1 - me) : 0.f;
            float ws = w0 + w1;
            #pragma unroll
            for (int o = 16; o; o >>= 1) ws += __shfl_xor_sync(0xffffffffu, ws, o);
            float inv = ws > 0.f ? 1.f / ws : 0.f;
            Awt[t*AST + lane]      = w0 * inv;
            Awt[t*AST + lane + 32] = w1 * inv;
        }
        __syncthreads();

        int buf = (h & 1) * XBUF;
        #pragma unroll
        for (int kk = 0; kk < CC; kk += 8) {
            uint32_t afrag[2][4];
            #pragma unroll
            for (int mi = 0; mi < 2; mi++) {
                int r = wm * 32 + mi * 16;
                afrag[mi][0] = FU(Awt[(r + g    )*AST + kk + t4    ]);
                afrag[mi][1] = FU(Awt[(r + g + 8)*AST + kk + t4    ]);
                afrag[mi][2] = FU(Awt[(r + g    )*AST + kk + t4 + 4]);
                afrag[mi][3] = FU(Awt[(r + g + 8)*AST + kk + t4 + 4]);
            }
            #pragma unroll
            for (int ni = 0; ni < 4; ni++) {
                int c = wn * 32 + ni * 8;
                // B[n][k] = Xh[k][n] (row-major, k = source s)
                uint32_t b0 = FU(BF2F(XhB[buf + (kk + t4    )*XSB + c + g]));
                uint32_t b1 = FU(BF2F(XhB[buf + (kk + t4 + 4)*XSB + c + g]));
                mma8(acc[0][ni], afrag[0], b0, b1);
                mma8(acc[1][ni], afrag[1], b0, b1);
            }
        }
        __syncthreads();
    }

    // ---- epilogue (unchanged; Os unions over Xh buffers) ----
    for (int idx = tid; idx < CC*DD; idx += 256) {
        int r = idx >> 7, f = idx & 127;
        Os[r*OST + f] = g_Htemp[(((size_t)(b*CC + r))*NP + p)*DD + f] + gbias[f];
    }
    __syncthreads();
    #pragma unroll
    for (int mi = 0; mi < 2; mi++)
        #pragma unroll
        for (int ni = 0; ni < 4; ni++) {
            int r = wm*32 + mi*16 + g;
            int c = wn*32 + ni*8 + 2*t4;
            #pragma unroll
            for (int half = 0; half < 2; half++) {
                int row = r + half*8;
                Os[row*OST + c    ] += acc[mi][ni][half*2 + 0] * 0.25f;
                Os[row*OST + c + 1] += acc[mi][ni][half*2 + 1] * 0.25f;
            }
        }
    __syncthreads();
    {
        float4 g4 = ((const float4*)sg)[lane];
        float4 b4 = ((const float4*)sb)[lane];
        for (int r = w; r < CC; r += 8) {
            float4 v = *(float4*)&Os[r*OST + lane*4];
            float s1 = v.x + v.y + v.z + v.w;
            #pragma unroll
            for (int o = 16; o; o >>= 1) s1 += __shfl_xor_sync(0xffffffffu, s1, o);
            float mean = s1 * (1.f/128.f);
            float dx=v.x-mean, dy=v.y-mean, dz=v.z-mean, dw=v.w-mean;
            float q = dx*dx+dy*dy+dz*dz+dw*dw;
            #pragma unroll
            for (int o = 16; o; o >>= 1) q += __shfl_xor_sync(0xffffffffu, q, o);
            float inv = rsqrtf(q * (1.f/128.f) + 1e-5f);
            float4 ov;
            ov.x = dx*inv*g4.x + b4.x; ov.y = dy*inv*g4.y + b4.y;
            ov.z = dz*inv*g4.z + b4.z; ov.w = dw*inv*g4.w + b4.w;
            ((float4*)(out + (((size_t)(b*CC + r))*NP + p)*DD))[lane] = ov;
        }
    }
}

// ---------------- host launch -------------------------------------------------
extern "C" void kernel_launch(void* const* d_in, const int* in_sizes, int n_in,
                              void* d_out, int out_size)
{
    const float* H_in      = (const float*)d_in[0];
    const float* static_adj= (const float*)d_in[1];
    const float* attn_in_w = (const float*)d_in[2];
    const float* attn_in_b = (const float*)d_in[3];
    const float* attn_out_w= (const float*)d_in[4];
    const float* attn_out_b= (const float*)d_in[5];
    const float* ln1_g     = (const float*)d_in[6];
    const float* ln1_b     = (const float*)d_in[7];
    const float* ln2_g     = (const float*)d_in[8];
    const float* ln2_b     = (const float*)d_in[9];
    const float* ff1_w     = (const float*)d_in[10];
    const float* ff1_b     = (const float*)d_in[11];
    const float* ff2_w     = (const float*)d_in[12];
    const float* ff2_b     = (const float*)d_in[13];
    const float* tnorm_g   = (const float*)d_in[14];
    const float* tnorm_b   = (const float*)d_in[15];
    const float* q_w       = (const float*)d_in[16];
    const float* q_b       = (const float*)d_in[17];
    const float* k_w       = (const float*)d_in[18];
    const float* k_b       = (const float*)d_in[19];
    const float* gat_w     = (const float*)d_in[20];
    const float* gat_att_src = (const float*)d_in[21];
    const float* gat_att_dst = (const float*)d_in[22];
    const float* gat_bias  = (const float*)d_in[23];
    const float* snorm_g   = (const float*)d_in[24];
    const float* snorm_b   = (const float*)d_in[25];

    float *x_, *Htemp_, *Hs_, *q2_, *k2_;
    __nv_bfloat16 *hb_, *xhb_, *qkvb_, *ob_, *ffb_;
    cudaGetSymbolAddress((void**)&hb_,    g_hb);
    cudaGetSymbolAddress((void**)&qkvb_,  g_qkvb);
    cudaGetSymbolAddress((void**)&ob_,    g_ob);
    cudaGetSymbolAddress((void**)&x_,     g_x);
    cudaGetSymbolAddress((void**)&ffb_,   g_ffb);
    cudaGetSymbolAddress((void**)&Htemp_, g_Htemp);
    cudaGetSymbolAddress((void**)&xhb_,   g_xhb);
    cudaGetSymbolAddress((void**)&Hs_,    g_Hs);
    cudaGetSymbolAddress((void**)&q2_,    g_q2);
    cudaGetSymbolAddress((void**)&k2_,    g_k2);

    const int mma_smem  = 4 * TILE * 4;                 // 73728
    const int mmaA_smem = 2*TILEA*2 + 2*TILE*4;         // 57344
    const int attn_smem = 13440 * 4;                    // 53760
    const int gat_smem  = (GUF + 4352 + 128) * 4;       // 52736
    cudaFuncSetAttribute(k_mma_bf,  cudaFuncAttributeMaxDynamicSharedMemorySize, mma_smem);
    cudaFuncSetAttribute(k_mma_bfA, cudaFuncAttributeMaxDynamicSharedMemorySize, mmaA_smem);
    cudaFuncSetAttribute(k_mma_b2b, cudaFuncAttributeMaxDynamicSharedMemorySize, mmaA_smem);
    cudaFuncSetAttribute(k_attn_mma, cudaFuncAttributeMaxDynamicSharedMemorySize, attn_smem);
    cudaFuncSetAttribute(k_gat,  cudaFuncAttributeMaxDynamicSharedMemorySize, gat_smem);

    // 0) W_att vectors
    k_watt<<<4, 256>>>(gat_w, gat_att_src, gat_att_dst);
    // 1) h = ln1(x0)  (bf16 out)
    k_ln<<<NTOK/8, 256>>>(H_in, ln1_g, ln1_b, hb_);
    // 2) qkv = h @ Wqkv^T + b  (bf16 in/out)
    k_mma_b2b<<<dim3(3, NTOK/TBM), 256, mmaA_smem>>>(hb_, attn_in_w, attn_in_b, qkvb_,
                                                     384, 128, 0);
    // 3) temporal attention (bf16 in/out)
    k_attn_mma<<<NSEQ*HT, 128, attn_smem>>>();
    // 4) x1 = x0 + o @ Wout^T + b  (bf16 A)
    k_mma_bfA<<<dim3(1, NTOK/TBM), 256, mmaA_smem>>>(ob_, attn_out_w, attn_out_b,
                                                     H_in, x_, 128, 128);
    // 5) h = ln2(x1)  (bf16 out)
    k_ln<<<NTOK/8, 256>>>(x_, ln2_g, ln2_b, hb_);
    // 6) ff = relu(h @ W1^T + b1)  (bf16 in/out)
    k_mma_b2b<<<dim3(4, NTOK/TBM), 256, mmaA_smem>>>(hb_, ff1_w, ff1_b, ffb_,
                                                     512, 128, 1);
    // 7) x2 = x1 + ff @ W2^T + b2  (bf16 A)
    k_mma_bfA<<<dim3(1, NTOK/TBM), 256, mmaA_smem>>>(ffb_, ff2_w, ff2_b,
                                                     x_, x_, 128, 512);
    // 8) H_temp = ln(x0 + x2, tnorm) + fused asrc/adst
    k_ln_asd<<<NTOK/8, 256>>>(x_, H_in, tnorm_g, tnorm_b, Htemp_);
    // 9) xh = H_temp @ gat_w^T  (bf16 out)
    k_mma_bf<<<dim3(4, NTOK/TBM), 256, mma_smem>>>(Htemp_, gat_w, nullptr, xhb_,
                                                   512, 128, 0);
    // 10) Hs = mean_p(H_temp)
    k_mean<<<NSEQ, 128>>>();
    // 11) q2 and k2 in one launch
    k_gemm2<<<dim3(2, NSEQ/BM), 256>>>(Hs_, q_w, q_b, q2_, k_w, k_b, k2_, 128);
    // 12) adjacency / top-k / mask
    k_graph<<<BB, 64>>>(static_adj);
    // 13) GAT v3 + snorm LN -> output
    k_gat<<<BB*NP, 256, gat_smem>>>(gat_bias, snorm_g, snorm_b, (float*)d_out);
}